// round 11
// baseline (speedup 1.0000x reference)
#include <cuda_runtime.h>
#include <cuda_fp16.h>
#include <math.h>
#include <stdint.h>

// ---------------- model constants ----------------
#define BB     16
#define EDIM   768
#define NHEADS 12
#define HD     64
#define FFDIM  3072
#define NLAYER 8
#define SEQ    64
#define ROWSM  1024     // BB*SEQ
#define PDIM   4096

// ---------------- scratch (device globals) ----------------
__device__ float g_pool1[16 * 255 * 255 * 16];
__device__ float g_pool2[16 * 126 * 126 * 16];
__device__ float g_t [ROWSM * EDIM];
__device__ float g_q [ROWSM * EDIM];
__device__ float g_k [ROWSM * EDIM];
__device__ float g_v [ROWSM * EDIM];
__device__ float g_o1[ROWSM * EDIM];
__device__ float g_part[3 * ROWSM * FFDIM];          // split-K fp32 partials / FF1 fp32 out

// fp16 packed-pair (u32 = 2 halves along K) buffers
__device__ uint32_t g_patch16[ROWSM * PDIM / 2];
__device__ uint32_t g_t16  [ROWSM * EDIM / 2];
__device__ uint32_t g_att16[ROWSM * EDIM / 2];
__device__ uint32_t g_o116 [ROWSM * EDIM / 2];
__device__ uint32_t g_f116 [ROWSM * FFDIM / 2];
// converted weights: [K/2][N] u32, pair = (k, k+1) at fixed n
__device__ uint32_t g_wq16[NLAYER * EDIM * EDIM / 2];
__device__ uint32_t g_wk16[NLAYER * EDIM * EDIM / 2];
__device__ uint32_t g_wv16[NLAYER * EDIM * EDIM / 2];
__device__ uint32_t g_wo16[NLAYER * EDIM * EDIM / 2];
__device__ uint32_t g_w116[NLAYER * EDIM * FFDIM / 2];
__device__ uint32_t g_w216[NLAYER * FFDIM * EDIM / 2];
__device__ uint32_t g_wp16[PDIM * EDIM / 2];

// ---------------- weight conversion: [K][N] fp32 -> [K/2][N] u32 ------------
__global__ void cvt_w_kernel(const float* __restrict__ W, uint32_t* __restrict__ O,
                             long total, int N) {
    long idx = (long)blockIdx.x * 256 + threadIdx.x;
    if (idx >= total) return;
    long kp = idx / N;
    int  n  = (int)(idx - kp * N);
    float a = W[(2 * kp) * (long)N + n];
    float b = W[(2 * kp + 1) * (long)N + n];
    __half2 h = __floats2half2_rn(a, b);
    O[idx] = *(uint32_t*)&h;
}

// ---------------- activation conversion: contiguous fp32 -> packed pairs ----
__global__ void cvt_act_kernel(const float* __restrict__ A, uint32_t* __restrict__ O,
                               long total_pairs) {
    long idx = (long)blockIdx.x * 256 + threadIdx.x;
    if (idx >= total_pairs) return;
    float2 v = *(const float2*)(A + 2 * idx);
    __half2 h = __floats2half2_rn(v.x, v.y);
    O[idx] = *(uint32_t*)&h;
}

// ---------------- conv1 (3x3x3->16) + relu + maxpool, smem-tiled ------------
// grid (16, 16, 16 b), block 256 = 16x16 pool outputs per block.
// Channels processed in 2 halves of 8 to keep register pressure low (no spill).
__global__ __launch_bounds__(256) void conv1_pool_kernel(
    const float* __restrict__ x,
    const float* __restrict__ w,
    const float* __restrict__ bias,
    float* __restrict__ out) {
    __shared__ float xs[34 * 104];
    __shared__ float ws[432];
    __shared__ float bs[16];
    const int tid = threadIdx.x;
    for (int i = tid; i < 432; i += 256) ws[i] = w[i];
    if (tid < 16) bs[tid] = bias[tid];

    const int b   = blockIdx.z;
    const int ph0 = blockIdx.y * 16;
    const int pw0 = blockIdx.x * 16;

    const int wlim = (512 - 2 * pw0) * 3;
    for (int idx = tid; idx < 34 * 102; idx += 256) {
        int r = idx / 102, i = idx - r * 102;
        int gr = 2 * ph0 + r;
        float v = 0.0f;
        if (gr < 512 && i < wlim)
            v = x[((long)(b * 512 + gr) * 512 + 2 * pw0) * 3 + i];
        xs[r * 104 + i] = v;
    }
    __syncthreads();

    const int py = tid >> 4, px = tid & 15;
    const int ph = ph0 + py, pw = pw0 + px;
    if (ph >= 255 || pw >= 255) return;

    float* op = out + ((long)(b * 255 + ph) * 255 + pw) * 16;

    for (int half = 0; half < 2; half++) {
        const int c0 = half * 8;
        float mx[8];
#pragma unroll
        for (int c = 0; c < 8; c++) mx[c] = 0.0f;

        for (int dy = 0; dy < 2; dy++) {
            for (int dx = 0; dx < 2; dx++) {
                float acc[8];
#pragma unroll
                for (int c = 0; c < 8; c++) acc[c] = bs[c0 + c];
#pragma unroll
                for (int kh = 0; kh < 3; kh++) {
                    const float* xr = xs + (2 * py + dy + kh) * 104 + (2 * px + dx) * 3;
#pragma unroll
                    for (int kw = 0; kw < 3; kw++) {
                        float x0 = xr[kw * 3], x1 = xr[kw * 3 + 1], x2 = xr[kw * 3 + 2];
                        const float* wp = ws + ((kh * 3 + kw) * 3) * 16 + c0;
#pragma unroll
                        for (int c = 0; c < 8; c++)
                            acc[c] += x0 * wp[c] + x1 * wp[16 + c] + x2 * wp[32 + c];
                    }
                }
#pragma unroll
                for (int c = 0; c < 8; c++) mx[c] = fmaxf(mx[c], fmaxf(acc[c], 0.0f));
            }
        }
        *(float4*)(op + c0)     = make_float4(mx[0], mx[1], mx[2], mx[3]);
        *(float4*)(op + c0 + 4) = make_float4(mx[4], mx[5], mx[6], mx[7]);
    }
}

// ---------------- conv2 (3x3x16->16) + relu + maxpool, smem-tiled -----------
// Channels in 2 halves of 8 (register diet; avoids local-memory spill which
// would grow the device local pool and trip the harness allocation guard).
#define C2_CISTR (34 * 35)
#define C2_XS    (16 * C2_CISTR)
#define C2_SMEM  ((C2_XS + 2304 + 16) * 4)          // 85440 B

__global__ __launch_bounds__(256) void conv2_pool_kernel(
    const float* __restrict__ in,
    const float* __restrict__ w,
    const float* __restrict__ bias,
    float* __restrict__ out) {
    extern __shared__ float cs[];
    float* xs = cs;
    float* ws = cs + C2_XS;
    float* bs = ws + 2304;

    const int tid = threadIdx.x;
    for (int i = tid; i < 2304; i += 256) ws[i] = w[i];
    if (tid < 16) bs[tid] = bias[tid];

    const int b   = blockIdx.z;
    const int ph0 = blockIdx.y * 16;
    const int pw0 = blockIdx.x * 16;

    for (int idx = tid; idx < 34 * 34 * 16; idx += 256) {
        int ci = idx & 15;
        int pcell = idx >> 4;
        int c = pcell % 34, r = pcell / 34;
        int gr = 2 * ph0 + r, gw = 2 * pw0 + c;
        float v = 0.0f;
        if (gr < 255 && gw < 255)
            v = in[((long)(b * 255 + gr) * 255 + gw) * 16 + ci];
        xs[ci * C2_CISTR + r * 35 + c] = v;
    }
    __syncthreads();

    const int py = tid >> 4, px = tid & 15;
    const int ph = ph0 + py, pw = pw0 + px;
    if (ph >= 126 || pw >= 126) return;

    float* op = out + ((long)(b * 126 + ph) * 126 + pw) * 16;

    for (int half = 0; half < 2; half++) {
        const int c0 = half * 8;
        float mx[8];
#pragma unroll
        for (int c = 0; c < 8; c++) mx[c] = 0.0f;

        for (int dy = 0; dy < 2; dy++) {
            for (int dx = 0; dx < 2; dx++) {
                float acc[8];
#pragma unroll
                for (int c = 0; c < 8; c++) acc[c] = bs[c0 + c];
#pragma unroll
                for (int kh = 0; kh < 3; kh++) {
                    const int lr = 2 * py + dy + kh;
#pragma unroll
                    for (int kw = 0; kw < 3; kw++) {
                        const int lc = 2 * px + dx + kw;
                        const float* xp = xs + lr * 35 + lc;
                        const float* wp = ws + ((kh * 3 + kw) * 16) * 16 + c0;
#pragma unroll
                        for (int ci = 0; ci < 16; ci++) {
                            float xv = xp[ci * C2_CISTR];
#pragma unroll
                            for (int c = 0; c < 8; c++)
                                acc[c] += xv * wp[ci * 16 + c];
                        }
                    }
                }
#pragma unroll
                for (int c = 0; c < 8; c++) mx[c] = fmaxf(mx[c], fmaxf(acc[c], 0.0f));
            }
        }
        *(float4*)(op + c0)     = make_float4(mx[0], mx[1], mx[2], mx[3]);
        *(float4*)(op + c0 + 4) = make_float4(mx[4], mx[5], mx[6], mx[7]);
    }
}

// ---------------- patch gather -> fp16 ---------------------------------------
__global__ void patch_kernel(const float* __restrict__ pool2,
                             __half* __restrict__ patches16) {
    long idx = (long)blockIdx.x * 256 + threadIdx.x;
    if (idx >= (long)ROWSM * PDIM) return;
    int d   = (int)(idx & (PDIM - 1));
    int row = (int)(idx >> 12);
    int b   = row >> 6;
    int p   = row & 63;
    int pr  = p >> 3, pc = p & 7;
    int r   = d >> 8;
    int c   = (d >> 4) & 15;
    int ch  = d & 15;
    int H = pr * 16 + r;
    int W = pc * 16 + c;
    float v = 0.0f;
    if (H >= 1 && H <= 126 && W >= 1 && W <= 126)
        v = pool2[((long)(b * 126 + (H - 1)) * 126 + (W - 1)) * 16 + ch];
    patches16[idx] = __float2half(v);
}

// ---------------- FP16 tensor-core GEMM (exact R7 version) -------------------
__device__ __forceinline__ void mma_f16(float* d, const uint32_t* a, const uint32_t* b) {
    asm volatile(
        "mma.sync.aligned.m16n8k16.row.col.f32.f16.f16.f32 "
        "{%0,%1,%2,%3}, {%4,%5,%6,%7}, {%8,%9}, {%0,%1,%2,%3};\n"
        : "+f"(d[0]), "+f"(d[1]), "+f"(d[2]), "+f"(d[3])
        : "r"(a[0]), "r"(a[1]), "r"(a[2]), "r"(a[3]), "r"(b[0]), "r"(b[1]));
}

__device__ __forceinline__ void cp16s(uint32_t saddr, const void* gsrc) {
    asm volatile("cp.async.cg.shared.global [%0], [%1], 16;\n" :: "r"(saddr), "l"(gsrc));
}
__device__ __forceinline__ void cp_commit() { asm volatile("cp.async.commit_group;\n"); }
template <int N> __device__ __forceinline__ void cp_wait() {
    asm volatile("cp.async.wait_group %0;\n" :: "n"(N));
}

#define ASTR 36
#define BSTR 136
#define AS_TILE (128 * ASTR)
#define BS_TILE (32 * BSTR)
#define STAGE_U32 (AS_TILE + BS_TILE)
#define NSTAGE 3
#define GEMM_SMEM (NSTAGE * STAGE_U32 * 4)   // 107520 B

__global__ __launch_bounds__(256, 2) void gemm_f16_kernel(
    const uint32_t* __restrict__ A,
    const uint32_t* __restrict__ Bp0, const uint32_t* __restrict__ Bp1,
    const uint32_t* __restrict__ Bp2,
    const float* __restrict__ bi0, const float* __restrict__ bi1,
    const float* __restrict__ bi2,
    float* __restrict__ Cp0, float* __restrict__ Cp1, float* __restrict__ Cp2,
    float* __restrict__ part,
    int M, int N, int K, int splitk, int relu)
{
    extern __shared__ uint32_t smu[];

    const int z   = blockIdx.z;
    const int mat = z / splitk;
    const int kz  = z - mat * splitk;
    const uint32_t* B  = mat == 0 ? Bp0 : (mat == 1 ? Bp1 : Bp2);
    const float*    bi = mat == 0 ? bi0 : (mat == 1 ? bi1 : bi2);
    float*          C  = mat == 0 ? Cp0 : (mat == 1 ? Cp1 : Cp2);

    const int tid  = threadIdx.x;
    const int lane = tid & 31;
    const int warp = tid >> 5;
    const int wm   = warp & 3;
    const int wn   = warp >> 2;
    const int gid  = lane >> 2;
    const int tkc  = lane & 3;

    const int bm = blockIdx.y * 128;
    const int bn = blockIdx.x * 128;

    const int KP   = K >> 1;
    const int ktot = K >> 6;
    const int ktb  = (kz * ktot) / splitk;
    const int kte  = ((kz + 1) * ktot) / splitk;
    const int nkt  = kte - ktb;

    const int rowA = tid >> 3;
    const int segA = (tid & 7) * 4;
    const int rowB = tid >> 5;
    const int segB = (tid & 31) * 4;
    const uint32_t* pA = A + (long)(bm + rowA) * KP + ktb * 32 + segA;
    const uint32_t* pB = B + (long)(ktb * 32 + rowB) * N + bn + segB;
    const uint32_t sbase = (uint32_t)__cvta_generic_to_shared(smu);
    const uint32_t sA = sbase + (rowA * ASTR + segA) * 4;
    const uint32_t sB = sbase + (AS_TILE + rowB * BSTR + segB) * 4;

    auto issue = [&](int i) {
        const uint32_t off = (uint32_t)((i % NSTAGE) * STAGE_U32 * 4);
        const long kf = (long)i * 32;
#pragma unroll
        for (int t = 0; t < 4; t++)
            cp16s(sA + off + t * (32 * ASTR * 4), pA + t * 32 * (long)KP + kf);
#pragma unroll
        for (int t = 0; t < 4; t++)
            cp16s(sB + off + t * (8 * BSTR * 4), pB + (kf + t * 8) * (long)N);
    };

    issue(0); cp_commit();
    if (nkt > 1) { issue(1); }
    cp_commit();

    float acc[2][8][4];
#pragma unroll
    for (int mc = 0; mc < 2; mc++)
#pragma unroll
        for (int nc = 0; nc < 8; nc++)
#pragma unroll
            for (int i = 0; i < 4; i++) acc[mc][nc][i] = 0.0f;

    for (int i = 0; i < nkt; i++) {
        cp_wait<1>();
        __syncthreads();
        if (i + 2 < nkt) issue(i + 2);
        cp_commit();

        const uint32_t* as = smu + (i % NSTAGE) * STAGE_U32;
        const uint32_t* bs = as + AS_TILE;

#pragma unroll
        for (int ks = 0; ks < 4; ks++) {
            const int kc = ks * 8 + tkc;
            uint32_t af[2][4];
#pragma unroll
            for (int mc = 0; mc < 2; mc++) {
                const int r = wm * 32 + mc * 16 + gid;
                af[mc][0] = as[r * ASTR + kc];
                af[mc][1] = as[(r + 8) * ASTR + kc];
                af[mc][2] = as[r * ASTR + kc + 4];
                af[mc][3] = as[(r + 8) * ASTR + kc + 4];
            }
#pragma unroll
            for (int nc = 0; nc < 8; nc++) {
                uint32_t bf[2];
                const int c = wn * 64 + nc * 8 + gid;
                bf[0] = bs[kc * BSTR + c];
                bf[1] = bs[(kc + 4) * BSTR + c];
                mma_f16(acc[0][nc], af[0], bf);
                mma_f16(acc[1][nc], af[1], bf);
            }
        }
    }

    if (splitk == 1) {
#pragma unroll
        for (int mc = 0; mc < 2; mc++) {
            const int r0 = bm + wm * 32 + mc * 16 + gid;
#pragma unroll
            for (int nc = 0; nc < 8; nc++) {
                const int col = bn + wn * 64 + nc * 8 + 2 * tkc;
                const float b0 = bi[col], b1 = bi[col + 1];
                float v0 = acc[mc][nc][0] + b0;
                float v1 = acc[mc][nc][1] + b1;
                float v2 = acc[mc][nc][2] + b0;
                float v3 = acc[mc][nc][3] + b1;
                if (relu) {
                    v0 = fmaxf(v0, 0.f); v1 = fmaxf(v1, 0.f);
                    v2 = fmaxf(v2, 0.f); v3 = fmaxf(v3, 0.f);
                }
                *(float2*)&C[(long)r0 * N + col]       = make_float2(v0, v1);
                *(float2*)&C[(long)(r0 + 8) * N + col] = make_float2(v2, v3);
            }
        }
    } else {
        float* P0 = part + (long)z * M * N;
#pragma unroll
        for (int mc = 0; mc < 2; mc++) {
            const int r0 = bm + wm * 32 + mc * 16 + gid;
#pragma unroll
            for (int nc = 0; nc < 8; nc++) {
                const int col = bn + wn * 64 + nc * 8 + 2 * tkc;
                *(float2*)&P0[(long)r0 * N + col]       = make_float2(acc[mc][nc][0], acc[mc][nc][1]);
                *(float2*)&P0[(long)(r0 + 8) * N + col] = make_float2(acc[mc][nc][2], acc[mc][nc][3]);
            }
        }
    }
}

// ordered split-K reduce + bias (+relu); optional fp32 and fp16 outputs
__global__ void splitk_reduce_kernel(const float* __restrict__ part,
                                     const float* __restrict__ bias,
                                     float* __restrict__ Cf,
                                     __half* __restrict__ Chh,
                                     int MN, int N, int splitk, int relu) {
    int idx = blockIdx.x * 256 + threadIdx.x;
    if (idx >= MN) return;
    float s = part[idx];
    for (int zz = 1; zz < splitk; zz++) s += part[(long)zz * MN + idx];
    s += bias[idx % N];
    if (relu) s = fmaxf(s, 0.0f);
    if (Cf) Cf[idx] = s;
    if (Chh) Chh[idx] = __float2half(s);
}

// ---------------- attention: one block per (b, head); fp16 output -----------
__global__ void attn_kernel(const float* __restrict__ Q,
                            const float* __restrict__ K,
                            const float* __restrict__ V,
                            __half* __restrict__ O16) {
    extern __shared__ float sm[];
    float* qs = sm;
    float* ks = qs + 64 * 65;
    float* vs = ks + 64 * 65;
    float* ss = vs + 64 * 65;

    int h = blockIdx.x;
    int b = blockIdx.y;
    int tid = threadIdx.x;

    for (int e = tid; e < 4096; e += 256) {
        int s = e >> 6, d = e & 63;
        long base = ((long)(b * 64 + s) * EDIM) + h * 64 + d;
        qs[s * 65 + d] = Q[base];
        ks[s * 65 + d] = K[base];
        vs[s * 65 + d] = V[base];
    }
    __syncthreads();

    for (int e = tid; e < 4096; e += 256) {
        int row = e >> 6, col = e & 63;
        float sum = 0.0f;
#pragma unroll 16
        for (int dd = 0; dd < 64; dd++)
            sum += qs[row * 65 + dd] * ks[col * 65 + dd];
        ss[row * 65 + col] = sum * 0.125f;
    }
    __syncthreads();

    if (tid < 64) {
        float* r = ss + tid * 65;
        float m = r[0];
#pragma unroll 16
        for (int c = 1; c < 64; c++) m = fmaxf(m, r[c]);
        float sum = 0.0f;
#pragma unroll 16
        for (int c = 0; c < 64; c++) { float e = expf(r[c] - m); r[c] = e; sum += e; }
        float inv = 1.0f / sum;
#pragma unroll 16
        for (int c = 0; c < 64; c++) r[c] *= inv;
    }
    __syncthreads();

    for (int e = tid; e < 4096; e += 256) {
        int row = e >> 6, d = e & 63;
        float sum = 0.0f;
#pragma unroll 16
        for (int col = 0; col < 64; col++)
            sum += ss[row * 65 + col] * vs[col * 65 + d];
        O16[(long)b * (NHEADS * SEQ * HD) + h * 4096 + row * 64 + d] = __float2half(sum);
    }
}

// ------ fused: y = 3 splitk partials + bias; out = LN(x + y), fp32+fp16 -----
__global__ void add_ln_splitk_kernel(const float* __restrict__ x,
                                     const float* __restrict__ part,
                                     const float* __restrict__ gb,
                                     const float* __restrict__ g,
                                     const float* __restrict__ be,
                                     float* __restrict__ out,
                                     __half* __restrict__ out16,
                                     int MN) {
    __shared__ float buf[EDIM];
    __shared__ float red[256];
    int row = blockIdx.x;
    int tid = threadIdx.x;
    long base = (long)row * EDIM;

    float partial = 0.0f;
    for (int e = tid; e < EDIM; e += 256) {
        float y = part[base + e] + part[MN + base + e] + part[2L * MN + base + e] + gb[e];
        float v = x[base + e] + y;
        buf[e] = v;
        partial += v;
    }
    red[tid] = partial;
    __syncthreads();
    for (int s = 128; s > 0; s >>= 1) {
        if (tid < s) red[tid] += red[tid + s];
        __syncthreads();
    }
    float mean = red[0] * (1.0f / EDIM);
    __syncthreads();

    float p2 = 0.0f;
    for (int e = tid; e < EDIM; e += 256) {
        float d = buf[e] - mean;
        p2 += d * d;
    }
    red[tid] = p2;
    __syncthreads();
    for (int s = 128; s > 0; s >>= 1) {
        if (tid < s) red[tid] += red[tid + s];
        __syncthreads();
    }
    float var = red[0] * (1.0f / EDIM);
    float rstd = rsqrtf(var + 1e-6f);

    for (int e = tid; e < EDIM; e += 256) {
        float o = (buf[e] - mean) * rstd * g[e] + be[e];
        out[base + e] = o;
        out16[base + e] = __float2half(o);
    }
}

// ---------------- mean-pool + head + sigmoid --------------------------------
__global__ void head_kernel(const float* __restrict__ t,
                            const float* __restrict__ hw,
                            const float* __restrict__ hb,
                            float* __restrict__ out) {
    __shared__ float red[256];
    int b = blockIdx.x;
    int tid = threadIdx.x;
    float partial = 0.0f;
    for (int e = tid; e < EDIM; e += 256) {
        float se = 0.0f;
        for (int s = 0; s < SEQ; s++)
            se += t[((long)(b * SEQ + s)) * EDIM + e];
        partial += (se * (1.0f / SEQ)) * hw[e];
    }
    red[tid] = partial;
    __syncthreads();
    for (int s = 128; s > 0; s >>= 1) {
        if (tid < s) red[tid] += red[tid + s];
        __syncthreads();
    }
    if (tid == 0) {
        float z = red[0] + hb[0];
        out[b] = 1.0f / (1.0f + expf(-z));
    }
}

// ---------------- host launch ------------------------------------------------
static inline void launch_gemm(const uint32_t* A, const uint32_t* B, const float* bias,
                               float* C, float* part,
                               int M, int N, int K, int splitk, int relu) {
    dim3 grid(N / 128, M / 128, splitk);
    gemm_f16_kernel<<<grid, 256, GEMM_SMEM>>>(A, B, B, B, bias, bias, bias,
                                              C, C, C, part, M, N, K, splitk, relu);
}

static inline void launch_cvt(const float* W, uint32_t* O, long kp_total, int N) {
    long total = kp_total * N;
    cvt_w_kernel<<<(int)((total + 255) / 256), 256>>>(W, O, total, N);
}

extern "C" void kernel_launch(void* const* d_in, const int* in_sizes, int n_in,
                              void* d_out, int out_size) {
    const float* x       = (const float*)d_in[0];
    const float* conv1_w = (const float*)d_in[1];
    const float* conv1_b = (const float*)d_in[2];
    const float* conv2_w = (const float*)d_in[3];
    const float* conv2_b = (const float*)d_in[4];
    const float* proj_w  = (const float*)d_in[5];
    const float* proj_b  = (const float*)d_in[6];
    const float* Wq = (const float*)d_in[7];
    const float* bq = (const float*)d_in[8];
    const float* Wk = (const float*)d_in[9];
    const float* bk = (const float*)d_in[10];
    const float* Wv = (const float*)d_in[11];
    const float* bv = (const float*)d_in[12];
    const float* Wo = (const float*)d_in[13];
    const float* bo = (const float*)d_in[14];
    const float* W1 = (const float*)d_in[15];
    const float* b1 = (const float*)d_in[16];
    const float* W2 = (const float*)d_in[17];
    const float* b2 = (const float*)d_in[18];
    const float* ln1_g = (const float*)d_in[19];
    const float* ln1_b = (const float*)d_in[20];
    const float* ln2_g = (const float*)d_in[21];
    const float* ln2_b = (const float*)d_in[22];
    const float* head_w = (const float*)d_in[23];
    const float* head_b = (const float*)d_in[24];
    float* out = (float*)d_out;

    float *pool1, *pool2, *t, *q, *k, *v, *o1, *part;
    uint32_t *patch16, *t16, *att16, *o116, *f116;
    uint32_t *wq16, *wk16, *wv16, *wo16, *w116, *w216, *wp16;
    cudaGetSymbolAddress((void**)&pool1, g_pool1);
    cudaGetSymbolAddress((void**)&pool2, g_pool2);
    cudaGetSymbolAddress((void**)&t,  g_t);
    cudaGetSymbolAddress((void**)&q,  g_q);
    cudaGetSymbolAddress((void**)&k,  g_k);
    cudaGetSymbolAddress((void**)&v,  g_v);
    cudaGetSymbolAddress((void**)&o1, g_o1);
    cudaGetSymbolAddress((void**)&part, g_part);
    cudaGetSymbolAddress((void**)&patch16, g_patch16);
    cudaGetSymbolAddress((void**)&t16,  g_t16);
    cudaGetSymbolAddress((void**)&att16, g_att16);
    cudaGetSymbolAddress((void**)&o116, g_o116);
    cudaGetSymbolAddress((void**)&f116, g_f116);
    cudaGetSymbolAddress((void**)&wq16, g_wq16);
    cudaGetSymbolAddress((void**)&wk16, g_wk16);
    cudaGetSymbolAddress((void**)&wv16, g_wv16);
    cudaGetSymbolAddress((void**)&wo16, g_wo16);
    cudaGetSymbolAddress((void**)&w116, g_w116);
    cudaGetSymbolAddress((void**)&w216, g_w216);
    cudaGetSymbolAddress((void**)&wp16, g_wp16);

    const int attn_smem = 4 * 64 * 65 * sizeof(float);
    cudaFuncSetAttribute(attn_kernel, cudaFuncAttributeMaxDynamicSharedMemorySize, attn_smem);
    cudaFuncSetAttribute(gemm_f16_kernel, cudaFuncAttributeMaxDynamicSharedMemorySize, GEMM_SMEM);
    cudaFuncSetAttribute(conv2_pool_kernel, cudaFuncAttributeMaxDynamicSharedMemorySize, C2_SMEM);

    // weight conversion (fp32 -> packed fp16 pairs)
    launch_cvt(proj_w, wp16, PDIM / 2, EDIM);
    launch_cvt(Wq, wq16, (long)NLAYER * EDIM / 2, EDIM);
    launch_cvt(Wk, wk16, (long)NLAYER * EDIM / 2, EDIM);
    launch_cvt(Wv, wv16, (long)NLAYER * EDIM / 2, EDIM);
    launch_cvt(Wo, wo16, (long)NLAYER * EDIM / 2, EDIM);
    launch_cvt(W1, w116, (long)NLAYER * EDIM / 2, FFDIM);
    launch_cvt(W2, w216, (long)NLAYER * FFDIM / 2, EDIM);

    // conv stack (smem-tiled)
    conv1_pool_kernel<<<dim3(16, 16, 16), 256>>>(x, conv1_w, conv1_b, pool1);
    conv2_pool_kernel<<<dim3(8, 8, 16), 256, C2_SMEM>>>(pool1, conv2_w, conv2_b, pool2);
    {
        long np = (long)ROWSM * PDIM;
        patch_kernel<<<(int)((np + 255) / 256), 256>>>(pool2, (__half*)patch16);
    }

    const int MN_E = ROWSM * EDIM;
    const long FP = (long)ROWSM * FFDIM / 2;   // FF1 pairs

    // patch projection (K=4096, splitk=3)
    launch_gemm(patch16, wp16, proj_b, NULL, part, ROWSM, EDIM, PDIM, 3, 0);
    splitk_reduce_kernel<<<(MN_E + 255) / 256, 256>>>(part, proj_b, t, (__half*)t16,
                                                      MN_E, EDIM, 3, 0);

    for (int i = 0; i < NLAYER; i++) {
        const uint32_t* wq = wq16 + (long)i * EDIM * EDIM / 2;
        const uint32_t* wk = wk16 + (long)i * EDIM * EDIM / 2;
        const uint32_t* wv = wv16 + (long)i * EDIM * EDIM / 2;
        const uint32_t* wo = wo16 + (long)i * EDIM * EDIM / 2;
        const uint32_t* w1 = w116 + (long)i * EDIM * FFDIM / 2;
        const uint32_t* w2 = w216 + (long)i * FFDIM * EDIM / 2;

        // fused QKV: z = 3 matrices
        {
            dim3 grid(EDIM / 128, ROWSM / 128, 3);
            gemm_f16_kernel<<<grid, 256, GEMM_SMEM>>>(
                t16, wq, wk, wv,
                bq + i * EDIM, bk + i * EDIM, bv + i * EDIM,
                q, k, v, part, ROWSM, EDIM, EDIM, 1, 0);
        }

        attn_kernel<<<dim3(NHEADS, BB), 256, attn_smem>>>(q, k, v, (__half*)att16);

        // Wo (splitk=3, reduce fused into add+LN)
        launch_gemm(att16, wo, bo + i * EDIM, NULL, part, ROWSM, EDIM, EDIM, 3, 0);
        add_ln_splitk_kernel<<<ROWSM, 256>>>(t, part, bo + i * EDIM,
                                             ln1_g + i * EDIM, ln1_b + i * EDIM,
                                             o1, (__half*)o116, MN_E);

        // FF1: 24x8 = 192 blocks, no split-K; fp32 out into part, then pack fp16
        launch_gemm(o116, w1, b1 + i * FFDIM, part, NULL, ROWSM, FFDIM, EDIM, 1, 1);
        cvt_act_kernel<<<(int)((FP + 255) / 256), 256>>>(part, f116, FP);

        // FF2 (splitk=3, reduce fused into add+LN)
        launch_gemm(f116, w2, b2 + i * EDIM, NULL, part, ROWSM, EDIM, FFDIM, 3, 0);
        add_ln_splitk_kernel<<<ROWSM, 256>>>(o1, part, b2 + i * EDIM,
                                             ln2_g + i * EDIM, ln2_b + i * EDIM,
                                             t, (__half*)t16, MN_E);
    }

    head_kernel<<<BB, 256>>>(t, head_w, head_b, out);
}

// round 12
// speedup vs baseline: 1.5862x; 1.5862x over previous
#include <cuda_runtime.h>
#include <cuda_fp16.h>
#include <math.h>
#include <stdint.h>

// ---------------- model constants ----------------
#define BB     16
#define EDIM   768
#define NHEADS 12
#define HD     64
#define FFDIM  3072
#define NLAYER 8
#define SEQ    64
#define ROWSM  1024     // BB*SEQ
#define PDIM   4096

// ---------------- scratch (device globals) ----------------
__device__ float g_pool1[16 * 255 * 255 * 16];
__device__ float g_pool2[16 * 126 * 126 * 16];
__device__ float g_t [ROWSM * EDIM];
__device__ float g_q [ROWSM * EDIM];
__device__ float g_k [ROWSM * EDIM];
__device__ float g_v [ROWSM * EDIM];
__device__ float g_o1[ROWSM * EDIM];
__device__ float g_part[3 * ROWSM * FFDIM];          // split-K fp32 partials / FF1 fp32 out

// fp16 packed-pair (u32 = 2 halves along K) buffers
__device__ uint32_t g_patch16[ROWSM * PDIM / 2];
__device__ uint32_t g_t16  [ROWSM * EDIM / 2];
__device__ uint32_t g_att16[ROWSM * EDIM / 2];
__device__ uint32_t g_o116 [ROWSM * EDIM / 2];
__device__ uint32_t g_f116 [ROWSM * FFDIM / 2];
// converted weights: [K/2][N] u32, pair = (k, k+1) at fixed n
__device__ uint32_t g_wq16[NLAYER * EDIM * EDIM / 2];
__device__ uint32_t g_wk16[NLAYER * EDIM * EDIM / 2];
__device__ uint32_t g_wv16[NLAYER * EDIM * EDIM / 2];
__device__ uint32_t g_wo16[NLAYER * EDIM * EDIM / 2];
__device__ uint32_t g_w116[NLAYER * EDIM * FFDIM / 2];
__device__ uint32_t g_w216[NLAYER * FFDIM * EDIM / 2];
__device__ uint32_t g_wp16[PDIM * EDIM / 2];

// ---------------- weight conversion: [K][N] fp32 -> [K/2][N] u32 ------------
__global__ void cvt_w_kernel(const float* __restrict__ W, uint32_t* __restrict__ O,
                             long total, int N) {
    long idx = (long)blockIdx.x * 256 + threadIdx.x;
    if (idx >= total) return;
    long kp = idx / N;
    int  n  = (int)(idx - kp * N);
    float a = W[(2 * kp) * (long)N + n];
    float b = W[(2 * kp + 1) * (long)N + n];
    __half2 h = __floats2half2_rn(a, b);
    O[idx] = *(uint32_t*)&h;
}

// ---------------- activation conversion: contiguous fp32 -> packed pairs ----
__global__ void cvt_act_kernel(const float* __restrict__ A, uint32_t* __restrict__ O,
                               long total_pairs) {
    long idx = (long)blockIdx.x * 256 + threadIdx.x;
    if (idx >= total_pairs) return;
    float2 v = *(const float2*)(A + 2 * idx);
    __half2 h = __floats2half2_rn(v.x, v.y);
    O[idx] = *(uint32_t*)&h;
}

// ---------------- conv1 (3x3x3->16) + relu + maxpool (R7 scalar version) ----
__global__ void conv1_pool_kernel(const float* __restrict__ x,
                                  const float* __restrict__ w,
                                  const float* __restrict__ bias,
                                  float* __restrict__ out) {
    __shared__ float ws[432];
    __shared__ float bs[16];
    int tid = threadIdx.x;
    for (int i = tid; i < 432; i += 256) ws[i] = w[i];
    if (tid < 16) bs[tid] = bias[tid];
    __syncthreads();

    int idx = blockIdx.x * 256 + tid;
    if (idx >= 16 * 255 * 255) return;
    int pw = idx % 255;
    int t  = idx / 255;
    int ph = t % 255;
    int b  = t / 255;

    float mx[16];
#pragma unroll
    for (int c = 0; c < 16; c++) mx[c] = 0.0f;

    for (int dy = 0; dy < 2; dy++) {
        for (int dx = 0; dx < 2; dx++) {
            int h0 = 2 * ph + dy;
            int w0 = 2 * pw + dx;
            float acc[16];
#pragma unroll
            for (int c = 0; c < 16; c++) acc[c] = bs[c];
            for (int kh = 0; kh < 3; kh++) {
                for (int kw = 0; kw < 3; kw++) {
                    const float* xp = x + (((long)(b * 512 + h0 + kh) * 512) + (w0 + kw)) * 3;
                    float x0 = xp[0], x1 = xp[1], x2 = xp[2];
                    const float* wp = ws + ((kh * 3 + kw) * 3) * 16;
#pragma unroll
                    for (int c = 0; c < 16; c++)
                        acc[c] += x0 * wp[c] + x1 * wp[16 + c] + x2 * wp[32 + c];
                }
            }
#pragma unroll
            for (int c = 0; c < 16; c++) mx[c] = fmaxf(mx[c], fmaxf(acc[c], 0.0f));
        }
    }
    float* op = out + (long)idx * 16;
#pragma unroll
    for (int c = 0; c < 16; c++) op[c] = mx[c];
}

// ---------------- conv2 (3x3x16->16) + relu + maxpool (R7 scalar version) ---
__global__ void conv2_pool_kernel(const float* __restrict__ in,
                                  const float* __restrict__ w,
                                  const float* __restrict__ bias,
                                  float* __restrict__ out) {
    __shared__ float ws[2304];
    __shared__ float bs[16];
    int tid = threadIdx.x;
    for (int i = tid; i < 2304; i += 256) ws[i] = w[i];
    if (tid < 16) bs[tid] = bias[tid];
    __syncthreads();

    int idx = blockIdx.x * 256 + tid;
    if (idx >= 16 * 126 * 126) return;
    int pw = idx % 126;
    int t  = idx / 126;
    int ph = t % 126;
    int b  = t / 126;

    float mx[16];
#pragma unroll
    for (int c = 0; c < 16; c++) mx[c] = 0.0f;

    for (int dy = 0; dy < 2; dy++) {
        for (int dx = 0; dx < 2; dx++) {
            int h0 = 2 * ph + dy;
            int w0 = 2 * pw + dx;
            float acc[16];
#pragma unroll
            for (int c = 0; c < 16; c++) acc[c] = bs[c];
            for (int kh = 0; kh < 3; kh++) {
                for (int kw = 0; kw < 3; kw++) {
                    const float* xp = in + ((long)(b * 255 + h0 + kh) * 255 + (w0 + kw)) * 16;
                    float xv[16];
#pragma unroll
                    for (int ci = 0; ci < 16; ci++) xv[ci] = xp[ci];
                    const float* wp = ws + ((kh * 3 + kw) * 16) * 16;
#pragma unroll
                    for (int ci = 0; ci < 16; ci++) {
#pragma unroll
                        for (int c = 0; c < 16; c++)
                            acc[c] += xv[ci] * wp[ci * 16 + c];
                    }
                }
            }
#pragma unroll
            for (int c = 0; c < 16; c++) mx[c] = fmaxf(mx[c], fmaxf(acc[c], 0.0f));
        }
    }
    float* op = out + (long)idx * 16;
#pragma unroll
    for (int c = 0; c < 16; c++) op[c] = mx[c];
}

// ---------------- patch gather -> fp16 ---------------------------------------
__global__ void patch_kernel(const float* __restrict__ pool2,
                             __half* __restrict__ patches16) {
    long idx = (long)blockIdx.x * 256 + threadIdx.x;
    if (idx >= (long)ROWSM * PDIM) return;
    int d   = (int)(idx & (PDIM - 1));
    int row = (int)(idx >> 12);
    int b   = row >> 6;
    int p   = row & 63;
    int pr  = p >> 3, pc = p & 7;
    int r   = d >> 8;
    int c   = (d >> 4) & 15;
    int ch  = d & 15;
    int H = pr * 16 + r;
    int W = pc * 16 + c;
    float v = 0.0f;
    if (H >= 1 && H <= 126 && W >= 1 && W <= 126)
        v = pool2[((long)(b * 126 + (H - 1)) * 126 + (W - 1)) * 16 + ch];
    patches16[idx] = __float2half(v);
}

// ---------------- FP16 tensor-core GEMM (exact R7 version) -------------------
__device__ __forceinline__ void mma_f16(float* d, const uint32_t* a, const uint32_t* b) {
    asm volatile(
        "mma.sync.aligned.m16n8k16.row.col.f32.f16.f16.f32 "
        "{%0,%1,%2,%3}, {%4,%5,%6,%7}, {%8,%9}, {%0,%1,%2,%3};\n"
        : "+f"(d[0]), "+f"(d[1]), "+f"(d[2]), "+f"(d[3])
        : "r"(a[0]), "r"(a[1]), "r"(a[2]), "r"(a[3]), "r"(b[0]), "r"(b[1]));
}

__device__ __forceinline__ void cp16s(uint32_t saddr, const void* gsrc) {
    asm volatile("cp.async.cg.shared.global [%0], [%1], 16;\n" :: "r"(saddr), "l"(gsrc));
}
__device__ __forceinline__ void cp_commit() { asm volatile("cp.async.commit_group;\n"); }
template <int N> __device__ __forceinline__ void cp_wait() {
    asm volatile("cp.async.wait_group %0;\n" :: "n"(N));
}

#define ASTR 36
#define BSTR 136
#define AS_TILE (128 * ASTR)
#define BS_TILE (32 * BSTR)
#define STAGE_U32 (AS_TILE + BS_TILE)
#define NSTAGE 3
#define GEMM_SMEM (NSTAGE * STAGE_U32 * 4)   // 107520 B

__global__ __launch_bounds__(256, 2) void gemm_f16_kernel(
    const uint32_t* __restrict__ A,
    const uint32_t* __restrict__ Bp0, const uint32_t* __restrict__ Bp1,
    const uint32_t* __restrict__ Bp2,
    const float* __restrict__ bi0, const float* __restrict__ bi1,
    const float* __restrict__ bi2,
    float* __restrict__ Cp0, float* __restrict__ Cp1, float* __restrict__ Cp2,
    float* __restrict__ part,
    int M, int N, int K, int splitk, int relu)
{
    extern __shared__ uint32_t smu[];

    const int z   = blockIdx.z;
    const int mat = z / splitk;
    const int kz  = z - mat * splitk;
    const uint32_t* B  = mat == 0 ? Bp0 : (mat == 1 ? Bp1 : Bp2);
    const float*    bi = mat == 0 ? bi0 : (mat == 1 ? bi1 : bi2);
    float*          C  = mat == 0 ? Cp0 : (mat == 1 ? Cp1 : Cp2);

    const int tid  = threadIdx.x;
    const int lane = tid & 31;
    const int warp = tid >> 5;
    const int wm   = warp & 3;
    const int wn   = warp >> 2;
    const int gid  = lane >> 2;
    const int tkc  = lane & 3;

    const int bm = blockIdx.y * 128;
    const int bn = blockIdx.x * 128;

    const int KP   = K >> 1;
    const int ktot = K >> 6;
    const int ktb  = (kz * ktot) / splitk;
    const int kte  = ((kz + 1) * ktot) / splitk;
    const int nkt  = kte - ktb;

    const int rowA = tid >> 3;
    const int segA = (tid & 7) * 4;
    const int rowB = tid >> 5;
    const int segB = (tid & 31) * 4;
    const uint32_t* pA = A + (long)(bm + rowA) * KP + ktb * 32 + segA;
    const uint32_t* pB = B + (long)(ktb * 32 + rowB) * N + bn + segB;
    const uint32_t sbase = (uint32_t)__cvta_generic_to_shared(smu);
    const uint32_t sA = sbase + (rowA * ASTR + segA) * 4;
    const uint32_t sB = sbase + (AS_TILE + rowB * BSTR + segB) * 4;

    auto issue = [&](int i) {
        const uint32_t off = (uint32_t)((i % NSTAGE) * STAGE_U32 * 4);
        const long kf = (long)i * 32;
#pragma unroll
        for (int t = 0; t < 4; t++)
            cp16s(sA + off + t * (32 * ASTR * 4), pA + t * 32 * (long)KP + kf);
#pragma unroll
        for (int t = 0; t < 4; t++)
            cp16s(sB + off + t * (8 * BSTR * 4), pB + (kf + t * 8) * (long)N);
    };

    issue(0); cp_commit();
    if (nkt > 1) { issue(1); }
    cp_commit();

    float acc[2][8][4];
#pragma unroll
    for (int mc = 0; mc < 2; mc++)
#pragma unroll
        for (int nc = 0; nc < 8; nc++)
#pragma unroll
            for (int i = 0; i < 4; i++) acc[mc][nc][i] = 0.0f;

    for (int i = 0; i < nkt; i++) {
        cp_wait<1>();
        __syncthreads();
        if (i + 2 < nkt) issue(i + 2);
        cp_commit();

        const uint32_t* as = smu + (i % NSTAGE) * STAGE_U32;
        const uint32_t* bs = as + AS_TILE;

#pragma unroll
        for (int ks = 0; ks < 4; ks++) {
            const int kc = ks * 8 + tkc;
            uint32_t af[2][4];
#pragma unroll
            for (int mc = 0; mc < 2; mc++) {
                const int r = wm * 32 + mc * 16 + gid;
                af[mc][0] = as[r * ASTR + kc];
                af[mc][1] = as[(r + 8) * ASTR + kc];
                af[mc][2] = as[r * ASTR + kc + 4];
                af[mc][3] = as[(r + 8) * ASTR + kc + 4];
            }
#pragma unroll
            for (int nc = 0; nc < 8; nc++) {
                uint32_t bf[2];
                const int c = wn * 64 + nc * 8 + gid;
                bf[0] = bs[kc * BSTR + c];
                bf[1] = bs[(kc + 4) * BSTR + c];
                mma_f16(acc[0][nc], af[0], bf);
                mma_f16(acc[1][nc], af[1], bf);
            }
        }
    }

    if (splitk == 1) {
#pragma unroll
        for (int mc = 0; mc < 2; mc++) {
            const int r0 = bm + wm * 32 + mc * 16 + gid;
#pragma unroll
            for (int nc = 0; nc < 8; nc++) {
                const int col = bn + wn * 64 + nc * 8 + 2 * tkc;
                const float b0 = bi[col], b1 = bi[col + 1];
                float v0 = acc[mc][nc][0] + b0;
                float v1 = acc[mc][nc][1] + b1;
                float v2 = acc[mc][nc][2] + b0;
                float v3 = acc[mc][nc][3] + b1;
                if (relu) {
                    v0 = fmaxf(v0, 0.f); v1 = fmaxf(v1, 0.f);
                    v2 = fmaxf(v2, 0.f); v3 = fmaxf(v3, 0.f);
                }
                *(float2*)&C[(long)r0 * N + col]       = make_float2(v0, v1);
                *(float2*)&C[(long)(r0 + 8) * N + col] = make_float2(v2, v3);
            }
        }
    } else {
        float* P0 = part + (long)z * M * N;
#pragma unroll
        for (int mc = 0; mc < 2; mc++) {
            const int r0 = bm + wm * 32 + mc * 16 + gid;
#pragma unroll
            for (int nc = 0; nc < 8; nc++) {
                const int col = bn + wn * 64 + nc * 8 + 2 * tkc;
                *(float2*)&P0[(long)r0 * N + col]       = make_float2(acc[mc][nc][0], acc[mc][nc][1]);
                *(float2*)&P0[(long)(r0 + 8) * N + col] = make_float2(acc[mc][nc][2], acc[mc][nc][3]);
            }
        }
    }
}

// ordered split-K reduce + bias (+relu); optional fp32 and fp16 outputs
__global__ void splitk_reduce_kernel(const float* __restrict__ part,
                                     const float* __restrict__ bias,
                                     float* __restrict__ Cf,
                                     __half* __restrict__ Chh,
                                     int MN, int N, int splitk, int relu) {
    int idx = blockIdx.x * 256 + threadIdx.x;
    if (idx >= MN) return;
    float s = part[idx];
    for (int zz = 1; zz < splitk; zz++) s += part[(long)zz * MN + idx];
    s += bias[idx % N];
    if (relu) s = fmaxf(s, 0.0f);
    if (Cf) Cf[idx] = s;
    if (Chh) Chh[idx] = __float2half(s);
}

// ---------------- attention: one block per (b, head); fp16 output -----------
__global__ void attn_kernel(const float* __restrict__ Q,
                            const float* __restrict__ K,
                            const float* __restrict__ V,
                            __half* __restrict__ O16) {
    extern __shared__ float sm[];
    float* qs = sm;
    float* ks = qs + 64 * 65;
    float* vs = ks + 64 * 65;
    float* ss = vs + 64 * 65;

    int h = blockIdx.x;
    int b = blockIdx.y;
    int tid = threadIdx.x;

    for (int e = tid; e < 4096; e += 256) {
        int s = e >> 6, d = e & 63;
        long base = ((long)(b * 64 + s) * EDIM) + h * 64 + d;
        qs[s * 65 + d] = Q[base];
        ks[s * 65 + d] = K[base];
        vs[s * 65 + d] = V[base];
    }
    __syncthreads();

    for (int e = tid; e < 4096; e += 256) {
        int row = e >> 6, col = e & 63;
        float sum = 0.0f;
#pragma unroll 16
        for (int dd = 0; dd < 64; dd++)
            sum += qs[row * 65 + dd] * ks[col * 65 + dd];
        ss[row * 65 + col] = sum * 0.125f;
    }
    __syncthreads();

    if (tid < 64) {
        float* r = ss + tid * 65;
        float m = r[0];
#pragma unroll 16
        for (int c = 1; c < 64; c++) m = fmaxf(m, r[c]);
        float sum = 0.0f;
#pragma unroll 16
        for (int c = 0; c < 64; c++) { float e = expf(r[c] - m); r[c] = e; sum += e; }
        float inv = 1.0f / sum;
#pragma unroll 16
        for (int c = 0; c < 64; c++) r[c] *= inv;
    }
    __syncthreads();

    for (int e = tid; e < 4096; e += 256) {
        int row = e >> 6, d = e & 63;
        float sum = 0.0f;
#pragma unroll 16
        for (int col = 0; col < 64; col++)
            sum += ss[row * 65 + col] * vs[col * 65 + d];
        O16[(long)b * (NHEADS * SEQ * HD) + h * 4096 + row * 64 + d] = __float2half(sum);
    }
}

// ------ fused: y = 3 splitk partials + bias; out = LN(x + y), fp32+fp16 -----
__global__ void add_ln_splitk_kernel(const float* __restrict__ x,
                                     const float* __restrict__ part,
                                     const float* __restrict__ gb,
                                     const float* __restrict__ g,
                                     const float* __restrict__ be,
                                     float* __restrict__ out,
                                     __half* __restrict__ out16,
                                     int MN) {
    __shared__ float buf[EDIM];
    __shared__ float red[256];
    int row = blockIdx.x;
    int tid = threadIdx.x;
    long base = (long)row * EDIM;

    float partial = 0.0f;
    for (int e = tid; e < EDIM; e += 256) {
        float y = part[base + e] + part[MN + base + e] + part[2L * MN + base + e] + gb[e];
        float v = x[base + e] + y;
        buf[e] = v;
        partial += v;
    }
    red[tid] = partial;
    __syncthreads();
    for (int s = 128; s > 0; s >>= 1) {
        if (tid < s) red[tid] += red[tid + s];
        __syncthreads();
    }
    float mean = red[0] * (1.0f / EDIM);
    __syncthreads();

    float p2 = 0.0f;
    for (int e = tid; e < EDIM; e += 256) {
        float d = buf[e] - mean;
        p2 += d * d;
    }
    red[tid] = p2;
    __syncthreads();
    for (int s = 128; s > 0; s >>= 1) {
        if (tid < s) red[tid] += red[tid + s];
        __syncthreads();
    }
    float var = red[0] * (1.0f / EDIM);
    float rstd = rsqrtf(var + 1e-6f);

    for (int e = tid; e < EDIM; e += 256) {
        float o = (buf[e] - mean) * rstd * g[e] + be[e];
        out[base + e] = o;
        out16[base + e] = __float2half(o);
    }
}

// ---------------- mean-pool + head + sigmoid --------------------------------
__global__ void head_kernel(const float* __restrict__ t,
                            const float* __restrict__ hw,
                            const float* __restrict__ hb,
                            float* __restrict__ out) {
    __shared__ float red[256];
    int b = blockIdx.x;
    int tid = threadIdx.x;
    float partial = 0.0f;
    for (int e = tid; e < EDIM; e += 256) {
        float se = 0.0f;
        for (int s = 0; s < SEQ; s++)
            se += t[((long)(b * SEQ + s)) * EDIM + e];
        partial += (se * (1.0f / SEQ)) * hw[e];
    }
    red[tid] = partial;
    __syncthreads();
    for (int s = 128; s > 0; s >>= 1) {
        if (tid < s) red[tid] += red[tid + s];
        __syncthreads();
    }
    if (tid == 0) {
        float z = red[0] + hb[0];
        out[b] = 1.0f / (1.0f + expf(-z));
    }
}

// ---------------- host launch ------------------------------------------------
static inline void launch_gemm(const uint32_t* A, const uint32_t* B, const float* bias,
                               float* C, float* part,
                               int M, int N, int K, int splitk, int relu) {
    dim3 grid(N / 128, M / 128, splitk);
    gemm_f16_kernel<<<grid, 256, GEMM_SMEM>>>(A, B, B, B, bias, bias, bias,
                                              C, C, C, part, M, N, K, splitk, relu);
}

static inline void launch_cvt(const float* W, uint32_t* O, long kp_total, int N) {
    long total = kp_total * N;
    cvt_w_kernel<<<(int)((total + 255) / 256), 256>>>(W, O, total, N);
}

extern "C" void kernel_launch(void* const* d_in, const int* in_sizes, int n_in,
                              void* d_out, int out_size) {
    const float* x       = (const float*)d_in[0];
    const float* conv1_w = (const float*)d_in[1];
    const float* conv1_b = (const float*)d_in[2];
    const float* conv2_w = (const float*)d_in[3];
    const float* conv2_b = (const float*)d_in[4];
    const float* proj_w  = (const float*)d_in[5];
    const float* proj_b  = (const float*)d_in[6];
    const float* Wq = (const float*)d_in[7];
    const float* bq = (const float*)d_in[8];
    const float* Wk = (const float*)d_in[9];
    const float* bk = (const float*)d_in[10];
    const float* Wv = (const float*)d_in[11];
    const float* bv = (const float*)d_in[12];
    const float* Wo = (const float*)d_in[13];
    const float* bo = (const float*)d_in[14];
    const float* W1 = (const float*)d_in[15];
    const float* b1 = (const float*)d_in[16];
    const float* W2 = (const float*)d_in[17];
    const float* b2 = (const float*)d_in[18];
    const float* ln1_g = (const float*)d_in[19];
    const float* ln1_b = (const float*)d_in[20];
    const float* ln2_g = (const float*)d_in[21];
    const float* ln2_b = (const float*)d_in[22];
    const float* head_w = (const float*)d_in[23];
    const float* head_b = (const float*)d_in[24];
    float* out = (float*)d_out;

    float *pool1, *pool2, *t, *q, *k, *v, *o1, *part;
    uint32_t *patch16, *t16, *att16, *o116, *f116;
    uint32_t *wq16, *wk16, *wv16, *wo16, *w116, *w216, *wp16;
    cudaGetSymbolAddress((void**)&pool1, g_pool1);
    cudaGetSymbolAddress((void**)&pool2, g_pool2);
    cudaGetSymbolAddress((void**)&t,  g_t);
    cudaGetSymbolAddress((void**)&q,  g_q);
    cudaGetSymbolAddress((void**)&k,  g_k);
    cudaGetSymbolAddress((void**)&v,  g_v);
    cudaGetSymbolAddress((void**)&o1, g_o1);
    cudaGetSymbolAddress((void**)&part, g_part);
    cudaGetSymbolAddress((void**)&patch16, g_patch16);
    cudaGetSymbolAddress((void**)&t16,  g_t16);
    cudaGetSymbolAddress((void**)&att16, g_att16);
    cudaGetSymbolAddress((void**)&o116, g_o116);
    cudaGetSymbolAddress((void**)&f116, g_f116);
    cudaGetSymbolAddress((void**)&wq16, g_wq16);
    cudaGetSymbolAddress((void**)&wk16, g_wk16);
    cudaGetSymbolAddress((void**)&wv16, g_wv16);
    cudaGetSymbolAddress((void**)&wo16, g_wo16);
    cudaGetSymbolAddress((void**)&w116, g_w116);
    cudaGetSymbolAddress((void**)&w216, g_w216);
    cudaGetSymbolAddress((void**)&wp16, g_wp16);

    const int attn_smem = 4 * 64 * 65 * sizeof(float);
    cudaFuncSetAttribute(attn_kernel, cudaFuncAttributeMaxDynamicSharedMemorySize, attn_smem);
    cudaFuncSetAttribute(gemm_f16_kernel, cudaFuncAttributeMaxDynamicSharedMemorySize, GEMM_SMEM);

    // weight conversion (fp32 -> packed fp16 pairs)
    launch_cvt(proj_w, wp16, PDIM / 2, EDIM);
    launch_cvt(Wq, wq16, (long)NLAYER * EDIM / 2, EDIM);
    launch_cvt(Wk, wk16, (long)NLAYER * EDIM / 2, EDIM);
    launch_cvt(Wv, wv16, (long)NLAYER * EDIM / 2, EDIM);
    launch_cvt(Wo, wo16, (long)NLAYER * EDIM / 2, EDIM);
    launch_cvt(W1, w116, (long)NLAYER * EDIM / 2, FFDIM);
    launch_cvt(W2, w216, (long)NLAYER * FFDIM / 2, EDIM);

    // conv stack (R7 scalar versions)
    {
        int n1 = 16 * 255 * 255;
        conv1_pool_kernel<<<(n1 + 255) / 256, 256>>>(x, conv1_w, conv1_b, pool1);
        int n2 = 16 * 126 * 126;
        conv2_pool_kernel<<<(n2 + 255) / 256, 256>>>(pool1, conv2_w, conv2_b, pool2);
        long np = (long)ROWSM * PDIM;
        patch_kernel<<<(int)((np + 255) / 256), 256>>>(pool2, (__half*)patch16);
    }

    const int MN_E = ROWSM * EDIM;
    const long FP = (long)ROWSM * FFDIM / 2;   // FF1 pairs

    // patch projection (K=4096, splitk=3)
    launch_gemm(patch16, wp16, proj_b, NULL, part, ROWSM, EDIM, PDIM, 3, 0);
    splitk_reduce_kernel<<<(MN_E + 255) / 256, 256>>>(part, proj_b, t, (__half*)t16,
                                                      MN_E, EDIM, 3, 0);

    for (int i = 0; i < NLAYER; i++) {
        const uint32_t* wq = wq16 + (long)i * EDIM * EDIM / 2;
        const uint32_t* wk = wk16 + (long)i * EDIM * EDIM / 2;
        const uint32_t* wv = wv16 + (long)i * EDIM * EDIM / 2;
        const uint32_t* wo = wo16 + (long)i * EDIM * EDIM / 2;
        const uint32_t* w1 = w116 + (long)i * EDIM * FFDIM / 2;
        const uint32_t* w2 = w216 + (long)i * FFDIM * EDIM / 2;

        // fused QKV: z = 3 matrices
        {
            dim3 grid(EDIM / 128, ROWSM / 128, 3);
            gemm_f16_kernel<<<grid, 256, GEMM_SMEM>>>(
                t16, wq, wk, wv,
                bq + i * EDIM, bk + i * EDIM, bv + i * EDIM,
                q, k, v, part, ROWSM, EDIM, EDIM, 1, 0);
        }

        attn_kernel<<<dim3(NHEADS, BB), 256, attn_smem>>>(q, k, v, (__half*)att16);

        // Wo (splitk=3, reduce fused into add+LN)
        launch_gemm(att16, wo, bo + i * EDIM, NULL, part, ROWSM, EDIM, EDIM, 3, 0);
        add_ln_splitk_kernel<<<ROWSM, 256>>>(t, part, bo + i * EDIM,
                                             ln1_g + i * EDIM, ln1_b + i * EDIM,
                                             o1, (__half*)o116, MN_E);

        // FF1: 24x8 = 192 blocks, no split-K; fp32 out into part, then pack fp16
        launch_gemm(o116, w1, b1 + i * FFDIM, part, NULL, ROWSM, FFDIM, EDIM, 1, 1);
        cvt_act_kernel<<<(int)((FP + 255) / 256), 256>>>(part, f116, FP);

        // FF2 (splitk=3, reduce fused into add+LN)
        launch_gemm(f116, w2, b2 + i * EDIM, NULL, part, ROWSM, EDIM, FFDIM, 3, 0);
        add_ln_splitk_kernel<<<ROWSM, 256>>>(o1, part, b2 + i * EDIM,
                                             ln2_g + i * EDIM, ln2_b + i * EDIM,
                                             t, (__half*)t16, MN_E);
    }

    head_kernel<<<BB, 256>>>(t, head_w, head_b, out);
}

// round 13
// speedup vs baseline: 1.6506x; 1.0406x over previous
#include <cuda_runtime.h>
#include <cuda_fp16.h>
#include <math.h>
#include <stdint.h>

// ---------------- model constants ----------------
#define BB     16
#define EDIM   768
#define NHEADS 12
#define HD     64
#define FFDIM  3072
#define NLAYER 8
#define SEQ    64
#define ROWSM  1024     // BB*SEQ
#define PDIM   4096

// ---------------- scratch (device globals) ----------------
__device__ float g_pool1[16 * 255 * 255 * 16];
__device__ float g_pool2[16 * 126 * 126 * 16];
__device__ float g_t [ROWSM * EDIM];
__device__ float g_o1[ROWSM * EDIM];
__device__ float g_part[3 * ROWSM * FFDIM];          // split-K fp32 partials

// fp16 packed-pair (u32 = 2 halves along K) buffers
__device__ uint32_t g_patch16[ROWSM * PDIM / 2];
__device__ uint32_t g_t16  [ROWSM * EDIM / 2];
__device__ uint32_t g_q16 [ROWSM * EDIM / 2];
__device__ uint32_t g_k16 [ROWSM * EDIM / 2];
__device__ uint32_t g_v16 [ROWSM * EDIM / 2];
__device__ uint32_t g_att16[ROWSM * EDIM / 2];
__device__ uint32_t g_o116 [ROWSM * EDIM / 2];
__device__ uint32_t g_f116 [ROWSM * FFDIM / 2];
// converted weights: [K/2][N] u32, pair = (k, k+1) at fixed n
__device__ uint32_t g_wq16[NLAYER * EDIM * EDIM / 2];
__device__ uint32_t g_wk16[NLAYER * EDIM * EDIM / 2];
__device__ uint32_t g_wv16[NLAYER * EDIM * EDIM / 2];
__device__ uint32_t g_wo16[NLAYER * EDIM * EDIM / 2];
__device__ uint32_t g_w116[NLAYER * EDIM * FFDIM / 2];
__device__ uint32_t g_w216[NLAYER * FFDIM * EDIM / 2];
__device__ uint32_t g_wp16[PDIM * EDIM / 2];

// ------- weight conversion (vectorized): [K][N] fp32 -> [K/2][N] u32 --------
// one thread = 4 consecutive n at fixed kp; N % 4 == 0.
__global__ void cvt_w_kernel(const float* __restrict__ W, uint32_t* __restrict__ O,
                             long total4, int N) {
    long idx4 = (long)blockIdx.x * 256 + threadIdx.x;
    if (idx4 >= total4) return;
    long idx = idx4 * 4;
    long kp = idx / N;
    int  n  = (int)(idx - kp * N);
    const float4 a = *(const float4*)(W + (2 * kp) * (long)N + n);
    const float4 b = *(const float4*)(W + (2 * kp + 1) * (long)N + n);
    uint4 o;
    __half2 h;
    h = __floats2half2_rn(a.x, b.x); o.x = *(uint32_t*)&h;
    h = __floats2half2_rn(a.y, b.y); o.y = *(uint32_t*)&h;
    h = __floats2half2_rn(a.z, b.z); o.z = *(uint32_t*)&h;
    h = __floats2half2_rn(a.w, b.w); o.w = *(uint32_t*)&h;
    *(uint4*)(O + idx) = o;
}

// ---------------- conv1 (3x3x3->16) + relu + maxpool (R7 scalar version) ----
__global__ void conv1_pool_kernel(const float* __restrict__ x,
                                  const float* __restrict__ w,
                                  const float* __restrict__ bias,
                                  float* __restrict__ out) {
    __shared__ float ws[432];
    __shared__ float bs[16];
    int tid = threadIdx.x;
    for (int i = tid; i < 432; i += 256) ws[i] = w[i];
    if (tid < 16) bs[tid] = bias[tid];
    __syncthreads();

    int idx = blockIdx.x * 256 + tid;
    if (idx >= 16 * 255 * 255) return;
    int pw = idx % 255;
    int t  = idx / 255;
    int ph = t % 255;
    int b  = t / 255;

    float mx[16];
#pragma unroll
    for (int c = 0; c < 16; c++) mx[c] = 0.0f;

    for (int dy = 0; dy < 2; dy++) {
        for (int dx = 0; dx < 2; dx++) {
            int h0 = 2 * ph + dy;
            int w0 = 2 * pw + dx;
            float acc[16];
#pragma unroll
            for (int c = 0; c < 16; c++) acc[c] = bs[c];
            for (int kh = 0; kh < 3; kh++) {
                for (int kw = 0; kw < 3; kw++) {
                    const float* xp = x + (((long)(b * 512 + h0 + kh) * 512) + (w0 + kw)) * 3;
                    float x0 = xp[0], x1 = xp[1], x2 = xp[2];
                    const float* wp = ws + ((kh * 3 + kw) * 3) * 16;
#pragma unroll
                    for (int c = 0; c < 16; c++)
                        acc[c] += x0 * wp[c] + x1 * wp[16 + c] + x2 * wp[32 + c];
                }
            }
#pragma unroll
            for (int c = 0; c < 16; c++) mx[c] = fmaxf(mx[c], fmaxf(acc[c], 0.0f));
        }
    }
    float* op = out + (long)idx * 16;
#pragma unroll
    for (int c = 0; c < 16; c++) op[c] = mx[c];
}

// ---------------- conv2 (3x3x16->16) + relu + maxpool (R7 scalar version) ---
__global__ void conv2_pool_kernel(const float* __restrict__ in,
                                  const float* __restrict__ w,
                                  const float* __restrict__ bias,
                                  float* __restrict__ out) {
    __shared__ float ws[2304];
    __shared__ float bs[16];
    int tid = threadIdx.x;
    for (int i = tid; i < 2304; i += 256) ws[i] = w[i];
    if (tid < 16) bs[tid] = bias[tid];
    __syncthreads();

    int idx = blockIdx.x * 256 + tid;
    if (idx >= 16 * 126 * 126) return;
    int pw = idx % 126;
    int t  = idx / 126;
    int ph = t % 126;
    int b  = t / 126;

    float mx[16];
#pragma unroll
    for (int c = 0; c < 16; c++) mx[c] = 0.0f;

    for (int dy = 0; dy < 2; dy++) {
        for (int dx = 0; dx < 2; dx++) {
            int h0 = 2 * ph + dy;
            int w0 = 2 * pw + dx;
            float acc[16];
#pragma unroll
            for (int c = 0; c < 16; c++) acc[c] = bs[c];
            for (int kh = 0; kh < 3; kh++) {
                for (int kw = 0; kw < 3; kw++) {
                    const float* xp = in + ((long)(b * 255 + h0 + kh) * 255 + (w0 + kw)) * 16;
                    float xv[16];
#pragma unroll
                    for (int ci = 0; ci < 16; ci++) xv[ci] = xp[ci];
                    const float* wp = ws + ((kh * 3 + kw) * 16) * 16;
#pragma unroll
                    for (int ci = 0; ci < 16; ci++) {
#pragma unroll
                        for (int c = 0; c < 16; c++)
                            acc[c] += xv[ci] * wp[ci * 16 + c];
                    }
                }
            }
#pragma unroll
            for (int c = 0; c < 16; c++) mx[c] = fmaxf(mx[c], fmaxf(acc[c], 0.0f));
        }
    }
    float* op = out + (long)idx * 16;
#pragma unroll
    for (int c = 0; c < 16; c++) op[c] = mx[c];
}

// ---------------- patch gather -> fp16 ---------------------------------------
__global__ void patch_kernel(const float* __restrict__ pool2,
                             __half* __restrict__ patches16) {
    long idx = (long)blockIdx.x * 256 + threadIdx.x;
    if (idx >= (long)ROWSM * PDIM) return;
    int d   = (int)(idx & (PDIM - 1));
    int row = (int)(idx >> 12);
    int b   = row >> 6;
    int p   = row & 63;
    int pr  = p >> 3, pc = p & 7;
    int r   = d >> 8;
    int c   = (d >> 4) & 15;
    int ch  = d & 15;
    int H = pr * 16 + r;
    int W = pc * 16 + c;
    float v = 0.0f;
    if (H >= 1 && H <= 126 && W >= 1 && W <= 126)
        v = pool2[((long)(b * 126 + (H - 1)) * 126 + (W - 1)) * 16 + ch];
    patches16[idx] = __float2half(v);
}

// ---------------- FP16 tensor-core GEMM --------------------------------------
// splitk==1: writes fp16 to Chx if non-null, else fp32 to Cpx.
__device__ __forceinline__ void mma_f16(float* d, const uint32_t* a, const uint32_t* b) {
    asm volatile(
        "mma.sync.aligned.m16n8k16.row.col.f32.f16.f16.f32 "
        "{%0,%1,%2,%3}, {%4,%5,%6,%7}, {%8,%9}, {%0,%1,%2,%3};\n"
        : "+f"(d[0]), "+f"(d[1]), "+f"(d[2]), "+f"(d[3])
        : "r"(a[0]), "r"(a[1]), "r"(a[2]), "r"(a[3]), "r"(b[0]), "r"(b[1]));
}

__device__ __forceinline__ void cp16s(uint32_t saddr, const void* gsrc) {
    asm volatile("cp.async.cg.shared.global [%0], [%1], 16;\n" :: "r"(saddr), "l"(gsrc));
}
__device__ __forceinline__ void cp_commit() { asm volatile("cp.async.commit_group;\n"); }
template <int N> __device__ __forceinline__ void cp_wait() {
    asm volatile("cp.async.wait_group %0;\n" :: "n"(N));
}

#define ASTR 36
#define BSTR 136
#define AS_TILE (128 * ASTR)
#define BS_TILE (32 * BSTR)
#define STAGE_U32 (AS_TILE + BS_TILE)
#define NSTAGE 3
#define GEMM_SMEM (NSTAGE * STAGE_U32 * 4)   // 107520 B

__global__ __launch_bounds__(256, 2) void gemm_f16_kernel(
    const uint32_t* __restrict__ A,
    const uint32_t* __restrict__ Bp0, const uint32_t* __restrict__ Bp1,
    const uint32_t* __restrict__ Bp2,
    const float* __restrict__ bi0, const float* __restrict__ bi1,
    const float* __restrict__ bi2,
    float* __restrict__ Cp0, float* __restrict__ Cp1, float* __restrict__ Cp2,
    __half* __restrict__ Ch0, __half* __restrict__ Ch1, __half* __restrict__ Ch2,
    float* __restrict__ part,
    int M, int N, int K, int splitk, int relu)
{
    extern __shared__ uint32_t smu[];

    const int z   = blockIdx.z;
    const int mat = z / splitk;
    const int kz  = z - mat * splitk;
    const uint32_t* B  = mat == 0 ? Bp0 : (mat == 1 ? Bp1 : Bp2);
    const float*    bi = mat == 0 ? bi0 : (mat == 1 ? bi1 : bi2);
    float*          C  = mat == 0 ? Cp0 : (mat == 1 ? Cp1 : Cp2);
    __half*         Ch = mat == 0 ? Ch0 : (mat == 1 ? Ch1 : Ch2);

    const int tid  = threadIdx.x;
    const int lane = tid & 31;
    const int warp = tid >> 5;
    const int wm   = warp & 3;
    const int wn   = warp >> 2;
    const int gid  = lane >> 2;
    const int tkc  = lane & 3;

    const int bm = blockIdx.y * 128;
    const int bn = blockIdx.x * 128;

    const int KP   = K >> 1;
    const int ktot = K >> 6;
    const int ktb  = (kz * ktot) / splitk;
    const int kte  = ((kz + 1) * ktot) / splitk;
    const int nkt  = kte - ktb;

    const int rowA = tid >> 3;
    const int segA = (tid & 7) * 4;
    const int rowB = tid >> 5;
    const int segB = (tid & 31) * 4;
    const uint32_t* pA = A + (long)(bm + rowA) * KP + ktb * 32 + segA;
    const uint32_t* pB = B + (long)(ktb * 32 + rowB) * N + bn + segB;
    const uint32_t sbase = (uint32_t)__cvta_generic_to_shared(smu);
    const uint32_t sA = sbase + (rowA * ASTR + segA) * 4;
    const uint32_t sB = sbase + (AS_TILE + rowB * BSTR + segB) * 4;

    auto issue = [&](int i) {
        const uint32_t off = (uint32_t)((i % NSTAGE) * STAGE_U32 * 4);
        const long kf = (long)i * 32;
#pragma unroll
        for (int t = 0; t < 4; t++)
            cp16s(sA + off + t * (32 * ASTR * 4), pA + t * 32 * (long)KP + kf);
#pragma unroll
        for (int t = 0; t < 4; t++)
            cp16s(sB + off + t * (8 * BSTR * 4), pB + (kf + t * 8) * (long)N);
    };

    issue(0); cp_commit();
    if (nkt > 1) { issue(1); }
    cp_commit();

    float acc[2][8][4];
#pragma unroll
    for (int mc = 0; mc < 2; mc++)
#pragma unroll
        for (int nc = 0; nc < 8; nc++)
#pragma unroll
            for (int i = 0; i < 4; i++) acc[mc][nc][i] = 0.0f;

    for (int i = 0; i < nkt; i++) {
        cp_wait<1>();
        __syncthreads();
        if (i + 2 < nkt) issue(i + 2);
        cp_commit();

        const uint32_t* as = smu + (i % NSTAGE) * STAGE_U32;
        const uint32_t* bs = as + AS_TILE;

#pragma unroll
        for (int ks = 0; ks < 4; ks++) {
            const int kc = ks * 8 + tkc;
            uint32_t af[2][4];
#pragma unroll
            for (int mc = 0; mc < 2; mc++) {
                const int r = wm * 32 + mc * 16 + gid;
                af[mc][0] = as[r * ASTR + kc];
                af[mc][1] = as[(r + 8) * ASTR + kc];
                af[mc][2] = as[r * ASTR + kc + 4];
                af[mc][3] = as[(r + 8) * ASTR + kc + 4];
            }
#pragma unroll
            for (int nc = 0; nc < 8; nc++) {
                uint32_t bf[2];
                const int c = wn * 64 + nc * 8 + gid;
                bf[0] = bs[kc * BSTR + c];
                bf[1] = bs[(kc + 4) * BSTR + c];
                mma_f16(acc[0][nc], af[0], bf);
                mma_f16(acc[1][nc], af[1], bf);
            }
        }
    }

    if (splitk == 1) {
#pragma unroll
        for (int mc = 0; mc < 2; mc++) {
            const int r0 = bm + wm * 32 + mc * 16 + gid;
#pragma unroll
            for (int nc = 0; nc < 8; nc++) {
                const int col = bn + wn * 64 + nc * 8 + 2 * tkc;
                const float b0 = bi[col], b1 = bi[col + 1];
                float v0 = acc[mc][nc][0] + b0;
                float v1 = acc[mc][nc][1] + b1;
                float v2 = acc[mc][nc][2] + b0;
                float v3 = acc[mc][nc][3] + b1;
                if (relu) {
                    v0 = fmaxf(v0, 0.f); v1 = fmaxf(v1, 0.f);
                    v2 = fmaxf(v2, 0.f); v3 = fmaxf(v3, 0.f);
                }
                if (Ch) {
                    __half2 lo = __floats2half2_rn(v0, v1);
                    __half2 hi = __floats2half2_rn(v2, v3);
                    *(__half2*)&Ch[(long)r0 * N + col]       = lo;
                    *(__half2*)&Ch[(long)(r0 + 8) * N + col] = hi;
                } else {
                    *(float2*)&C[(long)r0 * N + col]       = make_float2(v0, v1);
                    *(float2*)&C[(long)(r0 + 8) * N + col] = make_float2(v2, v3);
                }
            }
        }
    } else {
        float* P0 = part + (long)z * M * N;
#pragma unroll
        for (int mc = 0; mc < 2; mc++) {
            const int r0 = bm + wm * 32 + mc * 16 + gid;
#pragma unroll
            for (int nc = 0; nc < 8; nc++) {
                const int col = bn + wn * 64 + nc * 8 + 2 * tkc;
                *(float2*)&P0[(long)r0 * N + col]       = make_float2(acc[mc][nc][0], acc[mc][nc][1]);
                *(float2*)&P0[(long)(r0 + 8) * N + col] = make_float2(acc[mc][nc][2], acc[mc][nc][3]);
            }
        }
    }
}

// ordered split-K reduce + bias; fp32 and fp16 outputs
__global__ void splitk_reduce_kernel(const float* __restrict__ part,
                                     const float* __restrict__ bias,
                                     float* __restrict__ Cf,
                                     __half* __restrict__ Chh,
                                     int MN, int N, int splitk, int relu) {
    int idx = blockIdx.x * 256 + threadIdx.x;
    if (idx >= MN) return;
    float s = part[idx];
    for (int zz = 1; zz < splitk; zz++) s += part[(long)zz * MN + idx];
    s += bias[idx % N];
    if (relu) s = fmaxf(s, 0.0f);
    if (Cf) Cf[idx] = s;
    if (Chh) Chh[idx] = __float2half(s);
}

// ---------------- attention: fp16 in, fp16 out -------------------------------
__global__ void attn_kernel(const __half* __restrict__ Q,
                            const __half* __restrict__ K,
                            const __half* __restrict__ V,
                            __half* __restrict__ O16) {
    extern __shared__ float sm[];
    float* qs = sm;
    float* ks = qs + 64 * 65;
    float* vs = ks + 64 * 65;
    float* ss = vs + 64 * 65;

    int h = blockIdx.x;
    int b = blockIdx.y;
    int tid = threadIdx.x;

    for (int e = tid; e < 4096; e += 256) {
        int s = e >> 6, d = e & 63;
        long base = ((long)(b * 64 + s) * EDIM) + h * 64 + d;
        qs[s * 65 + d] = __half2float(Q[base]);
        ks[s * 65 + d] = __half2float(K[base]);
        vs[s * 65 + d] = __half2float(V[base]);
    }
    __syncthreads();

    for (int e = tid; e < 4096; e += 256) {
        int row = e >> 6, col = e & 63;
        float sum = 0.0f;
#pragma unroll 16
        for (int dd = 0; dd < 64; dd++)
            sum += qs[row * 65 + dd] * ks[col * 65 + dd];
        ss[row * 65 + col] = sum * 0.125f;
    }
    __syncthreads();

    if (tid < 64) {
        float* r = ss + tid * 65;
        float m = r[0];
#pragma unroll 16
        for (int c = 1; c < 64; c++) m = fmaxf(m, r[c]);
        float sum = 0.0f;
#pragma unroll 16
        for (int c = 0; c < 64; c++) { float e = expf(r[c] - m); r[c] = e; sum += e; }
        float inv = 1.0f / sum;
#pragma unroll 16
        for (int c = 0; c < 64; c++) r[c] *= inv;
    }
    __syncthreads();

    for (int e = tid; e < 4096; e += 256) {
        int row = e >> 6, d = e & 63;
        float sum = 0.0f;
#pragma unroll 16
        for (int col = 0; col < 64; col++)
            sum += ss[row * 65 + col] * vs[col * 65 + d];
        O16[(long)b * (NHEADS * SEQ * HD) + h * 4096 + row * 64 + d] = __float2half(sum);
    }
}

// ------ fused: y = 3 splitk partials + bias; out = LN(x + y), fp32+fp16 -----
__global__ void add_ln_splitk_kernel(const float* __restrict__ x,
                                     const float* __restrict__ part,
                                     const float* __restrict__ gb,
                                     const float* __restrict__ g,
                                     const float* __restrict__ be,
                                     float* __restrict__ out,
                                     __half* __restrict__ out16,
                                     int MN) {
    __shared__ float buf[EDIM];
    __shared__ float red[256];
    int row = blockIdx.x;
    int tid = threadIdx.x;
    long base = (long)row * EDIM;

    float partial = 0.0f;
    for (int e = tid; e < EDIM; e += 256) {
        float y = part[base + e] + part[MN + base + e] + part[2L * MN + base + e] + gb[e];
        float v = x[base + e] + y;
        buf[e] = v;
        partial += v;
    }
    red[tid] = partial;
    __syncthreads();
    for (int s = 128; s > 0; s >>= 1) {
        if (tid < s) red[tid] += red[tid + s];
        __syncthreads();
    }
    float mean = red[0] * (1.0f / EDIM);
    __syncthreads();

    float p2 = 0.0f;
    for (int e = tid; e < EDIM; e += 256) {
        float d = buf[e] - mean;
        p2 += d * d;
    }
    red[tid] = p2;
    __syncthreads();
    for (int s = 128; s > 0; s >>= 1) {
        if (tid < s) red[tid] += red[tid + s];
        __syncthreads();
    }
    float var = red[0] * (1.0f / EDIM);
    float rstd = rsqrtf(var + 1e-6f);

    for (int e = tid; e < EDIM; e += 256) {
        float o = (buf[e] - mean) * rstd * g[e] + be[e];
        out[base + e] = o;
        out16[base + e] = __float2half(o);
    }
}

// ---------------- mean-pool + head + sigmoid --------------------------------
__global__ void head_kernel(const float* __restrict__ t,
                            const float* __restrict__ hw,
                            const float* __restrict__ hb,
                            float* __restrict__ out) {
    __shared__ float red[256];
    int b = blockIdx.x;
    int tid = threadIdx.x;
    float partial = 0.0f;
    for (int e = tid; e < EDIM; e += 256) {
        float se = 0.0f;
        for (int s = 0; s < SEQ; s++)
            se += t[((long)(b * SEQ + s)) * EDIM + e];
        partial += (se * (1.0f / SEQ)) * hw[e];
    }
    red[tid] = partial;
    __syncthreads();
    for (int s = 128; s > 0; s >>= 1) {
        if (tid < s) red[tid] += red[tid + s];
        __syncthreads();
    }
    if (tid == 0) {
        float z = red[0] + hb[0];
        out[b] = 1.0f / (1.0f + expf(-z));
    }
}

// ---------------- host launch ------------------------------------------------
static inline void launch_gemm(const uint32_t* A, const uint32_t* B, const float* bias,
                               float* C, __half* Ch, float* part,
                               int M, int N, int K, int splitk, int relu) {
    dim3 grid(N / 128, M / 128, splitk);
    gemm_f16_kernel<<<grid, 256, GEMM_SMEM>>>(A, B, B, B, bias, bias, bias,
                                              C, C, C, Ch, Ch, Ch, part,
                                              M, N, K, splitk, relu);
}

static inline void launch_cvt(const float* W, uint32_t* O, long kp_total, int N) {
    long total4 = kp_total * N / 4;
    cvt_w_kernel<<<(int)((total4 + 255) / 256), 256>>>(W, O, total4, N);
}

extern "C" void kernel_launch(void* const* d_in, const int* in_sizes, int n_in,
                              void* d_out, int out_size) {
    const float* x       = (const float*)d_in[0];
    const float* conv1_w = (const float*)d_in[1];
    const float* conv1_b = (const float*)d_in[2];
    const float* conv2_w = (const float*)d_in[3];
    const float* conv2_b = (const float*)d_in[4];
    const float* proj_w  = (const float*)d_in[5];
    const float* proj_b  = (const float*)d_in[6];
    const float* Wq = (const float*)d_in[7];
    const float* bq = (const float*)d_in[8];
    const float* Wk = (const float*)d_in[9];
    const float* bk = (const float*)d_in[10];
    const float* Wv = (const float*)d_in[11];
    const float* bv = (const float*)d_in[12];
    const float* Wo = (const float*)d_in[13];
    const float* bo = (const float*)d_in[14];
    const float* W1 = (const float*)d_in[15];
    const float* b1 = (const float*)d_in[16];
    const float* W2 = (const float*)d_in[17];
    const float* b2 = (const float*)d_in[18];
    const float* ln1_g = (const float*)d_in[19];
    const float* ln1_b = (const float*)d_in[20];
    const float* ln2_g = (const float*)d_in[21];
    const float* ln2_b = (const float*)d_in[22];
    const float* head_w = (const float*)d_in[23];
    const float* head_b = (const float*)d_in[24];
    float* out = (float*)d_out;

    float *pool1, *pool2, *t, *o1, *part;
    uint32_t *patch16, *t16, *q16, *k16, *v16, *att16, *o116, *f116;
    uint32_t *wq16, *wk16, *wv16, *wo16, *w116, *w216, *wp16;
    cudaGetSymbolAddress((void**)&pool1, g_pool1);
    cudaGetSymbolAddress((void**)&pool2, g_pool2);
    cudaGetSymbolAddress((void**)&t,  g_t);
    cudaGetSymbolAddress((void**)&o1, g_o1);
    cudaGetSymbolAddress((void**)&part, g_part);
    cudaGetSymbolAddress((void**)&patch16, g_patch16);
    cudaGetSymbolAddress((void**)&t16,  g_t16);
    cudaGetSymbolAddress((void**)&q16,  g_q16);
    cudaGetSymbolAddress((void**)&k16,  g_k16);
    cudaGetSymbolAddress((void**)&v16,  g_v16);
    cudaGetSymbolAddress((void**)&att16, g_att16);
    cudaGetSymbolAddress((void**)&o116, g_o116);
    cudaGetSymbolAddress((void**)&f116, g_f116);
    cudaGetSymbolAddress((void**)&wq16, g_wq16);
    cudaGetSymbolAddress((void**)&wk16, g_wk16);
    cudaGetSymbolAddress((void**)&wv16, g_wv16);
    cudaGetSymbolAddress((void**)&wo16, g_wo16);
    cudaGetSymbolAddress((void**)&w116, g_w116);
    cudaGetSymbolAddress((void**)&w216, g_w216);
    cudaGetSymbolAddress((void**)&wp16, g_wp16);

    const int attn_smem = 4 * 64 * 65 * sizeof(float);
    cudaFuncSetAttribute(attn_kernel, cudaFuncAttributeMaxDynamicSharedMemorySize, attn_smem);
    cudaFuncSetAttribute(gemm_f16_kernel, cudaFuncAttributeMaxDynamicSharedMemorySize, GEMM_SMEM);

    // launches 0-3: first four weight conversions
    launch_cvt(proj_w, wp16, PDIM / 2, EDIM);
    launch_cvt(Wq, wq16, (long)NLAYER * EDIM / 2, EDIM);
    launch_cvt(Wk, wk16, (long)NLAYER * EDIM / 2, EDIM);
    launch_cvt(Wv, wv16, (long)NLAYER * EDIM / 2, EDIM);

    // launches 4,5: convs (index 5 = conv2 gets profiled by ncu -s 5 -c 1)
    {
        int n1 = 16 * 255 * 255;
        conv1_pool_kernel<<<(n1 + 255) / 256, 256>>>(x, conv1_w, conv1_b, pool1);
        int n2 = 16 * 126 * 126;
        conv2_pool_kernel<<<(n2 + 255) / 256, 256>>>(pool1, conv2_w, conv2_b, pool2);
    }

    // remaining conversions + patch
    launch_cvt(Wo, wo16, (long)NLAYER * EDIM / 2, EDIM);
    launch_cvt(W1, w116, (long)NLAYER * EDIM / 2, FFDIM);
    launch_cvt(W2, w216, (long)NLAYER * FFDIM / 2, EDIM);
    {
        long np = (long)ROWSM * PDIM;
        patch_kernel<<<(int)((np + 255) / 256), 256>>>(pool2, (__half*)patch16);
    }

    const int MN_E = ROWSM * EDIM;

    // patch projection (K=4096, splitk=3)
    launch_gemm(patch16, wp16, proj_b, NULL, NULL, part, ROWSM, EDIM, PDIM, 3, 0);
    splitk_reduce_kernel<<<(MN_E + 255) / 256, 256>>>(part, proj_b, t, (__half*)t16,
                                                      MN_E, EDIM, 3, 0);

    for (int i = 0; i < NLAYER; i++) {
        const uint32_t* wq = wq16 + (long)i * EDIM * EDIM / 2;
        const uint32_t* wk = wk16 + (long)i * EDIM * EDIM / 2;
        const uint32_t* wv = wv16 + (long)i * EDIM * EDIM / 2;
        const uint32_t* wo = wo16 + (long)i * EDIM * EDIM / 2;
        const uint32_t* w1 = w116 + (long)i * EDIM * FFDIM / 2;
        const uint32_t* w2 = w216 + (long)i * FFDIM * EDIM / 2;

        // fused QKV: z = 3 matrices, fp16 outputs
        {
            dim3 grid(EDIM / 128, ROWSM / 128, 3);
            gemm_f16_kernel<<<grid, 256, GEMM_SMEM>>>(
                t16, wq, wk, wv,
                bq + i * EDIM, bk + i * EDIM, bv + i * EDIM,
                NULL, NULL, NULL,
                (__half*)q16, (__half*)k16, (__half*)v16,
                part, ROWSM, EDIM, EDIM, 1, 0);
        }

        attn_kernel<<<dim3(NHEADS, BB), 256, attn_smem>>>(
            (const __half*)q16, (const __half*)k16, (const __half*)v16, (__half*)att16);

        // Wo (splitk=3, reduce fused into add+LN)
        launch_gemm(att16, wo, bo + i * EDIM, NULL, NULL, part, ROWSM, EDIM, EDIM, 3, 0);
        add_ln_splitk_kernel<<<ROWSM, 256>>>(t, part, bo + i * EDIM,
                                             ln1_g + i * EDIM, ln1_b + i * EDIM,
                                             o1, (__half*)o116, MN_E);

        // FF1: 192 blocks, no split-K, fp16 output direct from epilogue
        launch_gemm(o116, w1, b1 + i * FFDIM, NULL, (__half*)f116, part,
                    ROWSM, FFDIM, EDIM, 1, 1);

        // FF2 (splitk=3, reduce fused into add+LN)
        launch_gemm(f116, w2, b2 + i * EDIM, NULL, NULL, part, ROWSM, EDIM, FFDIM, 3, 0);
        add_ln_splitk_kernel<<<ROWSM, 256>>>(o1, part, b2 + i * EDIM,
                                             ln2_g + i * EDIM, ln2_b + i * EDIM,
                                             t, (__half*)t16, MN_E);
    }

    head_kernel<<<BB, 256>>>(t, head_w, head_b, out);
}

// round 14
// speedup vs baseline: 1.6593x; 1.0052x over previous
#include <cuda_runtime.h>
#include <cuda_fp16.h>
#include <math.h>
#include <stdint.h>

// ---------------- model constants ----------------
#define BB     16
#define EDIM   768
#define NHEADS 12
#define HD     64
#define FFDIM  3072
#define NLAYER 8
#define SEQ    64
#define ROWSM  1024     // BB*SEQ
#define PDIM   4096

// ---------------- scratch (device globals) ----------------
__device__ float g_pool1[16 * 255 * 255 * 16];
__device__ float g_pool2[16 * 126 * 126 * 16];
__device__ float g_t [ROWSM * EDIM];
__device__ float g_o1[ROWSM * EDIM];
__device__ float g_part[3 * ROWSM * FFDIM];          // split-K fp32 partials

// fp16 packed-pair (u32 = 2 halves along K) buffers
__device__ uint32_t g_patch16[ROWSM * PDIM / 2];
__device__ uint32_t g_t16  [ROWSM * EDIM / 2];
__device__ uint32_t g_q16 [ROWSM * EDIM / 2];
__device__ uint32_t g_k16 [ROWSM * EDIM / 2];
__device__ uint32_t g_v16 [ROWSM * EDIM / 2];
__device__ uint32_t g_att16[ROWSM * EDIM / 2];
__device__ uint32_t g_o116 [ROWSM * EDIM / 2];
__device__ uint32_t g_f116 [ROWSM * FFDIM / 2];
// converted weights: [K/2][N] u32, pair = (k, k+1) at fixed n
__device__ uint32_t g_wq16[NLAYER * EDIM * EDIM / 2];
__device__ uint32_t g_wk16[NLAYER * EDIM * EDIM / 2];
__device__ uint32_t g_wv16[NLAYER * EDIM * EDIM / 2];
__device__ uint32_t g_wo16[NLAYER * EDIM * EDIM / 2];
__device__ uint32_t g_w116[NLAYER * EDIM * FFDIM / 2];
__device__ uint32_t g_w216[NLAYER * FFDIM * EDIM / 2];
__device__ uint32_t g_wp16[PDIM * EDIM / 2];

// ------- weight conversion (vectorized): [K][N] fp32 -> [K/2][N] u32 --------
__global__ void cvt_w_kernel(const float* __restrict__ W, uint32_t* __restrict__ O,
                             long total4, int N) {
    long idx4 = (long)blockIdx.x * 256 + threadIdx.x;
    if (idx4 >= total4) return;
    long idx = idx4 * 4;
    long kp = idx / N;
    int  n  = (int)(idx - kp * N);
    const float4 a = *(const float4*)(W + (2 * kp) * (long)N + n);
    const float4 b = *(const float4*)(W + (2 * kp + 1) * (long)N + n);
    uint4 o;
    __half2 h;
    h = __floats2half2_rn(a.x, b.x); o.x = *(uint32_t*)&h;
    h = __floats2half2_rn(a.y, b.y); o.y = *(uint32_t*)&h;
    h = __floats2half2_rn(a.z, b.z); o.z = *(uint32_t*)&h;
    h = __floats2half2_rn(a.w, b.w); o.w = *(uint32_t*)&h;
    *(uint4*)(O + idx) = o;
}

// ---------------- conv1 (3x3x3->16) + relu + maxpool ------------------------
__global__ void conv1_pool_kernel(const float* __restrict__ x,
                                  const float* __restrict__ w,
                                  const float* __restrict__ bias,
                                  float* __restrict__ out) {
    __shared__ float ws[432];
    __shared__ float bs[16];
    int tid = threadIdx.x;
    for (int i = tid; i < 432; i += 256) ws[i] = w[i];
    if (tid < 16) bs[tid] = bias[tid];
    __syncthreads();

    int idx = blockIdx.x * 256 + tid;
    if (idx >= 16 * 255 * 255) return;
    int pw = idx % 255;
    int t  = idx / 255;
    int ph = t % 255;
    int b  = t / 255;

    float mx[16];
#pragma unroll
    for (int c = 0; c < 16; c++) mx[c] = 0.0f;

    for (int dy = 0; dy < 2; dy++) {
        for (int dx = 0; dx < 2; dx++) {
            int h0 = 2 * ph + dy;
            int w0 = 2 * pw + dx;
            float acc[16];
#pragma unroll
            for (int c = 0; c < 16; c++) acc[c] = bs[c];
            for (int kh = 0; kh < 3; kh++) {
                for (int kw = 0; kw < 3; kw++) {
                    const float* xp = x + (((long)(b * 512 + h0 + kh) * 512) + (w0 + kw)) * 3;
                    float x0 = xp[0], x1 = xp[1], x2 = xp[2];
                    const float* wp = ws + ((kh * 3 + kw) * 3) * 16;
#pragma unroll
                    for (int c = 0; c < 16; c++)
                        acc[c] += x0 * wp[c] + x1 * wp[16 + c] + x2 * wp[32 + c];
                }
            }
#pragma unroll
            for (int c = 0; c < 16; c++) mx[c] = fmaxf(mx[c], fmaxf(acc[c], 0.0f));
        }
    }
    float* op = out + (long)idx * 16;
#pragma unroll
    for (int c = 0; c < 16; c++) op[c] = mx[c];
}

// ---------------- conv2 (3x3x16->16) + relu + maxpool ------------------------
__global__ void conv2_pool_kernel(const float* __restrict__ in,
                                  const float* __restrict__ w,
                                  const float* __restrict__ bias,
                                  float* __restrict__ out) {
    __shared__ float ws[2304];
    __shared__ float bs[16];
    int tid = threadIdx.x;
    for (int i = tid; i < 2304; i += 256) ws[i] = w[i];
    if (tid < 16) bs[tid] = bias[tid];
    __syncthreads();

    int idx = blockIdx.x * 256 + tid;
    if (idx >= 16 * 126 * 126) return;
    int pw = idx % 126;
    int t  = idx / 126;
    int ph = t % 126;
    int b  = t / 126;

    float mx[16];
#pragma unroll
    for (int c = 0; c < 16; c++) mx[c] = 0.0f;

    for (int dy = 0; dy < 2; dy++) {
        for (int dx = 0; dx < 2; dx++) {
            int h0 = 2 * ph + dy;
            int w0 = 2 * pw + dx;
            float acc[16];
#pragma unroll
            for (int c = 0; c < 16; c++) acc[c] = bs[c];
            for (int kh = 0; kh < 3; kh++) {
                for (int kw = 0; kw < 3; kw++) {
                    const float* xp = in + ((long)(b * 255 + h0 + kh) * 255 + (w0 + kw)) * 16;
                    float xv[16];
#pragma unroll
                    for (int ci = 0; ci < 16; ci++) xv[ci] = xp[ci];
                    const float* wp = ws + ((kh * 3 + kw) * 16) * 16;
#pragma unroll
                    for (int ci = 0; ci < 16; ci++) {
#pragma unroll
                        for (int c = 0; c < 16; c++)
                            acc[c] += xv[ci] * wp[ci * 16 + c];
                    }
                }
            }
#pragma unroll
            for (int c = 0; c < 16; c++) mx[c] = fmaxf(mx[c], fmaxf(acc[c], 0.0f));
        }
    }
    float* op = out + (long)idx * 16;
#pragma unroll
    for (int c = 0; c < 16; c++) op[c] = mx[c];
}

// ---------------- patch gather -> fp16 ---------------------------------------
__global__ void patch_kernel(const float* __restrict__ pool2,
                             __half* __restrict__ patches16) {
    long idx = (long)blockIdx.x * 256 + threadIdx.x;
    if (idx >= (long)ROWSM * PDIM) return;
    int d   = (int)(idx & (PDIM - 1));
    int row = (int)(idx >> 12);
    int b   = row >> 6;
    int p   = row & 63;
    int pr  = p >> 3, pc = p & 7;
    int r   = d >> 8;
    int c   = (d >> 4) & 15;
    int ch  = d & 15;
    int H = pr * 16 + r;
    int W = pc * 16 + c;
    float v = 0.0f;
    if (H >= 1 && H <= 126 && W >= 1 && W <= 126)
        v = pool2[((long)(b * 126 + (H - 1)) * 126 + (W - 1)) * 16 + ch];
    patches16[idx] = __float2half(v);
}

// ---------------- FP16 tensor-core GEMM (ldmatrix A fragments) ---------------
__device__ __forceinline__ void mma_f16(float* d, const uint32_t* a, const uint32_t* b) {
    asm volatile(
        "mma.sync.aligned.m16n8k16.row.col.f32.f16.f16.f32 "
        "{%0,%1,%2,%3}, {%4,%5,%6,%7}, {%8,%9}, {%0,%1,%2,%3};\n"
        : "+f"(d[0]), "+f"(d[1]), "+f"(d[2]), "+f"(d[3])
        : "r"(a[0]), "r"(a[1]), "r"(a[2]), "r"(a[3]), "r"(b[0]), "r"(b[1]));
}

__device__ __forceinline__ void ldsm_x4(uint32_t* r, uint32_t saddr) {
    asm volatile("ldmatrix.sync.aligned.m8n8.x4.shared.b16 {%0,%1,%2,%3}, [%4];"
                 : "=r"(r[0]), "=r"(r[1]), "=r"(r[2]), "=r"(r[3]) : "r"(saddr));
}

__device__ __forceinline__ void cp16s(uint32_t saddr, const void* gsrc) {
    asm volatile("cp.async.cg.shared.global [%0], [%1], 16;\n" :: "r"(saddr), "l"(gsrc));
}
__device__ __forceinline__ void cp_commit() { asm volatile("cp.async.commit_group;\n"); }
template <int N> __device__ __forceinline__ void cp_wait() {
    asm volatile("cp.async.wait_group %0;\n" :: "n"(N));
}

#define ASTR 36
#define BSTR 136
#define AS_TILE (128 * ASTR)
#define BS_TILE (32 * BSTR)
#define STAGE_U32 (AS_TILE + BS_TILE)
#define NSTAGE 3
#define GEMM_SMEM (NSTAGE * STAGE_U32 * 4)   // 107520 B

__global__ __launch_bounds__(256, 2) void gemm_f16_kernel(
    const uint32_t* __restrict__ A,
    const uint32_t* __restrict__ Bp0, const uint32_t* __restrict__ Bp1,
    const uint32_t* __restrict__ Bp2,
    const float* __restrict__ bi0, const float* __restrict__ bi1,
    const float* __restrict__ bi2,
    float* __restrict__ Cp0, float* __restrict__ Cp1, float* __restrict__ Cp2,
    __half* __restrict__ Ch0, __half* __restrict__ Ch1, __half* __restrict__ Ch2,
    float* __restrict__ part,
    int M, int N, int K, int splitk, int relu)
{
    extern __shared__ uint32_t smu[];

    const int z   = blockIdx.z;
    const int mat = z / splitk;
    const int kz  = z - mat * splitk;
    const uint32_t* B  = mat == 0 ? Bp0 : (mat == 1 ? Bp1 : Bp2);
    const float*    bi = mat == 0 ? bi0 : (mat == 1 ? bi1 : bi2);
    float*          C  = mat == 0 ? Cp0 : (mat == 1 ? Cp1 : Cp2);
    __half*         Ch = mat == 0 ? Ch0 : (mat == 1 ? Ch1 : Ch2);

    const int tid  = threadIdx.x;
    const int lane = tid & 31;
    const int warp = tid >> 5;
    const int wm   = warp & 3;
    const int wn   = warp >> 2;
    const int gid  = lane >> 2;
    const int tkc  = lane & 3;

    const int bm = blockIdx.y * 128;
    const int bn = blockIdx.x * 128;

    const int KP   = K >> 1;
    const int ktot = K >> 6;
    const int ktb  = (kz * ktot) / splitk;
    const int kte  = ((kz + 1) * ktot) / splitk;
    const int nkt  = kte - ktb;

    const int rowA = tid >> 3;
    const int segA = (tid & 7) * 4;
    const int rowB = tid >> 5;
    const int segB = (tid & 31) * 4;
    const uint32_t* pA = A + (long)(bm + rowA) * KP + ktb * 32 + segA;
    const uint32_t* pB = B + (long)(ktb * 32 + rowB) * N + bn + segB;
    const uint32_t sbase = (uint32_t)__cvta_generic_to_shared(smu);
    const uint32_t sA = sbase + (rowA * ASTR + segA) * 4;
    const uint32_t sB = sbase + (AS_TILE + rowB * BSTR + segB) * 4;

    // ldmatrix per-lane base: lanes 0-15 -> rows, lanes 16-31 -> rows @ +4 u32
    const uint32_t aldm = sbase +
        (((uint32_t)(wm * 32 + (lane & 15)) * ASTR) + (uint32_t)((lane >> 4) * 4)) * 4;

    auto issue = [&](int i) {
        const uint32_t off = (uint32_t)((i % NSTAGE) * STAGE_U32 * 4);
        const long kf = (long)i * 32;
#pragma unroll
        for (int t = 0; t < 4; t++)
            cp16s(sA + off + t * (32 * ASTR * 4), pA + t * 32 * (long)KP + kf);
#pragma unroll
        for (int t = 0; t < 4; t++)
            cp16s(sB + off + t * (8 * BSTR * 4), pB + (kf + t * 8) * (long)N);
    };

    issue(0); cp_commit();
    if (nkt > 1) { issue(1); }
    cp_commit();

    float acc[2][8][4];
#pragma unroll
    for (int mc = 0; mc < 2; mc++)
#pragma unroll
        for (int nc = 0; nc < 8; nc++)
#pragma unroll
            for (int i = 0; i < 4; i++) acc[mc][nc][i] = 0.0f;

    for (int i = 0; i < nkt; i++) {
        cp_wait<1>();
        __syncthreads();
        if (i + 2 < nkt) issue(i + 2);
        cp_commit();

        const uint32_t off = (uint32_t)((i % NSTAGE) * STAGE_U32 * 4);
        const uint32_t* bs = smu + (i % NSTAGE) * STAGE_U32 + AS_TILE;

#pragma unroll
        for (int ks = 0; ks < 4; ks++) {
            const int kc = ks * 8 + tkc;
            uint32_t af[2][4];
            ldsm_x4(af[0], aldm + off + (uint32_t)(ks * 8) * 4);
            ldsm_x4(af[1], aldm + off + (uint32_t)(16 * ASTR + ks * 8) * 4);
#pragma unroll
            for (int nc = 0; nc < 8; nc++) {
                uint32_t bf[2];
                const int c = wn * 64 + nc * 8 + gid;
                bf[0] = bs[kc * BSTR + c];
                bf[1] = bs[(kc + 4) * BSTR + c];
                mma_f16(acc[0][nc], af[0], bf);
                mma_f16(acc[1][nc], af[1], bf);
            }
        }
    }

    if (splitk == 1) {
#pragma unroll
        for (int mc = 0; mc < 2; mc++) {
            const int r0 = bm + wm * 32 + mc * 16 + gid;
#pragma unroll
            for (int nc = 0; nc < 8; nc++) {
                const int col = bn + wn * 64 + nc * 8 + 2 * tkc;
                const float b0 = bi[col], b1 = bi[col + 1];
                float v0 = acc[mc][nc][0] + b0;
                float v1 = acc[mc][nc][1] + b1;
                float v2 = acc[mc][nc][2] + b0;
                float v3 = acc[mc][nc][3] + b1;
                if (relu) {
                    v0 = fmaxf(v0, 0.f); v1 = fmaxf(v1, 0.f);
                    v2 = fmaxf(v2, 0.f); v3 = fmaxf(v3, 0.f);
                }
                if (Ch) {
                    __half2 lo = __floats2half2_rn(v0, v1);
                    __half2 hi = __floats2half2_rn(v2, v3);
                    *(__half2*)&Ch[(long)r0 * N + col]       = lo;
                    *(__half2*)&Ch[(long)(r0 + 8) * N + col] = hi;
                } else {
                    *(float2*)&C[(long)r0 * N + col]       = make_float2(v0, v1);
                    *(float2*)&C[(long)(r0 + 8) * N + col] = make_float2(v2, v3);
                }
            }
        }
    } else {
        float* P0 = part + (long)z * M * N;
#pragma unroll
        for (int mc = 0; mc < 2; mc++) {
            const int r0 = bm + wm * 32 + mc * 16 + gid;
#pragma unroll
            for (int nc = 0; nc < 8; nc++) {
                const int col = bn + wn * 64 + nc * 8 + 2 * tkc;
                *(float2*)&P0[(long)r0 * N + col]       = make_float2(acc[mc][nc][0], acc[mc][nc][1]);
                *(float2*)&P0[(long)(r0 + 8) * N + col] = make_float2(acc[mc][nc][2], acc[mc][nc][3]);
            }
        }
    }
}

// ordered split-K reduce + bias; fp32 and fp16 outputs
__global__ void splitk_reduce_kernel(const float* __restrict__ part,
                                     const float* __restrict__ bias,
                                     float* __restrict__ Cf,
                                     __half* __restrict__ Chh,
                                     int MN, int N, int splitk, int relu) {
    int idx = blockIdx.x * 256 + threadIdx.x;
    if (idx >= MN) return;
    float s = part[idx];
    for (int zz = 1; zz < splitk; zz++) s += part[(long)zz * MN + idx];
    s += bias[idx % N];
    if (relu) s = fmaxf(s, 0.0f);
    if (Cf) Cf[idx] = s;
    if (Chh) Chh[idx] = __float2half(s);
}

// ---------------- attention: fp16 in, fp16 out -------------------------------
__global__ void attn_kernel(const __half* __restrict__ Q,
                            const __half* __restrict__ K,
                            const __half* __restrict__ V,
                            __half* __restrict__ O16) {
    extern __shared__ float sm[];
    float* qs = sm;
    float* ks = qs + 64 * 65;
    float* vs = ks + 64 * 65;
    float* ss = vs + 64 * 65;

    int h = blockIdx.x;
    int b = blockIdx.y;
    int tid = threadIdx.x;

    for (int e = tid; e < 4096; e += 256) {
        int s = e >> 6, d = e & 63;
        long base = ((long)(b * 64 + s) * EDIM) + h * 64 + d;
        qs[s * 65 + d] = __half2float(Q[base]);
        ks[s * 65 + d] = __half2float(K[base]);
        vs[s * 65 + d] = __half2float(V[base]);
    }
    __syncthreads();

    for (int e = tid; e < 4096; e += 256) {
        int row = e >> 6, col = e & 63;
        float sum = 0.0f;
#pragma unroll 16
        for (int dd = 0; dd < 64; dd++)
            sum += qs[row * 65 + dd] * ks[col * 65 + dd];
        ss[row * 65 + col] = sum * 0.125f;
    }
    __syncthreads();

    if (tid < 64) {
        float* r = ss + tid * 65;
        float m = r[0];
#pragma unroll 16
        for (int c = 1; c < 64; c++) m = fmaxf(m, r[c]);
        float sum = 0.0f;
#pragma unroll 16
        for (int c = 0; c < 64; c++) { float e = expf(r[c] - m); r[c] = e; sum += e; }
        float inv = 1.0f / sum;
#pragma unroll 16
        for (int c = 0; c < 64; c++) r[c] *= inv;
    }
    __syncthreads();

    for (int e = tid; e < 4096; e += 256) {
        int row = e >> 6, d = e & 63;
        float sum = 0.0f;
#pragma unroll 16
        for (int col = 0; col < 64; col++)
            sum += ss[row * 65 + col] * vs[col * 65 + d];
        O16[(long)b * (NHEADS * SEQ * HD) + h * 4096 + row * 64 + d] = __float2half(sum);
    }
}

// ------ fused: y = 3 splitk partials + bias; out = LN(x + y), fp32+fp16 -----
__global__ void add_ln_splitk_kernel(const float* __restrict__ x,
                                     const float* __restrict__ part,
                                     const float* __restrict__ gb,
                                     const float* __restrict__ g,
                                     const float* __restrict__ be,
                                     float* __restrict__ out,
                                     __half* __restrict__ out16,
                                     int MN) {
    __shared__ float buf[EDIM];
    __shared__ float red[256];
    int row = blockIdx.x;
    int tid = threadIdx.x;
    long base = (long)row * EDIM;

    float partial = 0.0f;
    for (int e = tid; e < EDIM; e += 256) {
        float y = part[base + e] + part[MN + base + e] + part[2L * MN + base + e] + gb[e];
        float v = x[base + e] + y;
        buf[e] = v;
        partial += v;
    }
    red[tid] = partial;
    __syncthreads();
    for (int s = 128; s > 0; s >>= 1) {
        if (tid < s) red[tid] += red[tid + s];
        __syncthreads();
    }
    float mean = red[0] * (1.0f / EDIM);
    __syncthreads();

    float p2 = 0.0f;
    for (int e = tid; e < EDIM; e += 256) {
        float d = buf[e] - mean;
        p2 += d * d;
    }
    red[tid] = p2;
    __syncthreads();
    for (int s = 128; s > 0; s >>= 1) {
        if (tid < s) red[tid] += red[tid + s];
        __syncthreads();
    }
    float var = red[0] * (1.0f / EDIM);
    float rstd = rsqrtf(var + 1e-6f);

    for (int e = tid; e < EDIM; e += 256) {
        float o = (buf[e] - mean) * rstd * g[e] + be[e];
        out[base + e] = o;
        out16[base + e] = __float2half(o);
    }
}

// ---------------- mean-pool + head + sigmoid --------------------------------
__global__ void head_kernel(const float* __restrict__ t,
                            const float* __restrict__ hw,
                            const float* __restrict__ hb,
                            float* __restrict__ out) {
    __shared__ float red[256];
    int b = blockIdx.x;
    int tid = threadIdx.x;
    float partial = 0.0f;
    for (int e = tid; e < EDIM; e += 256) {
        float se = 0.0f;
        for (int s = 0; s < SEQ; s++)
            se += t[((long)(b * SEQ + s)) * EDIM + e];
        partial += (se * (1.0f / SEQ)) * hw[e];
    }
    red[tid] = partial;
    __syncthreads();
    for (int s = 128; s > 0; s >>= 1) {
        if (tid < s) red[tid] += red[tid + s];
        __syncthreads();
    }
    if (tid == 0) {
        float z = red[0] + hb[0];
        out[b] = 1.0f / (1.0f + expf(-z));
    }
}

// ---------------- host launch ------------------------------------------------
static inline void launch_gemm(const uint32_t* A, const uint32_t* B, const float* bias,
                               float* C, __half* Ch, float* part,
                               int M, int N, int K, int splitk, int relu) {
    dim3 grid(N / 128, M / 128, splitk);
    gemm_f16_kernel<<<grid, 256, GEMM_SMEM>>>(A, B, B, B, bias, bias, bias,
                                              C, C, C, Ch, Ch, Ch, part,
                                              M, N, K, splitk, relu);
}

static inline void launch_cvt(const float* W, uint32_t* O, long kp_total, int N) {
    long total4 = kp_total * N / 4;
    cvt_w_kernel<<<(int)((total4 + 255) / 256), 256>>>(W, O, total4, N);
}

extern "C" void kernel_launch(void* const* d_in, const int* in_sizes, int n_in,
                              void* d_out, int out_size) {
    const float* x       = (const float*)d_in[0];
    const float* conv1_w = (const float*)d_in[1];
    const float* conv1_b = (const float*)d_in[2];
    const float* conv2_w = (const float*)d_in[3];
    const float* conv2_b = (const float*)d_in[4];
    const float* proj_w  = (const float*)d_in[5];
    const float* proj_b  = (const float*)d_in[6];
    const float* Wq = (const float*)d_in[7];
    const float* bq = (const float*)d_in[8];
    const float* Wk = (const float*)d_in[9];
    const float* bk = (const float*)d_in[10];
    const float* Wv = (const float*)d_in[11];
    const float* bv = (const float*)d_in[12];
    const float* Wo = (const float*)d_in[13];
    const float* bo = (const float*)d_in[14];
    const float* W1 = (const float*)d_in[15];
    const float* b1 = (const float*)d_in[16];
    const float* W2 = (const float*)d_in[17];
    const float* b2 = (const float*)d_in[18];
    const float* ln1_g = (const float*)d_in[19];
    const float* ln1_b = (const float*)d_in[20];
    const float* ln2_g = (const float*)d_in[21];
    const float* ln2_b = (const float*)d_in[22];
    const float* head_w = (const float*)d_in[23];
    const float* head_b = (const float*)d_in[24];
    float* out = (float*)d_out;

    float *pool1, *pool2, *t, *o1, *part;
    uint32_t *patch16, *t16, *q16, *k16, *v16, *att16, *o116, *f116;
    uint32_t *wq16, *wk16, *wv16, *wo16, *w116, *w216, *wp16;
    cudaGetSymbolAddress((void**)&pool1, g_pool1);
    cudaGetSymbolAddress((void**)&pool2, g_pool2);
    cudaGetSymbolAddress((void**)&t,  g_t);
    cudaGetSymbolAddress((void**)&o1, g_o1);
    cudaGetSymbolAddress((void**)&part, g_part);
    cudaGetSymbolAddress((void**)&patch16, g_patch16);
    cudaGetSymbolAddress((void**)&t16,  g_t16);
    cudaGetSymbolAddress((void**)&q16,  g_q16);
    cudaGetSymbolAddress((void**)&k16,  g_k16);
    cudaGetSymbolAddress((void**)&v16,  g_v16);
    cudaGetSymbolAddress((void**)&att16, g_att16);
    cudaGetSymbolAddress((void**)&o116, g_o116);
    cudaGetSymbolAddress((void**)&f116, g_f116);
    cudaGetSymbolAddress((void**)&wq16, g_wq16);
    cudaGetSymbolAddress((void**)&wk16, g_wk16);
    cudaGetSymbolAddress((void**)&wv16, g_wv16);
    cudaGetSymbolAddress((void**)&wo16, g_wo16);
    cudaGetSymbolAddress((void**)&w116, g_w116);
    cudaGetSymbolAddress((void**)&w216, g_w216);
    cudaGetSymbolAddress((void**)&wp16, g_wp16);

    const int attn_smem = 4 * 64 * 65 * sizeof(float);
    cudaFuncSetAttribute(attn_kernel, cudaFuncAttributeMaxDynamicSharedMemorySize, attn_smem);
    cudaFuncSetAttribute(gemm_f16_kernel, cudaFuncAttributeMaxDynamicSharedMemorySize, GEMM_SMEM);

    // weight conversions
    launch_cvt(proj_w, wp16, PDIM / 2, EDIM);
    launch_cvt(Wq, wq16, (long)NLAYER * EDIM / 2, EDIM);
    launch_cvt(Wk, wk16, (long)NLAYER * EDIM / 2, EDIM);
    launch_cvt(Wv, wv16, (long)NLAYER * EDIM / 2, EDIM);

    // convs
    {
        int n1 = 16 * 255 * 255;
        conv1_pool_kernel<<<(n1 + 255) / 256, 256>>>(x, conv1_w, conv1_b, pool1);
        int n2 = 16 * 126 * 126;
        conv2_pool_kernel<<<(n2 + 255) / 256, 256>>>(pool1, conv2_w, conv2_b, pool2);
    }

    launch_cvt(Wo, wo16, (long)NLAYER * EDIM / 2, EDIM);
    launch_cvt(W1, w116, (long)NLAYER * EDIM / 2, FFDIM);
    launch_cvt(W2, w216, (long)NLAYER * FFDIM / 2, EDIM);
    {
        long np = (long)ROWSM * PDIM;
        patch_kernel<<<(int)((np + 255) / 256), 256>>>(pool2, (__half*)patch16);
    }

    const int MN_E = ROWSM * EDIM;

    // patch projection (K=4096, splitk=3)
    launch_gemm(patch16, wp16, proj_b, NULL, NULL, part, ROWSM, EDIM, PDIM, 3, 0);
    splitk_reduce_kernel<<<(MN_E + 255) / 256, 256>>>(part, proj_b, t, (__half*)t16,
                                                      MN_E, EDIM, 3, 0);

    for (int i = 0; i < NLAYER; i++) {
        const uint32_t* wq = wq16 + (long)i * EDIM * EDIM / 2;
        const uint32_t* wk = wk16 + (long)i * EDIM * EDIM / 2;
        const uint32_t* wv = wv16 + (long)i * EDIM * EDIM / 2;
        const uint32_t* wo = wo16 + (long)i * EDIM * EDIM / 2;
        const uint32_t* w1 = w116 + (long)i * EDIM * FFDIM / 2;
        const uint32_t* w2 = w216 + (long)i * FFDIM * EDIM / 2;

        // fused QKV: z = 3 matrices, fp16 outputs
        {
            dim3 grid(EDIM / 128, ROWSM / 128, 3);
            gemm_f16_kernel<<<grid, 256, GEMM_SMEM>>>(
                t16, wq, wk, wv,
                bq + i * EDIM, bk + i * EDIM, bv + i * EDIM,
                NULL, NULL, NULL,
                (__half*)q16, (__half*)k16, (__half*)v16,
                part, ROWSM, EDIM, EDIM, 1, 0);
        }

        attn_kernel<<<dim3(NHEADS, BB), 256, attn_smem>>>(
            (const __half*)q16, (const __half*)k16, (const __half*)v16, (__half*)att16);

        // Wo (splitk=3, reduce fused into add+LN)
        launch_gemm(att16, wo, bo + i * EDIM, NULL, NULL, part, ROWSM, EDIM, EDIM, 3, 0);
        add_ln_splitk_kernel<<<ROWSM, 256>>>(t, part, bo + i * EDIM,
                                             ln1_g + i * EDIM, ln1_b + i * EDIM,
                                             o1, (__half*)o116, MN_E);

        // FF1: 192 blocks, no split-K, fp16 output direct from epilogue
        launch_gemm(o116, w1, b1 + i * FFDIM, NULL, (__half*)f116, part,
                    ROWSM, FFDIM, EDIM, 1, 1);

        // FF2 (splitk=3, reduce fused into add+LN)
        launch_gemm(f116, w2, b2 + i * EDIM, NULL, NULL, part, ROWSM, EDIM, FFDIM, 3, 0);
        add_ln_splitk_kernel<<<ROWSM, 256>>>(o1, part, b2 + i * EDIM,
                                             ln2_g + i * EDIM, ln2_b + i * EDIM,
                                             t, (__half*)t16, MN_E);
    }

    head_kernel<<<BB, 256>>>(t, head_w, head_b, out);
}

// round 15
// speedup vs baseline: 1.7902x; 1.0789x over previous
#include <cuda_runtime.h>
#include <cuda_fp16.h>
#include <math.h>
#include <stdint.h>

// ---------------- model constants ----------------
#define BB     16
#define EDIM   768
#define NHEADS 12
#define HD     64
#define FFDIM  3072
#define NLAYER 8
#define SEQ    64
#define ROWSM  1024     // BB*SEQ
#define PDIM   4096

// ---------------- scratch (device globals) ----------------
__device__ float g_pool1[16 * 255 * 255 * 16];
__device__ float g_pool2[16 * 126 * 126 * 16];
__device__ float g_t [ROWSM * EDIM];
__device__ float g_o1[ROWSM * EDIM];
__device__ float g_part[3 * ROWSM * FFDIM];          // split-K fp32 partials

// fp16 packed-pair (u32 = 2 halves along K) buffers
__device__ uint32_t g_patch16[ROWSM * PDIM / 2];
__device__ uint32_t g_t16  [ROWSM * EDIM / 2];
__device__ uint32_t g_q16 [ROWSM * EDIM / 2];
__device__ uint32_t g_k16 [ROWSM * EDIM / 2];
__device__ uint32_t g_v16 [ROWSM * EDIM / 2];
__device__ uint32_t g_att16[ROWSM * EDIM / 2];
__device__ uint32_t g_o116 [ROWSM * EDIM / 2];
__device__ uint32_t g_f116 [ROWSM * FFDIM / 2];
// converted weights: [K/2][N] u32, pair = (k, k+1) at fixed n
__device__ uint32_t g_wq16[NLAYER * EDIM * EDIM / 2];
__device__ uint32_t g_wk16[NLAYER * EDIM * EDIM / 2];
__device__ uint32_t g_wv16[NLAYER * EDIM * EDIM / 2];
__device__ uint32_t g_wo16[NLAYER * EDIM * EDIM / 2];
__device__ uint32_t g_w116[NLAYER * EDIM * FFDIM / 2];
__device__ uint32_t g_w216[NLAYER * FFDIM * EDIM / 2];
__device__ uint32_t g_wp16[PDIM * EDIM / 2];

// ------- weight conversion (vectorized): [K][N] fp32 -> [K/2][N] u32 --------
__global__ void cvt_w_kernel(const float* __restrict__ W, uint32_t* __restrict__ O,
                             long total4, int N) {
    long idx4 = (long)blockIdx.x * 256 + threadIdx.x;
    if (idx4 >= total4) return;
    long idx = idx4 * 4;
    long kp = idx / N;
    int  n  = (int)(idx - kp * N);
    const float4 a = *(const float4*)(W + (2 * kp) * (long)N + n);
    const float4 b = *(const float4*)(W + (2 * kp + 1) * (long)N + n);
    uint4 o;
    __half2 h;
    h = __floats2half2_rn(a.x, b.x); o.x = *(uint32_t*)&h;
    h = __floats2half2_rn(a.y, b.y); o.y = *(uint32_t*)&h;
    h = __floats2half2_rn(a.z, b.z); o.z = *(uint32_t*)&h;
    h = __floats2half2_rn(a.w, b.w); o.w = *(uint32_t*)&h;
    *(uint4*)(O + idx) = o;
}

// ---------------- conv1 (3x3x3->16) + relu + maxpool ------------------------
__global__ void conv1_pool_kernel(const float* __restrict__ x,
                                  const float* __restrict__ w,
                                  const float* __restrict__ bias,
                                  float* __restrict__ out) {
    __shared__ float ws[432];
    __shared__ float bs[16];
    int tid = threadIdx.x;
    for (int i = tid; i < 432; i += 256) ws[i] = w[i];
    if (tid < 16) bs[tid] = bias[tid];
    __syncthreads();

    int idx = blockIdx.x * 256 + tid;
    if (idx >= 16 * 255 * 255) return;
    int pw = idx % 255;
    int t  = idx / 255;
    int ph = t % 255;
    int b  = t / 255;

    float mx[16];
#pragma unroll
    for (int c = 0; c < 16; c++) mx[c] = 0.0f;

    for (int dy = 0; dy < 2; dy++) {
        for (int dx = 0; dx < 2; dx++) {
            int h0 = 2 * ph + dy;
            int w0 = 2 * pw + dx;
            float acc[16];
#pragma unroll
            for (int c = 0; c < 16; c++) acc[c] = bs[c];
            for (int kh = 0; kh < 3; kh++) {
                for (int kw = 0; kw < 3; kw++) {
                    const float* xp = x + (((long)(b * 512 + h0 + kh) * 512) + (w0 + kw)) * 3;
                    float x0 = xp[0], x1 = xp[1], x2 = xp[2];
                    const float* wp = ws + ((kh * 3 + kw) * 3) * 16;
#pragma unroll
                    for (int c = 0; c < 16; c++)
                        acc[c] += x0 * wp[c] + x1 * wp[16 + c] + x2 * wp[32 + c];
                }
            }
#pragma unroll
            for (int c = 0; c < 16; c++) mx[c] = fmaxf(mx[c], fmaxf(acc[c], 0.0f));
        }
    }
    float* op = out + (long)idx * 16;
#pragma unroll
    for (int c = 0; c < 16; c++) op[c] = mx[c];
}

// ---------------- conv2 (3x3x16->16) + relu + maxpool ------------------------
__global__ void conv2_pool_kernel(const float* __restrict__ in,
                                  const float* __restrict__ w,
                                  const float* __restrict__ bias,
                                  float* __restrict__ out) {
    __shared__ float ws[2304];
    __shared__ float bs[16];
    int tid = threadIdx.x;
    for (int i = tid; i < 2304; i += 256) ws[i] = w[i];
    if (tid < 16) bs[tid] = bias[tid];
    __syncthreads();

    int idx = blockIdx.x * 256 + tid;
    if (idx >= 16 * 126 * 126) return;
    int pw = idx % 126;
    int t  = idx / 126;
    int ph = t % 126;
    int b  = t / 126;

    float mx[16];
#pragma unroll
    for (int c = 0; c < 16; c++) mx[c] = 0.0f;

    for (int dy = 0; dy < 2; dy++) {
        for (int dx = 0; dx < 2; dx++) {
            int h0 = 2 * ph + dy;
            int w0 = 2 * pw + dx;
            float acc[16];
#pragma unroll
            for (int c = 0; c < 16; c++) acc[c] = bs[c];
            for (int kh = 0; kh < 3; kh++) {
                for (int kw = 0; kw < 3; kw++) {
                    const float* xp = in + ((long)(b * 255 + h0 + kh) * 255 + (w0 + kw)) * 16;
                    float xv[16];
#pragma unroll
                    for (int ci = 0; ci < 16; ci++) xv[ci] = xp[ci];
                    const float* wp = ws + ((kh * 3 + kw) * 16) * 16;
#pragma unroll
                    for (int ci = 0; ci < 16; ci++) {
#pragma unroll
                        for (int c = 0; c < 16; c++)
                            acc[c] += xv[ci] * wp[ci * 16 + c];
                    }
                }
            }
#pragma unroll
            for (int c = 0; c < 16; c++) mx[c] = fmaxf(mx[c], fmaxf(acc[c], 0.0f));
        }
    }
    float* op = out + (long)idx * 16;
#pragma unroll
    for (int c = 0; c < 16; c++) op[c] = mx[c];
}

// ---------------- patch gather -> fp16 ---------------------------------------
__global__ void patch_kernel(const float* __restrict__ pool2,
                             __half* __restrict__ patches16) {
    long idx = (long)blockIdx.x * 256 + threadIdx.x;
    if (idx >= (long)ROWSM * PDIM) return;
    int d   = (int)(idx & (PDIM - 1));
    int row = (int)(idx >> 12);
    int b   = row >> 6;
    int p   = row & 63;
    int pr  = p >> 3, pc = p & 7;
    int r   = d >> 8;
    int c   = (d >> 4) & 15;
    int ch  = d & 15;
    int H = pr * 16 + r;
    int W = pc * 16 + c;
    float v = 0.0f;
    if (H >= 1 && H <= 126 && W >= 1 && W <= 126)
        v = pool2[((long)(b * 126 + (H - 1)) * 126 + (W - 1)) * 16 + ch];
    patches16[idx] = __float2half(v);
}

// ---------------- FP16 tensor-core GEMM (ldmatrix A fragments) ---------------
__device__ __forceinline__ void mma_f16(float* d, const uint32_t* a, const uint32_t* b) {
    asm volatile(
        "mma.sync.aligned.m16n8k16.row.col.f32.f16.f16.f32 "
        "{%0,%1,%2,%3}, {%4,%5,%6,%7}, {%8,%9}, {%0,%1,%2,%3};\n"
        : "+f"(d[0]), "+f"(d[1]), "+f"(d[2]), "+f"(d[3])
        : "r"(a[0]), "r"(a[1]), "r"(a[2]), "r"(a[3]), "r"(b[0]), "r"(b[1]));
}

__device__ __forceinline__ void ldsm_x4(uint32_t* r, uint32_t saddr) {
    asm volatile("ldmatrix.sync.aligned.m8n8.x4.shared.b16 {%0,%1,%2,%3}, [%4];"
                 : "=r"(r[0]), "=r"(r[1]), "=r"(r[2]), "=r"(r[3]) : "r"(saddr));
}

__device__ __forceinline__ void cp16s(uint32_t saddr, const void* gsrc) {
    asm volatile("cp.async.cg.shared.global [%0], [%1], 16;\n" :: "r"(saddr), "l"(gsrc));
}
__device__ __forceinline__ void cp_commit() { asm volatile("cp.async.commit_group;\n"); }
template <int N> __device__ __forceinline__ void cp_wait() {
    asm volatile("cp.async.wait_group %0;\n" :: "n"(N));
}

#define ASTR 36
#define BSTR 136
#define AS_TILE (128 * ASTR)
#define BS_TILE (32 * BSTR)
#define STAGE_U32 (AS_TILE + BS_TILE)
#define NSTAGE 3
#define GEMM_SMEM (NSTAGE * STAGE_U32 * 4)   // 107520 B

__global__ __launch_bounds__(256, 2) void gemm_f16_kernel(
    const uint32_t* __restrict__ A,
    const uint32_t* __restrict__ Bp0, const uint32_t* __restrict__ Bp1,
    const uint32_t* __restrict__ Bp2,
    const float* __restrict__ bi0, const float* __restrict__ bi1,
    const float* __restrict__ bi2,
    float* __restrict__ Cp0, float* __restrict__ Cp1, float* __restrict__ Cp2,
    __half* __restrict__ Ch0, __half* __restrict__ Ch1, __half* __restrict__ Ch2,
    float* __restrict__ part,
    int M, int N, int K, int splitk, int relu)
{
    extern __shared__ uint32_t smu[];

    const int z   = blockIdx.z;
    const int mat = z / splitk;
    const int kz  = z - mat * splitk;
    const uint32_t* B  = mat == 0 ? Bp0 : (mat == 1 ? Bp1 : Bp2);
    const float*    bi = mat == 0 ? bi0 : (mat == 1 ? bi1 : bi2);
    float*          C  = mat == 0 ? Cp0 : (mat == 1 ? Cp1 : Cp2);
    __half*         Ch = mat == 0 ? Ch0 : (mat == 1 ? Ch1 : Ch2);

    const int tid  = threadIdx.x;
    const int lane = tid & 31;
    const int warp = tid >> 5;
    const int wm   = warp & 3;
    const int wn   = warp >> 2;
    const int gid  = lane >> 2;
    const int tkc  = lane & 3;

    const int bm = blockIdx.y * 128;
    const int bn = blockIdx.x * 128;

    const int KP   = K >> 1;
    const int ktot = K >> 6;
    const int ktb  = (kz * ktot) / splitk;
    const int kte  = ((kz + 1) * ktot) / splitk;
    const int nkt  = kte - ktb;

    const int rowA = tid >> 3;
    const int segA = (tid & 7) * 4;
    const int rowB = tid >> 5;
    const int segB = (tid & 31) * 4;
    const uint32_t* pA = A + (long)(bm + rowA) * KP + ktb * 32 + segA;
    const uint32_t* pB = B + (long)(ktb * 32 + rowB) * N + bn + segB;
    const uint32_t sbase = (uint32_t)__cvta_generic_to_shared(smu);
    const uint32_t sA = sbase + (rowA * ASTR + segA) * 4;
    const uint32_t sB = sbase + (AS_TILE + rowB * BSTR + segB) * 4;

    const uint32_t aldm = sbase +
        (((uint32_t)(wm * 32 + (lane & 15)) * ASTR) + (uint32_t)((lane >> 4) * 4)) * 4;

    auto issue = [&](int i) {
        const uint32_t off = (uint32_t)((i % NSTAGE) * STAGE_U32 * 4);
        const long kf = (long)i * 32;
#pragma unroll
        for (int t = 0; t < 4; t++)
            cp16s(sA + off + t * (32 * ASTR * 4), pA + t * 32 * (long)KP + kf);
#pragma unroll
        for (int t = 0; t < 4; t++)
            cp16s(sB + off + t * (8 * BSTR * 4), pB + (kf + t * 8) * (long)N);
    };

    issue(0); cp_commit();
    if (nkt > 1) { issue(1); }
    cp_commit();

    float acc[2][8][4];
#pragma unroll
    for (int mc = 0; mc < 2; mc++)
#pragma unroll
        for (int nc = 0; nc < 8; nc++)
#pragma unroll
            for (int i = 0; i < 4; i++) acc[mc][nc][i] = 0.0f;

    for (int i = 0; i < nkt; i++) {
        cp_wait<1>();
        __syncthreads();
        if (i + 2 < nkt) issue(i + 2);
        cp_commit();

        const uint32_t off = (uint32_t)((i % NSTAGE) * STAGE_U32 * 4);
        const uint32_t* bs = smu + (i % NSTAGE) * STAGE_U32 + AS_TILE;

#pragma unroll
        for (int ks = 0; ks < 4; ks++) {
            const int kc = ks * 8 + tkc;
            uint32_t af[2][4];
            ldsm_x4(af[0], aldm + off + (uint32_t)(ks * 8) * 4);
            ldsm_x4(af[1], aldm + off + (uint32_t)(16 * ASTR + ks * 8) * 4);
#pragma unroll
            for (int nc = 0; nc < 8; nc++) {
                uint32_t bf[2];
                const int c = wn * 64 + nc * 8 + gid;
                bf[0] = bs[kc * BSTR + c];
                bf[1] = bs[(kc + 4) * BSTR + c];
                mma_f16(acc[0][nc], af[0], bf);
                mma_f16(acc[1][nc], af[1], bf);
            }
        }
    }

    if (splitk == 1) {
#pragma unroll
        for (int mc = 0; mc < 2; mc++) {
            const int r0 = bm + wm * 32 + mc * 16 + gid;
#pragma unroll
            for (int nc = 0; nc < 8; nc++) {
                const int col = bn + wn * 64 + nc * 8 + 2 * tkc;
                const float b0 = bi[col], b1 = bi[col + 1];
                float v0 = acc[mc][nc][0] + b0;
                float v1 = acc[mc][nc][1] + b1;
                float v2 = acc[mc][nc][2] + b0;
                float v3 = acc[mc][nc][3] + b1;
                if (relu) {
                    v0 = fmaxf(v0, 0.f); v1 = fmaxf(v1, 0.f);
                    v2 = fmaxf(v2, 0.f); v3 = fmaxf(v3, 0.f);
                }
                if (Ch) {
                    __half2 lo = __floats2half2_rn(v0, v1);
                    __half2 hi = __floats2half2_rn(v2, v3);
                    *(__half2*)&Ch[(long)r0 * N + col]       = lo;
                    *(__half2*)&Ch[(long)(r0 + 8) * N + col] = hi;
                } else {
                    *(float2*)&C[(long)r0 * N + col]       = make_float2(v0, v1);
                    *(float2*)&C[(long)(r0 + 8) * N + col] = make_float2(v2, v3);
                }
            }
        }
    } else {
        float* P0 = part + (long)z * M * N;
#pragma unroll
        for (int mc = 0; mc < 2; mc++) {
            const int r0 = bm + wm * 32 + mc * 16 + gid;
#pragma unroll
            for (int nc = 0; nc < 8; nc++) {
                const int col = bn + wn * 64 + nc * 8 + 2 * tkc;
                *(float2*)&P0[(long)r0 * N + col]       = make_float2(acc[mc][nc][0], acc[mc][nc][1]);
                *(float2*)&P0[(long)(r0 + 8) * N + col] = make_float2(acc[mc][nc][2], acc[mc][nc][3]);
            }
        }
    }
}

// ordered split-K reduce + bias; fp32 and fp16 outputs
__global__ void splitk_reduce_kernel(const float* __restrict__ part,
                                     const float* __restrict__ bias,
                                     float* __restrict__ Cf,
                                     __half* __restrict__ Chh,
                                     int MN, int N, int splitk, int relu) {
    int idx = blockIdx.x * 256 + threadIdx.x;
    if (idx >= MN) return;
    float s = part[idx];
    for (int zz = 1; zz < splitk; zz++) s += part[(long)zz * MN + idx];
    s += bias[idx % N];
    if (relu) s = fmaxf(s, 0.0f);
    if (Cf) Cf[idx] = s;
    if (Chh) Chh[idx] = __float2half(s);
}

// ---------------- attention: fp16 in/out, float4-vectorized smem -------------
#define ATTN_STR 68    // floats per row (16B aligned; 64 used)
#define ATTN_SMEM (4 * 64 * ATTN_STR * 4)

__global__ void attn_kernel(const __half* __restrict__ Q,
                            const __half* __restrict__ K,
                            const __half* __restrict__ V,
                            __half* __restrict__ O16) {
    extern __shared__ float sm[];
    float* qs = sm;
    float* ks = qs + 64 * ATTN_STR;
    float* vs = ks + 64 * ATTN_STR;
    float* ss = vs + 64 * ATTN_STR;

    int h = blockIdx.x;
    int b = blockIdx.y;
    int tid = threadIdx.x;

    for (int e = tid; e < 4096; e += 256) {
        int s = e >> 6, d = e & 63;
        long base = ((long)(b * 64 + s) * EDIM) + h * 64 + d;
        qs[s * ATTN_STR + d] = __half2float(Q[base]);
        ks[s * ATTN_STR + d] = __half2float(K[base]);
        vs[s * ATTN_STR + d] = __half2float(V[base]);
    }
    __syncthreads();

    // S = Q K^T * 0.125, float4 along d
    for (int e = tid; e < 4096; e += 256) {
        int row = e >> 6, col = e & 63;
        const float4* qp = (const float4*)(qs + row * ATTN_STR);
        const float4* kp = (const float4*)(ks + col * ATTN_STR);
        float sum = 0.0f;
#pragma unroll
        for (int i = 0; i < 16; i++) {
            float4 a = qp[i], bb = kp[i];
            sum += a.x * bb.x + a.y * bb.y + a.z * bb.z + a.w * bb.w;
        }
        ss[row * ATTN_STR + col] = sum * 0.125f;
    }
    __syncthreads();

    if (tid < 64) {
        float* r = ss + tid * ATTN_STR;
        float m = r[0];
#pragma unroll 16
        for (int c = 1; c < 64; c++) m = fmaxf(m, r[c]);
        float sum = 0.0f;
#pragma unroll 16
        for (int c = 0; c < 64; c++) { float e = expf(r[c] - m); r[c] = e; sum += e; }
        float inv = 1.0f / sum;
#pragma unroll 16
        for (int c = 0; c < 64; c++) r[c] *= inv;
    }
    __syncthreads();

    // A = S V: each work item = 4 outputs (row, d4*4..d4*4+3), float4 V reads
    for (int e = tid; e < 1024; e += 256) {
        int row = e >> 4;
        int d4  = (e & 15) * 4;
        const float* sr = ss + row * ATTN_STR;
        float4 acc = make_float4(0.f, 0.f, 0.f, 0.f);
#pragma unroll 16
        for (int col = 0; col < 64; col++) {
            float s = sr[col];
            float4 v = *(const float4*)(vs + col * ATTN_STR + d4);
            acc.x += s * v.x; acc.y += s * v.y;
            acc.z += s * v.z; acc.w += s * v.w;
        }
        __half* op = O16 + (long)b * (NHEADS * SEQ * HD) + h * 4096 + row * 64 + d4;
        *(__half2*)(op)     = __floats2half2_rn(acc.x, acc.y);
        *(__half2*)(op + 2) = __floats2half2_rn(acc.z, acc.w);
    }
}

// ------ fused: y = 3 splitk partials + bias; out = LN(x + y), fp32+fp16 -----
__global__ void add_ln_splitk_kernel(const float* __restrict__ x,
                                     const float* __restrict__ part,
                                     const float* __restrict__ gb,
                                     const float* __restrict__ g,
                                     const float* __restrict__ be,
                                     float* __restrict__ out,
                                     __half* __restrict__ out16,
                                     int MN) {
    __shared__ float buf[EDIM];
    __shared__ float red[256];
    int row = blockIdx.x;
    int tid = threadIdx.x;
    long base = (long)row * EDIM;

    float partial = 0.0f;
    for (int e = tid; e < EDIM; e += 256) {
        float y = part[base + e] + part[MN + base + e] + part[2L * MN + base + e] + gb[e];
        float v = x[base + e] + y;
        buf[e] = v;
        partial += v;
    }
    red[tid] = partial;
    __syncthreads();
    for (int s = 128; s > 0; s >>= 1) {
        if (tid < s) red[tid] += red[tid + s];
        __syncthreads();
    }
    float mean = red[0] * (1.0f / EDIM);
    __syncthreads();

    float p2 = 0.0f;
    for (int e = tid; e < EDIM; e += 256) {
        float d = buf[e] - mean;
        p2 += d * d;
    }
    red[tid] = p2;
    __syncthreads();
    for (int s = 128; s > 0; s >>= 1) {
        if (tid < s) red[tid] += red[tid + s];
        __syncthreads();
    }
    float var = red[0] * (1.0f / EDIM);
    float rstd = rsqrtf(var + 1e-6f);

    for (int e = tid; e < EDIM; e += 256) {
        float o = (buf[e] - mean) * rstd * g[e] + be[e];
        out[base + e] = o;
        out16[base + e] = __float2half(o);
    }
}

// ---------------- mean-pool + head + sigmoid --------------------------------
__global__ void head_kernel(const float* __restrict__ t,
                            const float* __restrict__ hw,
                            const float* __restrict__ hb,
                            float* __restrict__ out) {
    __shared__ float red[256];
    int b = blockIdx.x;
    int tid = threadIdx.x;
    float partial = 0.0f;
    for (int e = tid; e < EDIM; e += 256) {
        float se = 0.0f;
        for (int s = 0; s < SEQ; s++)
            se += t[((long)(b * SEQ + s)) * EDIM + e];
        partial += (se * (1.0f / SEQ)) * hw[e];
    }
    red[tid] = partial;
    __syncthreads();
    for (int s = 128; s > 0; s >>= 1) {
        if (tid < s) red[tid] += red[tid + s];
        __syncthreads();
    }
    if (tid == 0) {
        float z = red[0] + hb[0];
        out[b] = 1.0f / (1.0f + expf(-z));
    }
}

// ---------------- host launch ------------------------------------------------
static inline void launch_gemm(const uint32_t* A, const uint32_t* B, const float* bias,
                               float* C, __half* Ch, float* part,
                               int M, int N, int K, int splitk, int relu) {
    dim3 grid(N / 128, M / 128, splitk);
    gemm_f16_kernel<<<grid, 256, GEMM_SMEM>>>(A, B, B, B, bias, bias, bias,
                                              C, C, C, Ch, Ch, Ch, part,
                                              M, N, K, splitk, relu);
}

static inline void launch_cvt(const float* W, uint32_t* O, long kp_total, int N) {
    long total4 = kp_total * N / 4;
    cvt_w_kernel<<<(int)((total4 + 255) / 256), 256>>>(W, O, total4, N);
}

extern "C" void kernel_launch(void* const* d_in, const int* in_sizes, int n_in,
                              void* d_out, int out_size) {
    const float* x       = (const float*)d_in[0];
    const float* conv1_w = (const float*)d_in[1];
    const float* conv1_b = (const float*)d_in[2];
    const float* conv2_w = (const float*)d_in[3];
    const float* conv2_b = (const float*)d_in[4];
    const float* proj_w  = (const float*)d_in[5];
    const float* proj_b  = (const float*)d_in[6];
    const float* Wq = (const float*)d_in[7];
    const float* bq = (const float*)d_in[8];
    const float* Wk = (const float*)d_in[9];
    const float* bk = (const float*)d_in[10];
    const float* Wv = (const float*)d_in[11];
    const float* bv = (const float*)d_in[12];
    const float* Wo = (const float*)d_in[13];
    const float* bo = (const float*)d_in[14];
    const float* W1 = (const float*)d_in[15];
    const float* b1 = (const float*)d_in[16];
    const float* W2 = (const float*)d_in[17];
    const float* b2 = (const float*)d_in[18];
    const float* ln1_g = (const float*)d_in[19];
    const float* ln1_b = (const float*)d_in[20];
    const float* ln2_g = (const float*)d_in[21];
    const float* ln2_b = (const float*)d_in[22];
    const float* head_w = (const float*)d_in[23];
    const float* head_b = (const float*)d_in[24];
    float* out = (float*)d_out;

    float *pool1, *pool2, *t, *o1, *part;
    uint32_t *patch16, *t16, *q16, *k16, *v16, *att16, *o116, *f116;
    uint32_t *wq16, *wk16, *wv16, *wo16, *w116, *w216, *wp16;
    cudaGetSymbolAddress((void**)&pool1, g_pool1);
    cudaGetSymbolAddress((void**)&pool2, g_pool2);
    cudaGetSymbolAddress((void**)&t,  g_t);
    cudaGetSymbolAddress((void**)&o1, g_o1);
    cudaGetSymbolAddress((void**)&part, g_part);
    cudaGetSymbolAddress((void**)&patch16, g_patch16);
    cudaGetSymbolAddress((void**)&t16,  g_t16);
    cudaGetSymbolAddress((void**)&q16,  g_q16);
    cudaGetSymbolAddress((void**)&k16,  g_k16);
    cudaGetSymbolAddress((void**)&v16,  g_v16);
    cudaGetSymbolAddress((void**)&att16, g_att16);
    cudaGetSymbolAddress((void**)&o116, g_o116);
    cudaGetSymbolAddress((void**)&f116, g_f116);
    cudaGetSymbolAddress((void**)&wq16, g_wq16);
    cudaGetSymbolAddress((void**)&wk16, g_wk16);
    cudaGetSymbolAddress((void**)&wv16, g_wv16);
    cudaGetSymbolAddress((void**)&wo16, g_wo16);
    cudaGetSymbolAddress((void**)&w116, g_w116);
    cudaGetSymbolAddress((void**)&w216, g_w216);
    cudaGetSymbolAddress((void**)&wp16, g_wp16);

    cudaFuncSetAttribute(attn_kernel, cudaFuncAttributeMaxDynamicSharedMemorySize, ATTN_SMEM);
    cudaFuncSetAttribute(gemm_f16_kernel, cudaFuncAttributeMaxDynamicSharedMemorySize, GEMM_SMEM);

    // launches 0-4: five weight conversions
    launch_cvt(proj_w, wp16, PDIM / 2, EDIM);
    launch_cvt(Wq, wq16, (long)NLAYER * EDIM / 2, EDIM);
    launch_cvt(Wk, wk16, (long)NLAYER * EDIM / 2, EDIM);
    launch_cvt(Wv, wv16, (long)NLAYER * EDIM / 2, EDIM);
    launch_cvt(Wo, wo16, (long)NLAYER * EDIM / 2, EDIM);

    // launches 5,6: conv1, conv2 (index 6 gets profiled by ncu)
    {
        int n1 = 16 * 255 * 255;
        conv1_pool_kernel<<<(n1 + 255) / 256, 256>>>(x, conv1_w, conv1_b, pool1);
        int n2 = 16 * 126 * 126;
        conv2_pool_kernel<<<(n2 + 255) / 256, 256>>>(pool1, conv2_w, conv2_b, pool2);
    }

    launch_cvt(W1, w116, (long)NLAYER * EDIM / 2, FFDIM);
    launch_cvt(W2, w216, (long)NLAYER * FFDIM / 2, EDIM);
    {
        long np = (long)ROWSM * PDIM;
        patch_kernel<<<(int)((np + 255) / 256), 256>>>(pool2, (__half*)patch16);
    }

    const int MN_E = ROWSM * EDIM;

    // patch projection (K=4096, splitk=3)
    launch_gemm(patch16, wp16, proj_b, NULL, NULL, part, ROWSM, EDIM, PDIM, 3, 0);
    splitk_reduce_kernel<<<(MN_E + 255) / 256, 256>>>(part, proj_b, t, (__half*)t16,
                                                      MN_E, EDIM, 3, 0);

    for (int i = 0; i < NLAYER; i++) {
        const uint32_t* wq = wq16 + (long)i * EDIM * EDIM / 2;
        const uint32_t* wk = wk16 + (long)i * EDIM * EDIM / 2;
        const uint32_t* wv = wv16 + (long)i * EDIM * EDIM / 2;
        const uint32_t* wo = wo16 + (long)i * EDIM * EDIM / 2;
        const uint32_t* w1 = w116 + (long)i * EDIM * FFDIM / 2;
        const uint32_t* w2 = w216 + (long)i * FFDIM * EDIM / 2;

        // fused QKV: z = 3 matrices, fp16 outputs
        {
            dim3 grid(EDIM / 128, ROWSM / 128, 3);
            gemm_f16_kernel<<<grid, 256, GEMM_SMEM>>>(
                t16, wq, wk, wv,
                bq + i * EDIM, bk + i * EDIM, bv + i * EDIM,
                NULL, NULL, NULL,
                (__half*)q16, (__half*)k16, (__half*)v16,
                part, ROWSM, EDIM, EDIM, 1, 0);
        }

        attn_kernel<<<dim3(NHEADS, BB), 256, ATTN_SMEM>>>(
            (const __half*)q16, (const __half*)k16, (const __half*)v16, (__half*)att16);

        // Wo (splitk=3, reduce fused into add+LN)
        launch_gemm(att16, wo, bo + i * EDIM, NULL, NULL, part, ROWSM, EDIM, EDIM, 3, 0);
        add_ln_splitk_kernel<<<ROWSM, 256>>>(t, part, bo + i * EDIM,
                                             ln1_g + i * EDIM, ln1_b + i * EDIM,
                                             o1, (__half*)o116, MN_E);

        // FF1: 192 blocks, no split-K, fp16 output direct from epilogue
        launch_gemm(o116, w1, b1 + i * FFDIM, NULL, (__half*)f116, part,
                    ROWSM, FFDIM, EDIM, 1, 1);

        // FF2 (splitk=3, reduce fused into add+LN)
        launch_gemm(f116, w2, b2 + i * EDIM, NULL, NULL, part, ROWSM, EDIM, FFDIM, 3, 0);
        add_ln_splitk_kernel<<<ROWSM, 256>>>(o1, part, b2 + i * EDIM,
                                             ln2_g + i * EDIM, ln2_b + i * EDIM,
                                             t, (__half*)t16, MN_E);
    }

    head_kernel<<<BB, 256>>>(t, head_w, head_b, out);
}

// round 16
// speedup vs baseline: 2.3911x; 1.3357x over previous
#include <cuda_runtime.h>
#include <cuda_fp16.h>
#include <math.h>
#include <stdint.h>

// ---------------- model constants ----------------
#define BB     16
#define EDIM   768
#define NHEADS 12
#define HD     64
#define FFDIM  3072
#define NLAYER 8
#define SEQ    64
#define ROWSM  1024     // BB*SEQ
#define PDIM   4096

// ---------------- scratch (device globals) ----------------
__device__ float g_pool1[16 * 255 * 255 * 16];
__device__ float g_pool2[16 * 126 * 126 * 16];
__device__ float g_t [ROWSM * EDIM];
__device__ float g_o1[ROWSM * EDIM];
__device__ float g_part[3 * ROWSM * FFDIM];          // split-K fp32 partials

// fp16 packed-pair (u32 = 2 halves along K) buffers
__device__ uint32_t g_patch16[ROWSM * PDIM / 2];
__device__ uint32_t g_t16  [ROWSM * EDIM / 2];
__device__ uint32_t g_q16 [ROWSM * EDIM / 2];
__device__ uint32_t g_k16 [ROWSM * EDIM / 2];
__device__ uint32_t g_v16 [ROWSM * EDIM / 2];
__device__ uint32_t g_att16[ROWSM * EDIM / 2];
__device__ uint32_t g_o116 [ROWSM * EDIM / 2];
__device__ uint32_t g_f116 [ROWSM * FFDIM / 2];
// converted weights: [K/2][N] u32, pair = (k, k+1) at fixed n
__device__ uint32_t g_wq16[NLAYER * EDIM * EDIM / 2];
__device__ uint32_t g_wk16[NLAYER * EDIM * EDIM / 2];
__device__ uint32_t g_wv16[NLAYER * EDIM * EDIM / 2];
__device__ uint32_t g_wo16[NLAYER * EDIM * EDIM / 2];
__device__ uint32_t g_w116[NLAYER * EDIM * FFDIM / 2];
__device__ uint32_t g_w216[NLAYER * FFDIM * EDIM / 2];
__device__ uint32_t g_wp16[PDIM * EDIM / 2];

// ------- weight conversion (vectorized): [K][N] fp32 -> [K/2][N] u32 --------
__global__ void cvt_w_kernel(const float* __restrict__ W, uint32_t* __restrict__ O,
                             long total4, int N) {
    long idx4 = (long)blockIdx.x * 256 + threadIdx.x;
    if (idx4 >= total4) return;
    long idx = idx4 * 4;
    long kp = idx / N;
    int  n  = (int)(idx - kp * N);
    const float4 a = *(const float4*)(W + (2 * kp) * (long)N + n);
    const float4 b = *(const float4*)(W + (2 * kp + 1) * (long)N + n);
    uint4 o;
    __half2 h;
    h = __floats2half2_rn(a.x, b.x); o.x = *(uint32_t*)&h;
    h = __floats2half2_rn(a.y, b.y); o.y = *(uint32_t*)&h;
    h = __floats2half2_rn(a.z, b.z); o.z = *(uint32_t*)&h;
    h = __floats2half2_rn(a.w, b.w); o.w = *(uint32_t*)&h;
    *(uint4*)(O + idx) = o;
}

// ---------------- conv1 (3x3x3->16) + relu + maxpool ------------------------
__global__ void conv1_pool_kernel(const float* __restrict__ x,
                                  const float* __restrict__ w,
                                  const float* __restrict__ bias,
                                  float* __restrict__ out) {
    __shared__ float ws[432];
    __shared__ float bs[16];
    int tid = threadIdx.x;
    for (int i = tid; i < 432; i += 256) ws[i] = w[i];
    if (tid < 16) bs[tid] = bias[tid];
    __syncthreads();

    int idx = blockIdx.x * 256 + tid;
    if (idx >= 16 * 255 * 255) return;
    int pw = idx % 255;
    int t  = idx / 255;
    int ph = t % 255;
    int b  = t / 255;

    float mx[16];
#pragma unroll
    for (int c = 0; c < 16; c++) mx[c] = 0.0f;

    for (int dy = 0; dy < 2; dy++) {
        for (int dx = 0; dx < 2; dx++) {
            int h0 = 2 * ph + dy;
            int w0 = 2 * pw + dx;
            float acc[16];
#pragma unroll
            for (int c = 0; c < 16; c++) acc[c] = bs[c];
            for (int kh = 0; kh < 3; kh++) {
                for (int kw = 0; kw < 3; kw++) {
                    const float* xp = x + (((long)(b * 512 + h0 + kh) * 512) + (w0 + kw)) * 3;
                    float x0 = xp[0], x1 = xp[1], x2 = xp[2];
                    const float* wp = ws + ((kh * 3 + kw) * 3) * 16;
#pragma unroll
                    for (int c = 0; c < 16; c++)
                        acc[c] += x0 * wp[c] + x1 * wp[16 + c] + x2 * wp[32 + c];
                }
            }
#pragma unroll
            for (int c = 0; c < 16; c++) mx[c] = fmaxf(mx[c], fmaxf(acc[c], 0.0f));
        }
    }
    float* op = out + (long)idx * 16;
#pragma unroll
    for (int c = 0; c < 16; c++) op[c] = mx[c];
}

// ---------------- conv2 (3x3x16->16) + relu + maxpool, float4 loads ---------
__global__ void conv2_pool_kernel(const float* __restrict__ in,
                                  const float* __restrict__ w,
                                  const float* __restrict__ bias,
                                  float* __restrict__ out) {
    __shared__ float ws[2304];
    __shared__ float bs[16];
    int tid = threadIdx.x;
    for (int i = tid; i < 2304; i += 256) ws[i] = w[i];
    if (tid < 16) bs[tid] = bias[tid];
    __syncthreads();

    int idx = blockIdx.x * 256 + tid;
    if (idx >= 16 * 126 * 126) return;
    int pw = idx % 126;
    int t  = idx / 126;
    int ph = t % 126;
    int b  = t / 126;

    float mx[16];
#pragma unroll
    for (int c = 0; c < 16; c++) mx[c] = 0.0f;

    for (int dy = 0; dy < 2; dy++) {
        for (int dx = 0; dx < 2; dx++) {
            int h0 = 2 * ph + dy;
            int w0 = 2 * pw + dx;
            float acc[16];
#pragma unroll
            for (int c = 0; c < 16; c++) acc[c] = bs[c];
            for (int kh = 0; kh < 3; kh++) {
                for (int kw = 0; kw < 3; kw++) {
                    const float4* xp4 = (const float4*)(in +
                        ((long)(b * 255 + h0 + kh) * 255 + (w0 + kw)) * 16);
                    float4 v0 = xp4[0], v1 = xp4[1], v2 = xp4[2], v3 = xp4[3];
                    float xv[16] = { v0.x, v0.y, v0.z, v0.w,
                                     v1.x, v1.y, v1.z, v1.w,
                                     v2.x, v2.y, v2.z, v2.w,
                                     v3.x, v3.y, v3.z, v3.w };
                    const float* wp = ws + ((kh * 3 + kw) * 16) * 16;
#pragma unroll
                    for (int ci = 0; ci < 16; ci++) {
#pragma unroll
                        for (int c = 0; c < 16; c++)
                            acc[c] += xv[ci] * wp[ci * 16 + c];
                    }
                }
            }
#pragma unroll
            for (int c = 0; c < 16; c++) mx[c] = fmaxf(mx[c], fmaxf(acc[c], 0.0f));
        }
    }
    float* op = out + (long)idx * 16;
#pragma unroll
    for (int c = 0; c < 16; c += 4)
        *(float4*)(op + c) = make_float4(mx[c], mx[c + 1], mx[c + 2], mx[c + 3]);
}

// ---------------- patch gather -> fp16 (16 channels per thread) -------------
// position index: row (0..1023) x (r,c) (0..255); 16 contiguous channels.
__global__ void patch_kernel(const float* __restrict__ pool2,
                             __half* __restrict__ patches16) {
    int pos = blockIdx.x * 256 + threadIdx.x;
    if (pos >= ROWSM * 256) return;
    int rc  = pos & 255;
    int row = pos >> 8;
    int b   = row >> 6;
    int p   = row & 63;
    int pr  = p >> 3, pc = p & 7;
    int r   = rc >> 4;
    int c   = rc & 15;
    int H = pr * 16 + r;
    int W = pc * 16 + c;

    __half hv[16];
    if (H >= 1 && H <= 126 && W >= 1 && W <= 126) {
        const float4* sp = (const float4*)(pool2 +
            ((long)(b * 126 + (H - 1)) * 126 + (W - 1)) * 16);
#pragma unroll
        for (int i = 0; i < 4; i++) {
            float4 v = sp[i];
            hv[i * 4 + 0] = __float2half(v.x);
            hv[i * 4 + 1] = __float2half(v.y);
            hv[i * 4 + 2] = __float2half(v.z);
            hv[i * 4 + 3] = __float2half(v.w);
        }
    } else {
#pragma unroll
        for (int i = 0; i < 16; i++) hv[i] = __float2half(0.0f);
    }
    // destination: 16 consecutive halves at (row, d = rc*16), 32B aligned
    *(uint4*)(patches16 + (long)pos * 16)     = *(uint4*)(hv);
    *(uint4*)(patches16 + (long)pos * 16 + 8) = *(uint4*)(hv + 8);
}

// ---------------- FP16 tensor-core GEMM (ldmatrix A fragments) ---------------
__device__ __forceinline__ void mma_f16(float* d, const uint32_t* a, const uint32_t* b) {
    asm volatile(
        "mma.sync.aligned.m16n8k16.row.col.f32.f16.f16.f32 "
        "{%0,%1,%2,%3}, {%4,%5,%6,%7}, {%8,%9}, {%0,%1,%2,%3};\n"
        : "+f"(d[0]), "+f"(d[1]), "+f"(d[2]), "+f"(d[3])
        : "r"(a[0]), "r"(a[1]), "r"(a[2]), "r"(a[3]), "r"(b[0]), "r"(b[1]));
}

__device__ __forceinline__ void ldsm_x4(uint32_t* r, uint32_t saddr) {
    asm volatile("ldmatrix.sync.aligned.m8n8.x4.shared.b16 {%0,%1,%2,%3}, [%4];"
                 : "=r"(r[0]), "=r"(r[1]), "=r"(r[2]), "=r"(r[3]) : "r"(saddr));
}

__device__ __forceinline__ void cp16s(uint32_t saddr, const void* gsrc) {
    asm volatile("cp.async.cg.shared.global [%0], [%1], 16;\n" :: "r"(saddr), "l"(gsrc));
}
__device__ __forceinline__ void cp_commit() { asm volatile("cp.async.commit_group;\n"); }
template <int N> __device__ __forceinline__ void cp_wait() {
    asm volatile("cp.async.wait_group %0;\n" :: "n"(N));
}

#define ASTR 36
#define BSTR 136
#define AS_TILE (128 * ASTR)
#define BS_TILE (32 * BSTR)
#define STAGE_U32 (AS_TILE + BS_TILE)
#define NSTAGE 3
#define GEMM_SMEM (NSTAGE * STAGE_U32 * 4)   // 107520 B

__global__ __launch_bounds__(256, 2) void gemm_f16_kernel(
    const uint32_t* __restrict__ A,
    const uint32_t* __restrict__ Bp0, const uint32_t* __restrict__ Bp1,
    const uint32_t* __restrict__ Bp2,
    const float* __restrict__ bi0, const float* __restrict__ bi1,
    const float* __restrict__ bi2,
    float* __restrict__ Cp0, float* __restrict__ Cp1, float* __restrict__ Cp2,
    __half* __restrict__ Ch0, __half* __restrict__ Ch1, __half* __restrict__ Ch2,
    float* __restrict__ part,
    int M, int N, int K, int splitk, int relu)
{
    extern __shared__ uint32_t smu[];

    const int z   = blockIdx.z;
    const int mat = z / splitk;
    const int kz  = z - mat * splitk;
    const uint32_t* B  = mat == 0 ? Bp0 : (mat == 1 ? Bp1 : Bp2);
    const float*    bi = mat == 0 ? bi0 : (mat == 1 ? bi1 : bi2);
    float*          C  = mat == 0 ? Cp0 : (mat == 1 ? Cp1 : Cp2);
    __half*         Ch = mat == 0 ? Ch0 : (mat == 1 ? Ch1 : Ch2);

    const int tid  = threadIdx.x;
    const int lane = tid & 31;
    const int warp = tid >> 5;
    const int wm   = warp & 3;
    const int wn   = warp >> 2;
    const int gid  = lane >> 2;
    const int tkc  = lane & 3;

    const int bm = blockIdx.y * 128;
    const int bn = blockIdx.x * 128;

    const int KP   = K >> 1;
    const int ktot = K >> 6;
    const int ktb  = (kz * ktot) / splitk;
    const int kte  = ((kz + 1) * ktot) / splitk;
    const int nkt  = kte - ktb;

    const int rowA = tid >> 3;
    const int segA = (tid & 7) * 4;
    const int rowB = tid >> 5;
    const int segB = (tid & 31) * 4;
    const uint32_t* pA = A + (long)(bm + rowA) * KP + ktb * 32 + segA;
    const uint32_t* pB = B + (long)(ktb * 32 + rowB) * N + bn + segB;
    const uint32_t sbase = (uint32_t)__cvta_generic_to_shared(smu);
    const uint32_t sA = sbase + (rowA * ASTR + segA) * 4;
    const uint32_t sB = sbase + (AS_TILE + rowB * BSTR + segB) * 4;

    const uint32_t aldm = sbase +
        (((uint32_t)(wm * 32 + (lane & 15)) * ASTR) + (uint32_t)((lane >> 4) * 4)) * 4;

    auto issue = [&](int i) {
        const uint32_t off = (uint32_t)((i % NSTAGE) * STAGE_U32 * 4);
        const long kf = (long)i * 32;
#pragma unroll
        for (int t = 0; t < 4; t++)
            cp16s(sA + off + t * (32 * ASTR * 4), pA + t * 32 * (long)KP + kf);
#pragma unroll
        for (int t = 0; t < 4; t++)
            cp16s(sB + off + t * (8 * BSTR * 4), pB + (kf + t * 8) * (long)N);
    };

    issue(0); cp_commit();
    if (nkt > 1) { issue(1); }
    cp_commit();

    float acc[2][8][4];
#pragma unroll
    for (int mc = 0; mc < 2; mc++)
#pragma unroll
        for (int nc = 0; nc < 8; nc++)
#pragma unroll
            for (int i = 0; i < 4; i++) acc[mc][nc][i] = 0.0f;

    for (int i = 0; i < nkt; i++) {
        cp_wait<1>();
        __syncthreads();
        if (i + 2 < nkt) issue(i + 2);
        cp_commit();

        const uint32_t off = (uint32_t)((i % NSTAGE) * STAGE_U32 * 4);
        const uint32_t* bs = smu + (i % NSTAGE) * STAGE_U32 + AS_TILE;

#pragma unroll
        for (int ks = 0; ks < 4; ks++) {
            const int kc = ks * 8 + tkc;
            uint32_t af[2][4];
            ldsm_x4(af[0], aldm + off + (uint32_t)(ks * 8) * 4);
            ldsm_x4(af[1], aldm + off + (uint32_t)(16 * ASTR + ks * 8) * 4);
#pragma unroll
            for (int nc = 0; nc < 8; nc++) {
                uint32_t bf[2];
                const int c = wn * 64 + nc * 8 + gid;
                bf[0] = bs[kc * BSTR + c];
                bf[1] = bs[(kc + 4) * BSTR + c];
                mma_f16(acc[0][nc], af[0], bf);
                mma_f16(acc[1][nc], af[1], bf);
            }
        }
    }

    if (splitk == 1) {
#pragma unroll
        for (int mc = 0; mc < 2; mc++) {
            const int r0 = bm + wm * 32 + mc * 16 + gid;
#pragma unroll
            for (int nc = 0; nc < 8; nc++) {
                const int col = bn + wn * 64 + nc * 8 + 2 * tkc;
                const float b0 = bi[col], b1 = bi[col + 1];
                float v0 = acc[mc][nc][0] + b0;
                float v1 = acc[mc][nc][1] + b1;
                float v2 = acc[mc][nc][2] + b0;
                float v3 = acc[mc][nc][3] + b1;
                if (relu) {
                    v0 = fmaxf(v0, 0.f); v1 = fmaxf(v1, 0.f);
                    v2 = fmaxf(v2, 0.f); v3 = fmaxf(v3, 0.f);
                }
                if (Ch) {
                    __half2 lo = __floats2half2_rn(v0, v1);
                    __half2 hi = __floats2half2_rn(v2, v3);
                    *(__half2*)&Ch[(long)r0 * N + col]       = lo;
                    *(__half2*)&Ch[(long)(r0 + 8) * N + col] = hi;
                } else {
                    *(float2*)&C[(long)r0 * N + col]       = make_float2(v0, v1);
                    *(float2*)&C[(long)(r0 + 8) * N + col] = make_float2(v2, v3);
                }
            }
        }
    } else {
        float* P0 = part + (long)z * M * N;
#pragma unroll
        for (int mc = 0; mc < 2; mc++) {
            const int r0 = bm + wm * 32 + mc * 16 + gid;
#pragma unroll
            for (int nc = 0; nc < 8; nc++) {
                const int col = bn + wn * 64 + nc * 8 + 2 * tkc;
                *(float2*)&P0[(long)r0 * N + col]       = make_float2(acc[mc][nc][0], acc[mc][nc][1]);
                *(float2*)&P0[(long)(r0 + 8) * N + col] = make_float2(acc[mc][nc][2], acc[mc][nc][3]);
            }
        }
    }
}

// ordered split-K reduce + bias; fp32 and fp16 outputs
__global__ void splitk_reduce_kernel(const float* __restrict__ part,
                                     const float* __restrict__ bias,
                                     float* __restrict__ Cf,
                                     __half* __restrict__ Chh,
                                     int MN, int N, int splitk, int relu) {
    int idx = blockIdx.x * 256 + threadIdx.x;
    if (idx >= MN) return;
    float s = part[idx];
    for (int zz = 1; zz < splitk; zz++) s += part[(long)zz * MN + idx];
    s += bias[idx % N];
    if (relu) s = fmaxf(s, 0.0f);
    if (Cf) Cf[idx] = s;
    if (Chh) Chh[idx] = __float2half(s);
}

// ---------------- attention: fp16 in/out, float4-vectorized smem -------------
#define ATTN_STR 68
#define ATTN_SMEM (4 * 64 * ATTN_STR * 4)

__global__ void attn_kernel(const __half* __restrict__ Q,
                            const __half* __restrict__ K,
                            const __half* __restrict__ V,
                            __half* __restrict__ O16) {
    extern __shared__ float sm[];
    float* qs = sm;
    float* ks = qs + 64 * ATTN_STR;
    float* vs = ks + 64 * ATTN_STR;
    float* ss = vs + 64 * ATTN_STR;

    int h = blockIdx.x;
    int b = blockIdx.y;
    int tid = threadIdx.x;

    for (int e = tid; e < 4096; e += 256) {
        int s = e >> 6, d = e & 63;
        long base = ((long)(b * 64 + s) * EDIM) + h * 64 + d;
        qs[s * ATTN_STR + d] = __half2float(Q[base]);
        ks[s * ATTN_STR + d] = __half2float(K[base]);
        vs[s * ATTN_STR + d] = __half2float(V[base]);
    }
    __syncthreads();

    for (int e = tid; e < 4096; e += 256) {
        int row = e >> 6, col = e & 63;
        const float4* qp = (const float4*)(qs + row * ATTN_STR);
        const float4* kp = (const float4*)(ks + col * ATTN_STR);
        float sum = 0.0f;
#pragma unroll
        for (int i = 0; i < 16; i++) {
            float4 a = qp[i], bb = kp[i];
            sum += a.x * bb.x + a.y * bb.y + a.z * bb.z + a.w * bb.w;
        }
        ss[row * ATTN_STR + col] = sum * 0.125f;
    }
    __syncthreads();

    if (tid < 64) {
        float* r = ss + tid * ATTN_STR;
        float m = r[0];
#pragma unroll 16
        for (int c = 1; c < 64; c++) m = fmaxf(m, r[c]);
        float sum = 0.0f;
#pragma unroll 16
        for (int c = 0; c < 64; c++) { float e = expf(r[c] - m); r[c] = e; sum += e; }
        float inv = 1.0f / sum;
#pragma unroll 16
        for (int c = 0; c < 64; c++) r[c] *= inv;
    }
    __syncthreads();

    for (int e = tid; e < 1024; e += 256) {
        int row = e >> 4;
        int d4  = (e & 15) * 4;
        const float* sr = ss + row * ATTN_STR;
        float4 acc = make_float4(0.f, 0.f, 0.f, 0.f);
#pragma unroll 16
        for (int col = 0; col < 64; col++) {
            float s = sr[col];
            float4 v = *(const float4*)(vs + col * ATTN_STR + d4);
            acc.x += s * v.x; acc.y += s * v.y;
            acc.z += s * v.z; acc.w += s * v.w;
        }
        __half* op = O16 + (long)b * (NHEADS * SEQ * HD) + h * 4096 + row * 64 + d4;
        *(__half2*)(op)     = __floats2half2_rn(acc.x, acc.y);
        *(__half2*)(op + 2) = __floats2half2_rn(acc.z, acc.w);
    }
}

// ------ fused: y = 3 splitk partials + bias; out = LN(x + y), float4 --------
// EDIM/4 = 192 float4 per row; threads 0..191 handle loads/stores.
__global__ void add_ln_splitk_kernel(const float* __restrict__ x,
                                     const float* __restrict__ part,
                                     const float* __restrict__ gb,
                                     const float* __restrict__ g,
                                     const float* __restrict__ be,
                                     float* __restrict__ out,
                                     __half* __restrict__ out16,
                                     int MN) {
    __shared__ float buf[EDIM];
    __shared__ float red[256];
    int row = blockIdx.x;
    int tid = threadIdx.x;
    long base = (long)row * EDIM;

    float partial = 0.0f;
    if (tid < 192) {
        int e = tid * 4;
        float4 p0 = *(const float4*)(part + base + e);
        float4 p1 = *(const float4*)(part + MN + base + e);
        float4 p2 = *(const float4*)(part + 2L * MN + base + e);
        float4 gb4 = *(const float4*)(gb + e);
        float4 xv = *(const float4*)(x + base + e);
        float4 v;
        v.x = xv.x + p0.x + p1.x + p2.x + gb4.x;
        v.y = xv.y + p0.y + p1.y + p2.y + gb4.y;
        v.z = xv.z + p0.z + p1.z + p2.z + gb4.z;
        v.w = xv.w + p0.w + p1.w + p2.w + gb4.w;
        *(float4*)(buf + e) = v;
        partial = v.x + v.y + v.z + v.w;
    }
    red[tid] = partial;
    __syncthreads();
    for (int s = 128; s > 0; s >>= 1) {
        if (tid < s) red[tid] += red[tid + s];
        __syncthreads();
    }
    float mean = red[0] * (1.0f / EDIM);
    __syncthreads();

    float p2s = 0.0f;
    if (tid < 192) {
        float4 v = *(const float4*)(buf + tid * 4);
        float dx = v.x - mean, dy = v.y - mean, dz = v.z - mean, dw = v.w - mean;
        p2s = dx * dx + dy * dy + dz * dz + dw * dw;
    }
    red[tid] = p2s;
    __syncthreads();
    for (int s = 128; s > 0; s >>= 1) {
        if (tid < s) red[tid] += red[tid + s];
        __syncthreads();
    }
    float var = red[0] * (1.0f / EDIM);
    float rstd = rsqrtf(var + 1e-6f);

    if (tid < 192) {
        int e = tid * 4;
        float4 v = *(const float4*)(buf + e);
        float4 g4 = *(const float4*)(g + e);
        float4 b4 = *(const float4*)(be + e);
        float4 o;
        o.x = (v.x - mean) * rstd * g4.x + b4.x;
        o.y = (v.y - mean) * rstd * g4.y + b4.y;
        o.z = (v.z - mean) * rstd * g4.z + b4.z;
        o.w = (v.w - mean) * rstd * g4.w + b4.w;
        *(float4*)(out + base + e) = o;
        __half2 lo = __floats2half2_rn(o.x, o.y);
        __half2 hi = __floats2half2_rn(o.z, o.w);
        *(__half2*)(out16 + base + e)     = lo;
        *(__half2*)(out16 + base + e + 2) = hi;
    }
}

// ---------------- mean-pool + head + sigmoid --------------------------------
__global__ void head_kernel(const float* __restrict__ t,
                            const float* __restrict__ hw,
                            const float* __restrict__ hb,
                            float* __restrict__ out) {
    __shared__ float red[256];
    int b = blockIdx.x;
    int tid = threadIdx.x;
    float partial = 0.0f;
    for (int e = tid; e < EDIM; e += 256) {
        float se = 0.0f;
        for (int s = 0; s < SEQ; s++)
            se += t[((long)(b * SEQ + s)) * EDIM + e];
        partial += (se * (1.0f / SEQ)) * hw[e];
    }
    red[tid] = partial;
    __syncthreads();
    for (int s = 128; s > 0; s >>= 1) {
        if (tid < s) red[tid] += red[tid + s];
        __syncthreads();
    }
    if (tid == 0) {
        float z = red[0] + hb[0];
        out[b] = 1.0f / (1.0f + expf(-z));
    }
}

// ---------------- host launch ------------------------------------------------
static inline void launch_gemm(const uint32_t* A, const uint32_t* B, const float* bias,
                               float* C, __half* Ch, float* part,
                               int M, int N, int K, int splitk, int relu) {
    dim3 grid(N / 128, M / 128, splitk);
    gemm_f16_kernel<<<grid, 256, GEMM_SMEM>>>(A, B, B, B, bias, bias, bias,
                                              C, C, C, Ch, Ch, Ch, part,
                                              M, N, K, splitk, relu);
}

static inline void launch_cvt(const float* W, uint32_t* O, long kp_total, int N) {
    long total4 = kp_total * N / 4;
    cvt_w_kernel<<<(int)((total4 + 255) / 256), 256>>>(W, O, total4, N);
}

extern "C" void kernel_launch(void* const* d_in, const int* in_sizes, int n_in,
                              void* d_out, int out_size) {
    const float* x       = (const float*)d_in[0];
    const float* conv1_w = (const float*)d_in[1];
    const float* conv1_b = (const float*)d_in[2];
    const float* conv2_w = (const float*)d_in[3];
    const float* conv2_b = (const float*)d_in[4];
    const float* proj_w  = (const float*)d_in[5];
    const float* proj_b  = (const float*)d_in[6];
    const float* Wq = (const float*)d_in[7];
    const float* bq = (const float*)d_in[8];
    const float* Wk = (const float*)d_in[9];
    const float* bk = (const float*)d_in[10];
    const float* Wv = (const float*)d_in[11];
    const float* bv = (const float*)d_in[12];
    const float* Wo = (const float*)d_in[13];
    const float* bo = (const float*)d_in[14];
    const float* W1 = (const float*)d_in[15];
    const float* b1 = (const float*)d_in[16];
    const float* W2 = (const float*)d_in[17];
    const float* b2 = (const float*)d_in[18];
    const float* ln1_g = (const float*)d_in[19];
    const float* ln1_b = (const float*)d_in[20];
    const float* ln2_g = (const float*)d_in[21];
    const float* ln2_b = (const float*)d_in[22];
    const float* head_w = (const float*)d_in[23];
    const float* head_b = (const float*)d_in[24];
    float* out = (float*)d_out;

    float *pool1, *pool2, *t, *o1, *part;
    uint32_t *patch16, *t16, *q16, *k16, *v16, *att16, *o116, *f116;
    uint32_t *wq16, *wk16, *wv16, *wo16, *w116, *w216, *wp16;
    cudaGetSymbolAddress((void**)&pool1, g_pool1);
    cudaGetSymbolAddress((void**)&pool2, g_pool2);
    cudaGetSymbolAddress((void**)&t,  g_t);
    cudaGetSymbolAddress((void**)&o1, g_o1);
    cudaGetSymbolAddress((void**)&part, g_part);
    cudaGetSymbolAddress((void**)&patch16, g_patch16);
    cudaGetSymbolAddress((void**)&t16,  g_t16);
    cudaGetSymbolAddress((void**)&q16,  g_q16);
    cudaGetSymbolAddress((void**)&k16,  g_k16);
    cudaGetSymbolAddress((void**)&v16,  g_v16);
    cudaGetSymbolAddress((void**)&att16, g_att16);
    cudaGetSymbolAddress((void**)&o116, g_o116);
    cudaGetSymbolAddress((void**)&f116, g_f116);
    cudaGetSymbolAddress((void**)&wq16, g_wq16);
    cudaGetSymbolAddress((void**)&wk16, g_wk16);
    cudaGetSymbolAddress((void**)&wv16, g_wv16);
    cudaGetSymbolAddress((void**)&wo16, g_wo16);
    cudaGetSymbolAddress((void**)&w116, g_w116);
    cudaGetSymbolAddress((void**)&w216, g_w216);
    cudaGetSymbolAddress((void**)&wp16, g_wp16);

    cudaFuncSetAttribute(attn_kernel, cudaFuncAttributeMaxDynamicSharedMemorySize, ATTN_SMEM);
    cudaFuncSetAttribute(gemm_f16_kernel, cudaFuncAttributeMaxDynamicSharedMemorySize, GEMM_SMEM);

    // weight conversions
    launch_cvt(proj_w, wp16, PDIM / 2, EDIM);
    launch_cvt(Wq, wq16, (long)NLAYER * EDIM / 2, EDIM);
    launch_cvt(Wk, wk16, (long)NLAYER * EDIM / 2, EDIM);
    launch_cvt(Wv, wv16, (long)NLAYER * EDIM / 2, EDIM);
    launch_cvt(Wo, wo16, (long)NLAYER * EDIM / 2, EDIM);

    // convs
    {
        int n1 = 16 * 255 * 255;
        conv1_pool_kernel<<<(n1 + 255) / 256, 256>>>(x, conv1_w, conv1_b, pool1);
        int n2 = 16 * 126 * 126;
        conv2_pool_kernel<<<(n2 + 255) / 256, 256>>>(pool1, conv2_w, conv2_b, pool2);
    }

    launch_cvt(W1, w116, (long)NLAYER * EDIM / 2, FFDIM);
    launch_cvt(W2, w216, (long)NLAYER * FFDIM / 2, EDIM);
    {
        int np = ROWSM * 256;
        patch_kernel<<<(np + 255) / 256, 256>>>(pool2, (__half*)patch16);
    }

    const int MN_E = ROWSM * EDIM;

    // patch projection (K=4096, splitk=3)
    launch_gemm(patch16, wp16, proj_b, NULL, NULL, part, ROWSM, EDIM, PDIM, 3, 0);
    splitk_reduce_kernel<<<(MN_E + 255) / 256, 256>>>(part, proj_b, t, (__half*)t16,
                                                      MN_E, EDIM, 3, 0);

    for (int i = 0; i < NLAYER; i++) {
        const uint32_t* wq = wq16 + (long)i * EDIM * EDIM / 2;
        const uint32_t* wk = wk16 + (long)i * EDIM * EDIM / 2;
        const uint32_t* wv = wv16 + (long)i * EDIM * EDIM / 2;
        const uint32_t* wo = wo16 + (long)i * EDIM * EDIM / 2;
        const uint32_t* w1 = w116 + (long)i * EDIM * FFDIM / 2;
        const uint32_t* w2 = w216 + (long)i * FFDIM * EDIM / 2;

        // fused QKV: z = 3 matrices, fp16 outputs
        {
            dim3 grid(EDIM / 128, ROWSM / 128, 3);
            gemm_f16_kernel<<<grid, 256, GEMM_SMEM>>>(
                t16, wq, wk, wv,
                bq + i * EDIM, bk + i * EDIM, bv + i * EDIM,
                NULL, NULL, NULL,
                (__half*)q16, (__half*)k16, (__half*)v16,
                part, ROWSM, EDIM, EDIM, 1, 0);
        }

        attn_kernel<<<dim3(NHEADS, BB), 256, ATTN_SMEM>>>(
            (const __half*)q16, (const __half*)k16, (const __half*)v16, (__half*)att16);

        // Wo (splitk=3, reduce fused into add+LN)
        launch_gemm(att16, wo, bo + i * EDIM, NULL, NULL, part, ROWSM, EDIM, EDIM, 3, 0);
        add_ln_splitk_kernel<<<ROWSM, 256>>>(t, part, bo + i * EDIM,
                                             ln1_g + i * EDIM, ln1_b + i * EDIM,
                                             o1, (__half*)o116, MN_E);

        // FF1: 192 blocks, no split-K, fp16 output direct from epilogue
        launch_gemm(o116, w1, b1 + i * FFDIM, NULL, (__half*)f116, part,
                    ROWSM, FFDIM, EDIM, 1, 1);

        // FF2 (splitk=3, reduce fused into add+LN)
        launch_gemm(f116, w2, b2 + i * EDIM, NULL, NULL, part, ROWSM, EDIM, FFDIM, 3, 0);
        add_ln_splitk_kernel<<<ROWSM, 256>>>(o1, part, b2 + i * EDIM,
                                             ln2_g + i * EDIM, ln2_b + i * EDIM,
                                             t, (__half*)t16, MN_E);
    }

    head_kernel<<<BB, 256>>>(t, head_w, head_b, out);
}

// round 17
// speedup vs baseline: 2.4604x; 1.0289x over previous
#include <cuda_runtime.h>
#include <cuda_fp16.h>
#include <math.h>
#include <stdint.h>

// ---------------- model constants ----------------
#define BB     16
#define EDIM   768
#define NHEADS 12
#define HD     64
#define FFDIM  3072
#define NLAYER 8
#define SEQ    64
#define ROWSM  1024     // BB*SEQ
#define PDIM   4096

// ---------------- scratch (device globals) ----------------
__device__ float g_pool1[16 * 255 * 255 * 16];
__device__ float g_pool2[16 * 126 * 126 * 16];
__device__ float g_t [ROWSM * EDIM];
__device__ float g_o1[ROWSM * EDIM];
__device__ float g_part[3 * ROWSM * FFDIM];          // split-K partials (fp16 view)

// fp16 packed-pair (u32 = 2 halves along K) buffers
__device__ uint32_t g_patch16[ROWSM * PDIM / 2];
__device__ uint32_t g_t16  [ROWSM * EDIM / 2];
__device__ uint32_t g_q16 [ROWSM * EDIM / 2];
__device__ uint32_t g_k16 [ROWSM * EDIM / 2];
__device__ uint32_t g_v16 [ROWSM * EDIM / 2];
__device__ uint32_t g_att16[ROWSM * EDIM / 2];
__device__ uint32_t g_o116 [ROWSM * EDIM / 2];
__device__ uint32_t g_f116 [ROWSM * FFDIM / 2];
// converted weights: [K/2][N] u32, pair = (k, k+1) at fixed n
__device__ uint32_t g_wq16[NLAYER * EDIM * EDIM / 2];
__device__ uint32_t g_wk16[NLAYER * EDIM * EDIM / 2];
__device__ uint32_t g_wv16[NLAYER * EDIM * EDIM / 2];
__device__ uint32_t g_wo16[NLAYER * EDIM * EDIM / 2];
__device__ uint32_t g_w116[NLAYER * EDIM * FFDIM / 2];
__device__ uint32_t g_w216[NLAYER * FFDIM * EDIM / 2];
__device__ uint32_t g_wp16[PDIM * EDIM / 2];

// ------- weight conversion (vectorized): [K][N] fp32 -> [K/2][N] u32 --------
__global__ void cvt_w_kernel(const float* __restrict__ W, uint32_t* __restrict__ O,
                             long total4, int N) {
    long idx4 = (long)blockIdx.x * 256 + threadIdx.x;
    if (idx4 >= total4) return;
    long idx = idx4 * 4;
    long kp = idx / N;
    int  n  = (int)(idx - kp * N);
    const float4 a = *(const float4*)(W + (2 * kp) * (long)N + n);
    const float4 b = *(const float4*)(W + (2 * kp + 1) * (long)N + n);
    uint4 o;
    __half2 h;
    h = __floats2half2_rn(a.x, b.x); o.x = *(uint32_t*)&h;
    h = __floats2half2_rn(a.y, b.y); o.y = *(uint32_t*)&h;
    h = __floats2half2_rn(a.z, b.z); o.z = *(uint32_t*)&h;
    h = __floats2half2_rn(a.w, b.w); o.w = *(uint32_t*)&h;
    *(uint4*)(O + idx) = o;
}

// ---------------- conv1 (3x3x3->16) + relu + maxpool, register window -------
// One thread per pool output. Loads its 4x4x3 super-window once (4 rows x
// 6 float2 = 24 LDG.64, 8B aligned) and computes the 4 conv taps from regs.
__global__ void conv1_pool_kernel(const float* __restrict__ x,
                                  const float* __restrict__ w,
                                  const float* __restrict__ bias,
                                  float* __restrict__ out) {
    __shared__ float ws[432];
    __shared__ float bs[16];
    int tid = threadIdx.x;
    for (int i = tid; i < 432; i += 256) ws[i] = w[i];
    if (tid < 16) bs[tid] = bias[tid];
    __syncthreads();

    int idx = blockIdx.x * 256 + tid;
    if (idx >= 16 * 255 * 255) return;
    int pw = idx % 255;
    int t  = idx / 255;
    int ph = t % 255;
    int b  = t / 255;

    // load 4 rows x 12 floats (4 px x 3 ch)
    float win[4][12];
    const float* base = x + ((long)(b * 512 + 2 * ph) * 512 + 2 * pw) * 3;
#pragma unroll
    for (int r = 0; r < 4; r++) {
        const float2* rp = (const float2*)(base + (long)r * (512 * 3));
#pragma unroll
        for (int i = 0; i < 6; i++) {
            float2 v = rp[i];
            win[r][i * 2]     = v.x;
            win[r][i * 2 + 1] = v.y;
        }
    }

    float mx[16];
#pragma unroll
    for (int c = 0; c < 16; c++) mx[c] = 0.0f;

#pragma unroll
    for (int dy = 0; dy < 2; dy++) {
#pragma unroll
        for (int dx = 0; dx < 2; dx++) {
            float acc[16];
#pragma unroll
            for (int c = 0; c < 16; c++) acc[c] = bs[c];
#pragma unroll
            for (int kh = 0; kh < 3; kh++) {
#pragma unroll
                for (int kw = 0; kw < 3; kw++) {
                    float x0 = win[dy + kh][(dx + kw) * 3];
                    float x1 = win[dy + kh][(dx + kw) * 3 + 1];
                    float x2 = win[dy + kh][(dx + kw) * 3 + 2];
                    const float* wp = ws + ((kh * 3 + kw) * 3) * 16;
#pragma unroll
                    for (int c = 0; c < 16; c++)
                        acc[c] += x0 * wp[c] + x1 * wp[16 + c] + x2 * wp[32 + c];
                }
            }
#pragma unroll
            for (int c = 0; c < 16; c++) mx[c] = fmaxf(mx[c], fmaxf(acc[c], 0.0f));
        }
    }
    float* op = out + (long)idx * 16;
#pragma unroll
    for (int c = 0; c < 16; c += 4)
        *(float4*)(op + c) = make_float4(mx[c], mx[c + 1], mx[c + 2], mx[c + 3]);
}

// ---------------- conv2 (3x3x16->16) + relu + maxpool, float4 loads ---------
__global__ void conv2_pool_kernel(const float* __restrict__ in,
                                  const float* __restrict__ w,
                                  const float* __restrict__ bias,
                                  float* __restrict__ out) {
    __shared__ float ws[2304];
    __shared__ float bs[16];
    int tid = threadIdx.x;
    for (int i = tid; i < 2304; i += 256) ws[i] = w[i];
    if (tid < 16) bs[tid] = bias[tid];
    __syncthreads();

    int idx = blockIdx.x * 256 + tid;
    if (idx >= 16 * 126 * 126) return;
    int pw = idx % 126;
    int t  = idx / 126;
    int ph = t % 126;
    int b  = t / 126;

    float mx[16];
#pragma unroll
    for (int c = 0; c < 16; c++) mx[c] = 0.0f;

    for (int dy = 0; dy < 2; dy++) {
        for (int dx = 0; dx < 2; dx++) {
            int h0 = 2 * ph + dy;
            int w0 = 2 * pw + dx;
            float acc[16];
#pragma unroll
            for (int c = 0; c < 16; c++) acc[c] = bs[c];
            for (int kh = 0; kh < 3; kh++) {
                for (int kw = 0; kw < 3; kw++) {
                    const float4* xp4 = (const float4*)(in +
                        ((long)(b * 255 + h0 + kh) * 255 + (w0 + kw)) * 16);
                    float4 v0 = xp4[0], v1 = xp4[1], v2 = xp4[2], v3 = xp4[3];
                    float xv[16] = { v0.x, v0.y, v0.z, v0.w,
                                     v1.x, v1.y, v1.z, v1.w,
                                     v2.x, v2.y, v2.z, v2.w,
                                     v3.x, v3.y, v3.z, v3.w };
                    const float* wp = ws + ((kh * 3 + kw) * 16) * 16;
#pragma unroll
                    for (int ci = 0; ci < 16; ci++) {
#pragma unroll
                        for (int c = 0; c < 16; c++)
                            acc[c] += xv[ci] * wp[ci * 16 + c];
                    }
                }
            }
#pragma unroll
            for (int c = 0; c < 16; c++) mx[c] = fmaxf(mx[c], fmaxf(acc[c], 0.0f));
        }
    }
    float* op = out + (long)idx * 16;
#pragma unroll
    for (int c = 0; c < 16; c += 4)
        *(float4*)(op + c) = make_float4(mx[c], mx[c + 1], mx[c + 2], mx[c + 3]);
}

// ---------------- patch gather -> fp16 (16 channels per thread) -------------
__global__ void patch_kernel(const float* __restrict__ pool2,
                             __half* __restrict__ patches16) {
    int pos = blockIdx.x * 256 + threadIdx.x;
    if (pos >= ROWSM * 256) return;
    int rc  = pos & 255;
    int row = pos >> 8;
    int b   = row >> 6;
    int p   = row & 63;
    int pr  = p >> 3, pc = p & 7;
    int r   = rc >> 4;
    int c   = rc & 15;
    int H = pr * 16 + r;
    int W = pc * 16 + c;

    __half hv[16];
    if (H >= 1 && H <= 126 && W >= 1 && W <= 126) {
        const float4* sp = (const float4*)(pool2 +
            ((long)(b * 126 + (H - 1)) * 126 + (W - 1)) * 16);
#pragma unroll
        for (int i = 0; i < 4; i++) {
            float4 v = sp[i];
            hv[i * 4 + 0] = __float2half(v.x);
            hv[i * 4 + 1] = __float2half(v.y);
            hv[i * 4 + 2] = __float2half(v.z);
            hv[i * 4 + 3] = __float2half(v.w);
        }
    } else {
#pragma unroll
        for (int i = 0; i < 16; i++) hv[i] = __float2half(0.0f);
    }
    *(uint4*)(patches16 + (long)pos * 16)     = *(uint4*)(hv);
    *(uint4*)(patches16 + (long)pos * 16 + 8) = *(uint4*)(hv + 8);
}

// ---------------- FP16 tensor-core GEMM (ldmatrix A fragments) ---------------
// splitk==1: fp16 (Chx) or fp32 (Cpx) output. splitk>1: fp16 partials to part.
__device__ __forceinline__ void mma_f16(float* d, const uint32_t* a, const uint32_t* b) {
    asm volatile(
        "mma.sync.aligned.m16n8k16.row.col.f32.f16.f16.f32 "
        "{%0,%1,%2,%3}, {%4,%5,%6,%7}, {%8,%9}, {%0,%1,%2,%3};\n"
        : "+f"(d[0]), "+f"(d[1]), "+f"(d[2]), "+f"(d[3])
        : "r"(a[0]), "r"(a[1]), "r"(a[2]), "r"(a[3]), "r"(b[0]), "r"(b[1]));
}

__device__ __forceinline__ void ldsm_x4(uint32_t* r, uint32_t saddr) {
    asm volatile("ldmatrix.sync.aligned.m8n8.x4.shared.b16 {%0,%1,%2,%3}, [%4];"
                 : "=r"(r[0]), "=r"(r[1]), "=r"(r[2]), "=r"(r[3]) : "r"(saddr));
}

__device__ __forceinline__ void cp16s(uint32_t saddr, const void* gsrc) {
    asm volatile("cp.async.cg.shared.global [%0], [%1], 16;\n" :: "r"(saddr), "l"(gsrc));
}
__device__ __forceinline__ void cp_commit() { asm volatile("cp.async.commit_group;\n"); }
template <int N> __device__ __forceinline__ void cp_wait() {
    asm volatile("cp.async.wait_group %0;\n" :: "n"(N));
}

#define ASTR 36
#define BSTR 136
#define AS_TILE (128 * ASTR)
#define BS_TILE (32 * BSTR)
#define STAGE_U32 (AS_TILE + BS_TILE)
#define NSTAGE 3
#define GEMM_SMEM (NSTAGE * STAGE_U32 * 4)   // 107520 B

__global__ __launch_bounds__(256, 2) void gemm_f16_kernel(
    const uint32_t* __restrict__ A,
    const uint32_t* __restrict__ Bp0, const uint32_t* __restrict__ Bp1,
    const uint32_t* __restrict__ Bp2,
    const float* __restrict__ bi0, const float* __restrict__ bi1,
    const float* __restrict__ bi2,
    float* __restrict__ Cp0, float* __restrict__ Cp1, float* __restrict__ Cp2,
    __half* __restrict__ Ch0, __half* __restrict__ Ch1, __half* __restrict__ Ch2,
    __half* __restrict__ part,
    int M, int N, int K, int splitk, int relu)
{
    extern __shared__ uint32_t smu[];

    const int z   = blockIdx.z;
    const int mat = z / splitk;
    const int kz  = z - mat * splitk;
    const uint32_t* B  = mat == 0 ? Bp0 : (mat == 1 ? Bp1 : Bp2);
    const float*    bi = mat == 0 ? bi0 : (mat == 1 ? bi1 : bi2);
    float*          C  = mat == 0 ? Cp0 : (mat == 1 ? Cp1 : Cp2);
    __half*         Ch = mat == 0 ? Ch0 : (mat == 1 ? Ch1 : Ch2);

    const int tid  = threadIdx.x;
    const int lane = tid & 31;
    const int warp = tid >> 5;
    const int wm   = warp & 3;
    const int wn   = warp >> 2;
    const int gid  = lane >> 2;
    const int tkc  = lane & 3;

    const int bm = blockIdx.y * 128;
    const int bn = blockIdx.x * 128;

    const int KP   = K >> 1;
    const int ktot = K >> 6;
    const int ktb  = (kz * ktot) / splitk;
    const int kte  = ((kz + 1) * ktot) / splitk;
    const int nkt  = kte - ktb;

    const int rowA = tid >> 3;
    const int segA = (tid & 7) * 4;
    const int rowB = tid >> 5;
    const int segB = (tid & 31) * 4;
    const uint32_t* pA = A + (long)(bm + rowA) * KP + ktb * 32 + segA;
    const uint32_t* pB = B + (long)(ktb * 32 + rowB) * N + bn + segB;
    const uint32_t sbase = (uint32_t)__cvta_generic_to_shared(smu);
    const uint32_t sA = sbase + (rowA * ASTR + segA) * 4;
    const uint32_t sB = sbase + (AS_TILE + rowB * BSTR + segB) * 4;

    const uint32_t aldm = sbase +
        (((uint32_t)(wm * 32 + (lane & 15)) * ASTR) + (uint32_t)((lane >> 4) * 4)) * 4;

    auto issue = [&](int i) {
        const uint32_t off = (uint32_t)((i % NSTAGE) * STAGE_U32 * 4);
        const long kf = (long)i * 32;
#pragma unroll
        for (int t = 0; t < 4; t++)
            cp16s(sA + off + t * (32 * ASTR * 4), pA + t * 32 * (long)KP + kf);
#pragma unroll
        for (int t = 0; t < 4; t++)
            cp16s(sB + off + t * (8 * BSTR * 4), pB + (kf + t * 8) * (long)N);
    };

    issue(0); cp_commit();
    if (nkt > 1) { issue(1); }
    cp_commit();

    float acc[2][8][4];
#pragma unroll
    for (int mc = 0; mc < 2; mc++)
#pragma unroll
        for (int nc = 0; nc < 8; nc++)
#pragma unroll
            for (int i = 0; i < 4; i++) acc[mc][nc][i] = 0.0f;

    for (int i = 0; i < nkt; i++) {
        cp_wait<1>();
        __syncthreads();
        if (i + 2 < nkt) issue(i + 2);
        cp_commit();

        const uint32_t off = (uint32_t)((i % NSTAGE) * STAGE_U32 * 4);
        const uint32_t* bs = smu + (i % NSTAGE) * STAGE_U32 + AS_TILE;

#pragma unroll
        for (int ks = 0; ks < 4; ks++) {
            const int kc = ks * 8 + tkc;
            uint32_t af[2][4];
            ldsm_x4(af[0], aldm + off + (uint32_t)(ks * 8) * 4);
            ldsm_x4(af[1], aldm + off + (uint32_t)(16 * ASTR + ks * 8) * 4);
#pragma unroll
            for (int nc = 0; nc < 8; nc++) {
                uint32_t bf[2];
                const int c = wn * 64 + nc * 8 + gid;
                bf[0] = bs[kc * BSTR + c];
                bf[1] = bs[(kc + 4) * BSTR + c];
                mma_f16(acc[0][nc], af[0], bf);
                mma_f16(acc[1][nc], af[1], bf);
            }
        }
    }

    if (splitk == 1) {
#pragma unroll
        for (int mc = 0; mc < 2; mc++) {
            const int r0 = bm + wm * 32 + mc * 16 + gid;
#pragma unroll
            for (int nc = 0; nc < 8; nc++) {
                const int col = bn + wn * 64 + nc * 8 + 2 * tkc;
                const float b0 = bi[col], b1 = bi[col + 1];
                float v0 = acc[mc][nc][0] + b0;
                float v1 = acc[mc][nc][1] + b1;
                float v2 = acc[mc][nc][2] + b0;
                float v3 = acc[mc][nc][3] + b1;
                if (relu) {
                    v0 = fmaxf(v0, 0.f); v1 = fmaxf(v1, 0.f);
                    v2 = fmaxf(v2, 0.f); v3 = fmaxf(v3, 0.f);
                }
                if (Ch) {
                    __half2 lo = __floats2half2_rn(v0, v1);
                    __half2 hi = __floats2half2_rn(v2, v3);
                    *(__half2*)&Ch[(long)r0 * N + col]       = lo;
                    *(__half2*)&Ch[(long)(r0 + 8) * N + col] = hi;
                } else {
                    *(float2*)&C[(long)r0 * N + col]       = make_float2(v0, v1);
                    *(float2*)&C[(long)(r0 + 8) * N + col] = make_float2(v2, v3);
                }
            }
        }
    } else {
        __half* P0 = part + (long)z * M * N;
#pragma unroll
        for (int mc = 0; mc < 2; mc++) {
            const int r0 = bm + wm * 32 + mc * 16 + gid;
#pragma unroll
            for (int nc = 0; nc < 8; nc++) {
                const int col = bn + wn * 64 + nc * 8 + 2 * tkc;
                __half2 lo = __floats2half2_rn(acc[mc][nc][0], acc[mc][nc][1]);
                __half2 hi = __floats2half2_rn(acc[mc][nc][2], acc[mc][nc][3]);
                *(__half2*)&P0[(long)r0 * N + col]       = lo;
                *(__half2*)&P0[(long)(r0 + 8) * N + col] = hi;
            }
        }
    }
}

// ordered split-K reduce + bias; fp16 partials in; fp32 and fp16 outputs
__global__ void splitk_reduce_kernel(const __half* __restrict__ part,
                                     const float* __restrict__ bias,
                                     float* __restrict__ Cf,
                                     __half* __restrict__ Chh,
                                     int MN, int N, int splitk, int relu) {
    int idx = blockIdx.x * 256 + threadIdx.x;
    if (idx >= MN) return;
    float s = __half2float(part[idx]);
    for (int zz = 1; zz < splitk; zz++) s += __half2float(part[(long)zz * MN + idx]);
    s += bias[idx % N];
    if (relu) s = fmaxf(s, 0.0f);
    if (Cf) Cf[idx] = s;
    if (Chh) Chh[idx] = __float2half(s);
}

// ---------------- attention: fp16 in/out, float4-vectorized smem -------------
#define ATTN_STR 68
#define ATTN_SMEM (4 * 64 * ATTN_STR * 4)

__global__ void attn_kernel(const __half* __restrict__ Q,
                            const __half* __restrict__ K,
                            const __half* __restrict__ V,
                            __half* __restrict__ O16) {
    extern __shared__ float sm[];
    float* qs = sm;
    float* ks = qs + 64 * ATTN_STR;
    float* vs = ks + 64 * ATTN_STR;
    float* ss = vs + 64 * ATTN_STR;

    int h = blockIdx.x;
    int b = blockIdx.y;
    int tid = threadIdx.x;

    for (int e = tid; e < 4096; e += 256) {
        int s = e >> 6, d = e & 63;
        long base = ((long)(b * 64 + s) * EDIM) + h * 64 + d;
        qs[s * ATTN_STR + d] = __half2float(Q[base]);
        ks[s * ATTN_STR + d] = __half2float(K[base]);
        vs[s * ATTN_STR + d] = __half2float(V[base]);
    }
    __syncthreads();

    for (int e = tid; e < 4096; e += 256) {
        int row = e >> 6, col = e & 63;
        const float4* qp = (const float4*)(qs + row * ATTN_STR);
        const float4* kp = (const float4*)(ks + col * ATTN_STR);
        float sum = 0.0f;
#pragma unroll
        for (int i = 0; i < 16; i++) {
            float4 a = qp[i], bb = kp[i];
            sum += a.x * bb.x + a.y * bb.y + a.z * bb.z + a.w * bb.w;
        }
        ss[row * ATTN_STR + col] = sum * 0.125f;
    }
    __syncthreads();

    if (tid < 64) {
        float* r = ss + tid * ATTN_STR;
        float m = r[0];
#pragma unroll 16
        for (int c = 1; c < 64; c++) m = fmaxf(m, r[c]);
        float sum = 0.0f;
#pragma unroll 16
        for (int c = 0; c < 64; c++) { float e = expf(r[c] - m); r[c] = e; sum += e; }
        float inv = 1.0f / sum;
#pragma unroll 16
        for (int c = 0; c < 64; c++) r[c] *= inv;
    }
    __syncthreads();

    for (int e = tid; e < 1024; e += 256) {
        int row = e >> 4;
        int d4  = (e & 15) * 4;
        const float* sr = ss + row * ATTN_STR;
        float4 acc = make_float4(0.f, 0.f, 0.f, 0.f);
#pragma unroll 16
        for (int col = 0; col < 64; col++) {
            float s = sr[col];
            float4 v = *(const float4*)(vs + col * ATTN_STR + d4);
            acc.x += s * v.x; acc.y += s * v.y;
            acc.z += s * v.z; acc.w += s * v.w;
        }
        __half* op = O16 + (long)b * (NHEADS * SEQ * HD) + h * 4096 + row * 64 + d4;
        *(__half2*)(op)     = __floats2half2_rn(acc.x, acc.y);
        *(__half2*)(op + 2) = __floats2half2_rn(acc.z, acc.w);
    }
}

// ------ fused: y = 3 fp16 splitk partials + bias; out = LN(x + y) -----------
__global__ void add_ln_splitk_kernel(const float* __restrict__ x,
                                     const __half* __restrict__ part,
                                     const float* __restrict__ gb,
                                     const float* __restrict__ g,
                                     const float* __restrict__ be,
                                     float* __restrict__ out,
                                     __half* __restrict__ out16,
                                     int MN) {
    __shared__ float buf[EDIM];
    __shared__ float red[256];
    int row = blockIdx.x;
    int tid = threadIdx.x;
    long base = (long)row * EDIM;

    float partial = 0.0f;
    if (tid < 192) {
        int e = tid * 4;
        const __half2* h0 = (const __half2*)(part + base + e);
        const __half2* h1 = (const __half2*)(part + MN + base + e);
        const __half2* h2 = (const __half2*)(part + 2L * MN + base + e);
        float2 p0a = __half22float2(h0[0]), p0b = __half22float2(h0[1]);
        float2 p1a = __half22float2(h1[0]), p1b = __half22float2(h1[1]);
        float2 p2a = __half22float2(h2[0]), p2b = __half22float2(h2[1]);
        float4 gb4 = *(const float4*)(gb + e);
        float4 xv = *(const float4*)(x + base + e);
        float4 v;
        v.x = xv.x + p0a.x + p1a.x + p2a.x + gb4.x;
        v.y = xv.y + p0a.y + p1a.y + p2a.y + gb4.y;
        v.z = xv.z + p0b.x + p1b.x + p2b.x + gb4.z;
        v.w = xv.w + p0b.y + p1b.y + p2b.y + gb4.w;
        *(float4*)(buf + e) = v;
        partial = v.x + v.y + v.z + v.w;
    }
    red[tid] = partial;
    __syncthreads();
    for (int s = 128; s > 0; s >>= 1) {
        if (tid < s) red[tid] += red[tid + s];
        __syncthreads();
    }
    float mean = red[0] * (1.0f / EDIM);
    __syncthreads();

    float p2s = 0.0f;
    if (tid < 192) {
        float4 v = *(const float4*)(buf + tid * 4);
        float dx = v.x - mean, dy = v.y - mean, dz = v.z - mean, dw = v.w - mean;
        p2s = dx * dx + dy * dy + dz * dz + dw * dw;
    }
    red[tid] = p2s;
    __syncthreads();
    for (int s = 128; s > 0; s >>= 1) {
        if (tid < s) red[tid] += red[tid + s];
        __syncthreads();
    }
    float var = red[0] * (1.0f / EDIM);
    float rstd = rsqrtf(var + 1e-6f);

    if (tid < 192) {
        int e = tid * 4;
        float4 v = *(const float4*)(buf + e);
        float4 g4 = *(const float4*)(g + e);
        float4 b4 = *(const float4*)(be + e);
        float4 o;
        o.x = (v.x - mean) * rstd * g4.x + b4.x;
        o.y = (v.y - mean) * rstd * g4.y + b4.y;
        o.z = (v.z - mean) * rstd * g4.z + b4.z;
        o.w = (v.w - mean) * rstd * g4.w + b4.w;
        *(float4*)(out + base + e) = o;
        __half2 lo = __floats2half2_rn(o.x, o.y);
        __half2 hi = __floats2half2_rn(o.z, o.w);
        *(__half2*)(out16 + base + e)     = lo;
        *(__half2*)(out16 + base + e + 2) = hi;
    }
}

// ---------------- mean-pool + head + sigmoid --------------------------------
__global__ void head_kernel(const float* __restrict__ t,
                            const float* __restrict__ hw,
                            const float* __restrict__ hb,
                            float* __restrict__ out) {
    __shared__ float red[256];
    int b = blockIdx.x;
    int tid = threadIdx.x;
    float partial = 0.0f;
    for (int e = tid; e < EDIM; e += 256) {
        float se = 0.0f;
        for (int s = 0; s < SEQ; s++)
            se += t[((long)(b * SEQ + s)) * EDIM + e];
        partial += (se * (1.0f / SEQ)) * hw[e];
    }
    red[tid] = partial;
    __syncthreads();
    for (int s = 128; s > 0; s >>= 1) {
        if (tid < s) red[tid] += red[tid + s];
        __syncthreads();
    }
    if (tid == 0) {
        float z = red[0] + hb[0];
        out[b] = 1.0f / (1.0f + expf(-z));
    }
}

// ---------------- host launch ------------------------------------------------
static inline void launch_gemm(const uint32_t* A, const uint32_t* B, const float* bias,
                               float* C, __half* Ch, __half* part,
                               int M, int N, int K, int splitk, int relu) {
    dim3 grid(N / 128, M / 128, splitk);
    gemm_f16_kernel<<<grid, 256, GEMM_SMEM>>>(A, B, B, B, bias, bias, bias,
                                              C, C, C, Ch, Ch, Ch, part,
                                              M, N, K, splitk, relu);
}

static inline void launch_cvt(const float* W, uint32_t* O, long kp_total, int N) {
    long total4 = kp_total * N / 4;
    cvt_w_kernel<<<(int)((total4 + 255) / 256), 256>>>(W, O, total4, N);
}

extern "C" void kernel_launch(void* const* d_in, const int* in_sizes, int n_in,
                              void* d_out, int out_size) {
    const float* x       = (const float*)d_in[0];
    const float* conv1_w = (const float*)d_in[1];
    const float* conv1_b = (const float*)d_in[2];
    const float* conv2_w = (const float*)d_in[3];
    const float* conv2_b = (const float*)d_in[4];
    const float* proj_w  = (const float*)d_in[5];
    const float* proj_b  = (const float*)d_in[6];
    const float* Wq = (const float*)d_in[7];
    const float* bq = (const float*)d_in[8];
    const float* Wk = (const float*)d_in[9];
    const float* bk = (const float*)d_in[10];
    const float* Wv = (const float*)d_in[11];
    const float* bv = (const float*)d_in[12];
    const float* Wo = (const float*)d_in[13];
    const float* bo = (const float*)d_in[14];
    const float* W1 = (const float*)d_in[15];
    const float* b1 = (const float*)d_in[16];
    const float* W2 = (const float*)d_in[17];
    const float* b2 = (const float*)d_in[18];
    const float* ln1_g = (const float*)d_in[19];
    const float* ln1_b = (const float*)d_in[20];
    const float* ln2_g = (const float*)d_in[21];
    const float* ln2_b = (const float*)d_in[22];
    const float* head_w = (const float*)d_in[23];
    const float* head_b = (const float*)d_in[24];
    float* out = (float*)d_out;

    float *pool1, *pool2, *t, *o1, *partf;
    uint32_t *patch16, *t16, *q16, *k16, *v16, *att16, *o116, *f116;
    uint32_t *wq16, *wk16, *wv16, *wo16, *w116, *w216, *wp16;
    cudaGetSymbolAddress((void**)&pool1, g_pool1);
    cudaGetSymbolAddress((void**)&pool2, g_pool2);
    cudaGetSymbolAddress((void**)&t,  g_t);
    cudaGetSymbolAddress((void**)&o1, g_o1);
    cudaGetSymbolAddress((void**)&partf, g_part);
    cudaGetSymbolAddress((void**)&patch16, g_patch16);
    cudaGetSymbolAddress((void**)&t16,  g_t16);
    cudaGetSymbolAddress((void**)&q16,  g_q16);
    cudaGetSymbolAddress((void**)&k16,  g_k16);
    cudaGetSymbolAddress((void**)&v16,  g_v16);
    cudaGetSymbolAddress((void**)&att16, g_att16);
    cudaGetSymbolAddress((void**)&o116, g_o116);
    cudaGetSymbolAddress((void**)&f116, g_f116);
    cudaGetSymbolAddress((void**)&wq16, g_wq16);
    cudaGetSymbolAddress((void**)&wk16, g_wk16);
    cudaGetSymbolAddress((void**)&wv16, g_wv16);
    cudaGetSymbolAddress((void**)&wo16, g_wo16);
    cudaGetSymbolAddress((void**)&w116, g_w116);
    cudaGetSymbolAddress((void**)&w216, g_w216);
    cudaGetSymbolAddress((void**)&wp16, g_wp16);
    __half* part = (__half*)partf;

    cudaFuncSetAttribute(attn_kernel, cudaFuncAttributeMaxDynamicSharedMemorySize, ATTN_SMEM);
    cudaFuncSetAttribute(gemm_f16_kernel, cudaFuncAttributeMaxDynamicSharedMemorySize, GEMM_SMEM);

    // weight conversions
    launch_cvt(proj_w, wp16, PDIM / 2, EDIM);
    launch_cvt(Wq, wq16, (long)NLAYER * EDIM / 2, EDIM);
    launch_cvt(Wk, wk16, (long)NLAYER * EDIM / 2, EDIM);
    launch_cvt(Wv, wv16, (long)NLAYER * EDIM / 2, EDIM);
    launch_cvt(Wo, wo16, (long)NLAYER * EDIM / 2, EDIM);

    // convs
    {
        int n1 = 16 * 255 * 255;
        conv1_pool_kernel<<<(n1 + 255) / 256, 256>>>(x, conv1_w, conv1_b, pool1);
        int n2 = 16 * 126 * 126;
        conv2_pool_kernel<<<(n2 + 255) / 256, 256>>>(pool1, conv2_w, conv2_b, pool2);
    }

    launch_cvt(W1, w116, (long)NLAYER * EDIM / 2, FFDIM);
    launch_cvt(W2, w216, (long)NLAYER * FFDIM / 2, EDIM);
    {
        int np = ROWSM * 256;
        patch_kernel<<<(np + 255) / 256, 256>>>(pool2, (__half*)patch16);
    }

    const int MN_E = ROWSM * EDIM;

    // patch projection (K=4096, splitk=3)
    launch_gemm(patch16, wp16, proj_b, NULL, NULL, part, ROWSM, EDIM, PDIM, 3, 0);
    splitk_reduce_kernel<<<(MN_E + 255) / 256, 256>>>(part, proj_b, t, (__half*)t16,
                                                      MN_E, EDIM, 3, 0);

    for (int i = 0; i < NLAYER; i++) {
        const uint32_t* wq = wq16 + (long)i * EDIM * EDIM / 2;
        const uint32_t* wk = wk16 + (long)i * EDIM * EDIM / 2;
        const uint32_t* wv = wv16 + (long)i * EDIM * EDIM / 2;
        const uint32_t* wo = wo16 + (long)i * EDIM * EDIM / 2;
        const uint32_t* w1 = w116 + (long)i * EDIM * FFDIM / 2;
        const uint32_t* w2 = w216 + (long)i * FFDIM * EDIM / 2;

        // fused QKV: z = 3 matrices, fp16 outputs
        {
            dim3 grid(EDIM / 128, ROWSM / 128, 3);
            gemm_f16_kernel<<<grid, 256, GEMM_SMEM>>>(
                t16, wq, wk, wv,
                bq + i * EDIM, bk + i * EDIM, bv + i * EDIM,
                NULL, NULL, NULL,
                (__half*)q16, (__half*)k16, (__half*)v16,
                part, ROWSM, EDIM, EDIM, 1, 0);
        }

        attn_kernel<<<dim3(NHEADS, BB), 256, ATTN_SMEM>>>(
            (const __half*)q16, (const __half*)k16, (const __half*)v16, (__half*)att16);

        // Wo (splitk=3, fp16 partials, reduce fused into add+LN)
        launch_gemm(att16, wo, bo + i * EDIM, NULL, NULL, part, ROWSM, EDIM, EDIM, 3, 0);
        add_ln_splitk_kernel<<<ROWSM, 256>>>(t, part, bo + i * EDIM,
                                             ln1_g + i * EDIM, ln1_b + i * EDIM,
                                             o1, (__half*)o116, MN_E);

        // FF1: 192 blocks, no split-K, fp16 output direct from epilogue
        launch_gemm(o116, w1, b1 + i * FFDIM, NULL, (__half*)f116, part,
                    ROWSM, FFDIM, EDIM, 1, 1);

        // FF2 (splitk=3, fp16 partials, reduce fused into add+LN)
        launch_gemm(f116, w2, b2 + i * EDIM, NULL, NULL, part, ROWSM, EDIM, FFDIM, 3, 0);
        add_ln_splitk_kernel<<<ROWSM, 256>>>(o1, part, b2 + i * EDIM,
                                             ln2_g + i * EDIM, ln2_b + i * EDIM,
                                             t, (__half*)t16, MN_E);
    }

    head_kernel<<<BB, 256>>>(t, head_w, head_b, out);
}